// round 13
// baseline (speedup 1.0000x reference)
#include <cuda_runtime.h>
#include <cuda_bf16.h>
#include <cuda_fp16.h>
#include <math.h>
#include <stdint.h>

// ---------------- problem constants ----------------
#define Bc   2
#define Sq   1024
#define Dm   1024
#define Hh   16
#define DHd  64
#define Ex   8
#define FFd  4096
#define BH   (Bc*Hh)     // 32
#define ROWS (Bc*Sq)     // 2048
#define QK_SCALE 10.0f

// GEMM tiling (bgemm: 256x128 CTA tile)
#define BM 256
#define BN 128
#define BK 64
#define LDS 72                        // BK + 8 pad (16-bit units)
#define A_BYTES (256*LDS*2)           // 36864
#define B_BYTES (128*LDS*2)           // 18432
#define SMEM_M0 (2*(2*A_BYTES + 2*B_BYTES))  // 221184 (bf16 3-term, 2 stages)
#define SMEM_M2 (4*(A_BYTES + B_BYTES))      // 221184 (fp16 1-term, 4 stages)

// flash attention tiling
#define FQ_BYTES (128*LDS*2)          // 18432
#define LDSV 136
#define FV_BYTES (64*LDSV*2)          // 17408
#define FK_STAGE (2*FQ_BYTES + 2*FV_BYTES)   // 71680
#define SMEM_FL (2*FQ_BYTES + 2*FK_STAGE)    // 180224

// ---------------- low-level helpers ----------------
__device__ __forceinline__ uint32_t smem_u32(const void* p) {
    uint32_t a;
    asm("{ .reg .u64 t; cvta.to.shared.u64 t, %1; cvt.u32.u64 %0, t; }" : "=r"(a) : "l"(p));
    return a;
}
__device__ __forceinline__ void cp16(uint32_t dst, const void* src) {
    asm volatile("cp.async.cg.shared.global [%0], [%1], 16;" :: "r"(dst), "l"(src));
}
#define CP_COMMIT() asm volatile("cp.async.commit_group;" ::: "memory")
#define CP_WAIT(n)  asm volatile("cp.async.wait_group %0;" :: "n"(n) : "memory")

#define LDSM_X4(r0, r1, r2, r3, addr) \
    asm volatile("ldmatrix.sync.aligned.m8n8.x4.shared.b16 {%0,%1,%2,%3}, [%4];" \
        : "=r"(r0), "=r"(r1), "=r"(r2), "=r"(r3) : "r"(addr))

#define MMA_BF16(d, a, b0, b1) \
    asm volatile("mma.sync.aligned.m16n8k16.row.col.f32.bf16.bf16.f32 " \
        "{%0,%1,%2,%3}, {%4,%5,%6,%7}, {%8,%9}, {%0,%1,%2,%3};" \
        : "+f"((d)[0]), "+f"((d)[1]), "+f"((d)[2]), "+f"((d)[3]) \
        : "r"((a)[0]), "r"((a)[1]), "r"((a)[2]), "r"((a)[3]), "r"(b0), "r"(b1))

#define MMA_F16(d, a, b0, b1) \
    asm volatile("mma.sync.aligned.m16n8k16.row.col.f32.f16.f16.f32 " \
        "{%0,%1,%2,%3}, {%4,%5,%6,%7}, {%8,%9}, {%0,%1,%2,%3};" \
        : "+f"((d)[0]), "+f"((d)[1]), "+f"((d)[2]), "+f"((d)[3]) \
        : "r"((a)[0]), "r"((a)[1]), "r"((a)[2]), "r"((a)[3]), "r"(b0), "r"(b1))

__device__ __forceinline__ uint32_t pack_bf16(float a, float b) {
    __nv_bfloat162 t;
    t.x = __float2bfloat16(a);
    t.y = __float2bfloat16(b);
    return *(uint32_t*)&t;
}

// ---------------- scratch (device globals) ----------------
__device__ __nv_bfloat16 g_h1hi[ROWS*Dm], g_h1lo[ROWS*Dm];
__device__ float g_qkvf[ROWS*3*Dm];
__device__ __nv_bfloat16 g_qnh[BH*Sq*DHd], g_qnl[BH*Sq*DHd];
__device__ __nv_bfloat16 g_knh[BH*Sq*DHd], g_knl[BH*Sq*DHd];
__device__ __nv_bfloat16 g_vTh[BH*DHd*Sq], g_vTl[BH*DHd*Sq];
__device__ __nv_bfloat16 g_aohi[ROWS*Dm], g_aolo[ROWS*Dm];
__device__ float g_o[ROWS*Dm], g_h2[ROWS*Dm];
__device__ __half g_h2h16[ROWS*Dm];
__device__ float g_gate[ROWS*Ex];
__device__ __half g_hid[(size_t)Ex*ROWS*FFd];
__device__ float g_expout[(size_t)Ex*ROWS*Dm];
__device__ __nv_bfloat16 g_wqkvThi[3*Dm*Dm], g_wqkvTlo[3*Dm*Dm];
__device__ __nv_bfloat16 g_woThi[Dm*Dm], g_woTlo[Dm*Dm];
__device__ __half g_w1Th[(size_t)Ex*FFd*Dm];
__device__ __half g_w2Th[(size_t)Ex*Dm*FFd];

// ---------------- math helpers ----------------
__device__ __forceinline__ float gelu_f(float x) {
    float x3 = x * x * x;
    float t  = tanhf(0.7978845608028654f * (x + 0.044715f * x3));
    return 0.5f * x * (1.0f + t);
}

// ---------------- weight transpose + bf16 split (small matrices) -----------
__global__ void wprep_kernel(const float* __restrict__ W, __nv_bfloat16* __restrict__ hi,
                             __nv_bfloat16* __restrict__ lo, int K, int N)
{
    __shared__ float t[32][33];
    const size_t zoff = (size_t)blockIdx.z * K * N;
    const int k0 = blockIdx.y * 32, n0 = blockIdx.x * 32;
    const int tx = threadIdx.x, ty = threadIdx.y;
    #pragma unroll
    for (int i = 0; i < 4; i++)
        t[ty + 8*i][tx] = W[zoff + (size_t)(k0 + ty + 8*i) * N + n0 + tx];
    __syncthreads();
    #pragma unroll
    for (int i = 0; i < 4; i++) {
        float v = t[tx][ty + 8*i];
        const size_t o = zoff + (size_t)(n0 + ty + 8*i) * K + k0 + tx;
        __nv_bfloat16 h = __float2bfloat16(v);
        hi[o] = h;
        lo[o] = __float2bfloat16(v - __bfloat162float(h));
    }
}

// ---------------- FAST weight transpose + fp16: W[K,N] -> fp16 [N,K] -------
__global__ void __launch_bounds__(256)
wprep16_kernel(const float* __restrict__ W, __half* __restrict__ out, int K, int N)
{
    __shared__ float t[64][33];
    const size_t zoff = (size_t)blockIdx.z * K * N;
    const int k0 = blockIdx.y * 64, n0 = blockIdx.x * 32;
    const int tid = threadIdx.x;
    const int lx = tid & 31;
    const int ly = tid >> 5;
    #pragma unroll
    for (int i = 0; i < 8; i++) {
        const int kk = ly + 8 * i;
        t[kk][lx] = W[zoff + (size_t)(k0 + kk) * N + n0 + lx];
    }
    __syncthreads();
    const int n  = tid >> 3;
    const int ks = (tid & 7) * 8;
    __half h[8];
    #pragma unroll
    for (int j = 0; j < 8; j++) h[j] = __float2half(t[ks + j][n]);
    *(uint4*)(out + zoff + (size_t)(n0 + n) * K + k0 + ks) = *(uint4*)h;
}

// ---------------- LayerNorm (+ optional fused gate softmax) ----------------
__global__ void ln_kernel(const float* __restrict__ x, const float* __restrict__ g,
                          const float* __restrict__ b, float* __restrict__ yf,
                          __nv_bfloat16* __restrict__ yhi, __nv_bfloat16* __restrict__ ylo,
                          __half* __restrict__ y16,
                          const float* __restrict__ gw, const float* __restrict__ gb,
                          float* __restrict__ gateOut)
{
    __shared__ float buf[Dm];
    __shared__ float red[256];
    __shared__ float lg[Ex];
    const int row = blockIdx.x;
    const int tid = threadIdx.x;
    const float* xr = x + (size_t)row * Dm;
    float s = 0.f;
    for (int i = tid; i < Dm; i += 256) { float v = xr[i]; buf[i] = v; s += v; }
    red[tid] = s; __syncthreads();
    for (int off = 128; off > 0; off >>= 1) { if (tid < off) red[tid] += red[tid+off]; __syncthreads(); }
    const float mean = red[0] * (1.0f / Dm);
    __syncthreads();
    float s2 = 0.f;
    for (int i = tid; i < Dm; i += 256) { float d = buf[i] - mean; s2 += d * d; }
    red[tid] = s2; __syncthreads();
    for (int off = 128; off > 0; off >>= 1) { if (tid < off) red[tid] += red[tid+off]; __syncthreads(); }
    const float inv = rsqrtf(red[0] * (1.0f / Dm) + 1e-5f);
    for (int i = tid; i < Dm; i += 256) {
        float v = (buf[i] - mean) * inv * g[i] + b[i];
        buf[i] = v;   // keep normalized row for the gate
        if (yf) yf[(size_t)row*Dm + i] = v;
        if (yhi) {
            __nv_bfloat16 h = __float2bfloat16(v);
            yhi[(size_t)row*Dm + i] = h;
            ylo[(size_t)row*Dm + i] = __float2bfloat16(v - __bfloat162float(h));
        }
        if (y16) y16[(size_t)row*Dm + i] = __float2half(v);
    }
    if (gateOut) {
        __syncthreads();
        const int e = tid >> 5, lane = tid & 31;
        float sg = 0.f;
        for (int k = lane; k < Dm; k += 32) sg += buf[k] * gw[k * Ex + e];
        #pragma unroll
        for (int o = 16; o; o >>= 1) sg += __shfl_xor_sync(0xffffffffu, sg, o);
        if (lane == 0) lg[e] = sg + gb[e];
        __syncthreads();
        if (tid == 0) {
            float m = lg[0];
            #pragma unroll
            for (int q = 1; q < Ex; q++) m = fmaxf(m, lg[q]);
            float ex[Ex], sum = 0.f;
            #pragma unroll
            for (int q = 0; q < Ex; q++) { ex[q] = expf(lg[q] - m); sum += ex[q]; }
            const float invs = 1.0f / sum;
            #pragma unroll
            for (int q = 0; q < Ex; q++) gateOut[(size_t)row * Ex + q] = ex[q] * invs;
        }
    }
}

// ---------------- mma.sync GEMM ------------
// MODE 0: bf16 3-term, NSTG=2. MODE 2: fp16 single-term, NSTG=4.
// EPI 0: fp32 store; EPI 1: gelu(acc+bias) -> fp16; EPI 2: gate*(acc+bias) -> fp32
template<int EPI, int MODE>
__global__ void __launch_bounds__(256, 1)
bgemm_kernel(const void* __restrict__ Ahi_, const void* __restrict__ Alo_,
             const void* __restrict__ Bhi_, const void* __restrict__ Blo_,
             int N, int K,
             long long az, long long bz, long long oz,
             float* __restrict__ outf,
             void* __restrict__ outhi_,
             const float* __restrict__ bias, long long biasz,
             const float* __restrict__ gate)
{
    extern __shared__ char smem[];
    const uint32_t sbase = smem_u32(smem);
    const int tid  = threadIdx.x;
    const int wid  = tid >> 5;
    const int lane = tid & 31;
    const int wm   = wid >> 1;
    const int wn   = wid & 1;
    const int m0 = blockIdx.y * BM;
    const int n0 = blockIdx.x * BN;
    const int e  = blockIdx.z;

    constexpr int NSTG = (MODE == 0) ? 2 : 4;
    constexpr int STG = (MODE == 0) ? (2*A_BYTES + 2*B_BYTES) : (A_BYTES + B_BYTES);
    const uint16_t* pAhi = (const uint16_t*)Ahi_ + (size_t)e * az;
    const uint16_t* pAlo = (const uint16_t*)Alo_ + (size_t)e * az;
    const uint16_t* pBhi = (const uint16_t*)Bhi_ + (size_t)e * bz;
    const uint16_t* pBlo = (const uint16_t*)Blo_ + (size_t)e * bz;
    constexpr uint32_t B_OFF = (MODE == 0) ? 2*A_BYTES : A_BYTES;

    const int lrow = tid >> 3;
    const int lc8  = (tid & 7) * 8;

    float acc[4][8][4];
    #pragma unroll
    for (int i = 0; i < 4; i++)
        #pragma unroll
        for (int j = 0; j < 8; j++)
            #pragma unroll
            for (int q = 0; q < 4; q++) acc[i][j][q] = 0.f;

    const int NB = K / BK;

    auto load_stage = [&](int kb, int slot) {
        const int kk = kb * BK;
        const uint32_t so = sbase + slot * STG;
        #pragma unroll
        for (int i = 0; i < 8; i++) {
            const int row = lrow + i * 32;
            const uint32_t sa = so + (uint32_t)(row * LDS + lc8) * 2;
            const size_t ga = (size_t)(m0 + row) * K + kk + lc8;
            cp16(sa, pAhi + ga);
            if (MODE == 0) cp16(sa + A_BYTES, pAlo + ga);
        }
        #pragma unroll
        for (int i = 0; i < 4; i++) {
            const int row = lrow + i * 32;
            const uint32_t sb = so + B_OFF + (uint32_t)(row * LDS + lc8) * 2;
            const size_t gb = (size_t)(n0 + row) * K + kk + lc8;
            cp16(sb, pBhi + gb);
            if (MODE == 0) cp16(sb + B_BYTES, pBlo + gb);
        }
        CP_COMMIT();
    };

    // prefetch NSTG-1 stages
    #pragma unroll
    for (int p = 0; p < NSTG - 1; p++) load_stage(p, p);

    for (int kb = 0; kb < NB; kb++) {
        const int s = kb % NSTG;
        if (kb + NSTG - 1 < NB) {
            load_stage(kb + NSTG - 1, (kb + NSTG - 1) % NSTG);
            CP_WAIT(NSTG - 1);
        } else if (kb + 1 < NB) {
            CP_WAIT(1);
        } else {
            CP_WAIT(0);
        }
        __syncthreads();

        const uint32_t so = sbase + s * STG;
        #pragma unroll
        for (int k16 = 0; k16 < 4; k16++) {
            const int kc = k16 * 16;
            uint32_t ah[4][4], al[4][4], bh[4][4], bl[4][4];
            #pragma unroll
            for (int mt = 0; mt < 4; mt++) {
                const int arow = wm * 64 + mt * 16 + (lane & 15);
                const int acol = kc + ((lane >> 4) << 3);
                const uint32_t addr = so + (uint32_t)(arow * LDS + acol) * 2;
                LDSM_X4(ah[mt][0], ah[mt][1], ah[mt][2], ah[mt][3], addr);
                if (MODE == 0) LDSM_X4(al[mt][0], al[mt][1], al[mt][2], al[mt][3], addr + A_BYTES);
            }
            #pragma unroll
            for (int p = 0; p < 4; p++) {
                const int nrow = wn * 64 + p * 16 + (lane & 7) + ((lane & 16) >> 1);
                const int ncol = kc + (lane & 8);
                const uint32_t addr = so + B_OFF + (uint32_t)(nrow * LDS + ncol) * 2;
                LDSM_X4(bh[p][0], bh[p][1], bh[p][2], bh[p][3], addr);
                if (MODE == 0) LDSM_X4(bl[p][0], bl[p][1], bl[p][2], bl[p][3], addr + B_BYTES);
            }
            #pragma unroll
            for (int mt = 0; mt < 4; mt++) {
                #pragma unroll
                for (int nt = 0; nt < 8; nt++) {
                    const int pr = nt >> 1, ix = (nt & 1) * 2;
                    if (MODE == 0) {
                        MMA_BF16(acc[mt][nt], ah[mt], bh[pr][ix], bh[pr][ix+1]);
                        MMA_BF16(acc[mt][nt], al[mt], bh[pr][ix], bh[pr][ix+1]);
                        MMA_BF16(acc[mt][nt], ah[mt], bl[pr][ix], bl[pr][ix+1]);
                    } else {
                        MMA_F16(acc[mt][nt], ah[mt], bh[pr][ix], bh[pr][ix+1]);
                    }
                }
            }
        }
        __syncthreads();
    }

    #pragma unroll
    for (int mt = 0; mt < 4; mt++) {
        const int rA = m0 + wm * 64 + mt * 16 + (lane >> 2);
        const int rB = rA + 8;
        float gv0 = 0.f, gv1 = 0.f;
        if (EPI == 2) {
            gv0 = gate[(size_t)rA * Ex + e];
            gv1 = gate[(size_t)rB * Ex + e];
        }
        #pragma unroll
        for (int nt = 0; nt < 8; nt++) {
            const int col = n0 + wn * 64 + nt * 8 + (lane & 3) * 2;
            float d0 = acc[mt][nt][0], d1 = acc[mt][nt][1];
            float d2 = acc[mt][nt][2], d3 = acc[mt][nt][3];
            if (EPI == 0) {
                *(float2*)(outf + (size_t)rA * N + col) = make_float2(d0, d1);
                *(float2*)(outf + (size_t)rB * N + col) = make_float2(d2, d3);
            } else if (EPI == 1) {
                const float b0 = bias[(size_t)e * biasz + col];
                const float b1 = bias[(size_t)e * biasz + col + 1];
                float v0 = gelu_f(d0 + b0), v1 = gelu_f(d1 + b1);
                float v2 = gelu_f(d2 + b0), v3 = gelu_f(d3 + b1);
                const size_t gA = (size_t)e * oz + (size_t)rA * N + col;
                const size_t gB = (size_t)e * oz + (size_t)rB * N + col;
                __half* oh = (__half*)outhi_;
                *(__half2*)(oh + gA) = __halves2half2(__float2half(v0), __float2half(v1));
                *(__half2*)(oh + gB) = __halves2half2(__float2half(v2), __float2half(v3));
            } else {
                const float b0 = bias[(size_t)e * biasz + col];
                const float b1 = bias[(size_t)e * biasz + col + 1];
                const size_t gA = (size_t)e * oz + (size_t)rA * N + col;
                const size_t gB = (size_t)e * oz + (size_t)rB * N + col;
                *(float2*)(outf + gA) = make_float2(gv0 * (d0 + b0), gv0 * (d1 + b1));
                *(float2*)(outf + gB) = make_float2(gv1 * (d2 + b0), gv1 * (d3 + b1));
            }
        }
    }
}

// ---------------- l2norm + scale -> bf16 hi/lo ----------------
__global__ void l2n_kernel(const float* __restrict__ qkv, int base,
                           const float* __restrict__ scale,
                           __nv_bfloat16* __restrict__ oh, __nv_bfloat16* __restrict__ ol)
{
    const int r    = blockIdx.x * 8 + (threadIdx.x >> 5);
    const int lane = threadIdx.x & 31;
    const int b = r / (Hh * Sq);
    const int h = (r / Sq) % Hh;
    const int s = r % Sq;
    const float* src = qkv + (size_t)(b * Sq + s) * (3*Dm) + base + h * DHd;
    float v0 = src[lane], v1 = src[lane + 32];
    float ss = v0 * v0 + v1 * v1;
    #pragma unroll
    for (int o = 16; o; o >>= 1) ss += __shfl_xor_sync(0xffffffffu, ss, o);
    const float inv = rsqrtf(ss + 1e-12f);
    float f0 = v0 * inv * scale[h * DHd + lane];
    float f1 = v1 * inv * scale[h * DHd + lane + 32];
    const size_t d = (size_t)r * DHd;
    __nv_bfloat16 h0 = __float2bfloat16(f0);
    __nv_bfloat16 h1 = __float2bfloat16(f1);
    oh[d + lane]      = h0;
    ol[d + lane]      = __float2bfloat16(f0 - __bfloat162float(h0));
    oh[d + lane + 32] = h1;
    ol[d + lane + 32] = __float2bfloat16(f1 - __bfloat162float(h1));
}

// ---------------- V transpose -> vT hi/lo [bh, d, s] ----------------
__global__ void vtrans_kernel(const float* __restrict__ qkv,
                              __nv_bfloat16* __restrict__ vh, __nv_bfloat16* __restrict__ vl)
{
    __shared__ float t[32][33];
    const int bh = blockIdx.z;
    const int b = bh >> 4, h = bh & 15;
    const int s0 = blockIdx.x * 32, d0 = blockIdx.y * 32;
    const int tx = threadIdx.x, ty = threadIdx.y;
    #pragma unroll
    for (int i = 0; i < 4; i++)
        t[ty + 8*i][tx] = qkv[(size_t)(b * Sq + s0 + ty + 8*i) * (3*Dm) + 2*Dm + h * DHd + d0 + tx];
    __syncthreads();
    #pragma unroll
    for (int i = 0; i < 4; i++) {
        float v = t[tx][ty + 8*i];
        const size_t o = ((size_t)bh * DHd + d0 + ty + 8*i) * Sq + s0 + tx;
        __nv_bfloat16 hh = __float2bfloat16(v);
        vh[o] = hh;
        vl[o] = __float2bfloat16(v - __bfloat162float(hh));
    }
}

// ---------------- fused flash attention (heavy tiles scheduled first) -------
__global__ void __launch_bounds__(256, 1)
flash_kernel(const __nv_bfloat16* __restrict__ qh, const __nv_bfloat16* __restrict__ ql,
             const __nv_bfloat16* __restrict__ kh, const __nv_bfloat16* __restrict__ kl,
             const __nv_bfloat16* __restrict__ vth, const __nv_bfloat16* __restrict__ vtl,
             __nv_bfloat16* __restrict__ aohi, __nv_bfloat16* __restrict__ aolo)
{
    extern __shared__ char smem[];
    const uint32_t sbase = smem_u32(smem);
    const int tid  = threadIdx.x;
    const int wid  = tid >> 5;
    const int lane = tid & 31;
    const int it = gridDim.x - 1 - blockIdx.x;   // heavy rows first
    const int bh = blockIdx.y;
    const int b = bh >> 4, h = bh & 15;

    const int lrow = tid >> 3;
    const int lc8  = (tid & 7) * 8;
    const int vrow = tid >> 4;
    const int vc8  = (tid & 15) * 8;

    const uint32_t sq = sbase;
    const uint32_t skv0 = sbase + 2 * FQ_BYTES;

    #pragma unroll
    for (int i = 0; i < 4; i++) {
        const int row = lrow + i * 32;
        const uint32_t sa = sq + (uint32_t)(row * LDS + lc8) * 2;
        const size_t gq = ((size_t)bh * Sq + it * 128 + row) * DHd + lc8;
        cp16(sa,            qh + gq);
        cp16(sa + FQ_BYTES, ql + gq);
    }
    {
        const uint32_t so = skv0;
        #pragma unroll
        for (int i = 0; i < 4; i++) {
            const int row = lrow + i * 32;
            const uint32_t sa = so + (uint32_t)(row * LDS + lc8) * 2;
            const size_t gk = ((size_t)bh * Sq + row) * DHd + lc8;
            cp16(sa,            kh + gk);
            cp16(sa + FQ_BYTES, kl + gk);
        }
        #pragma unroll
        for (int i = 0; i < 4; i++) {
            const int row = vrow + i * 16;
            const uint32_t sa = so + 2*FQ_BYTES + (uint32_t)(row * LDSV + vc8) * 2;
            const size_t gv = ((size_t)bh * DHd + row) * Sq + vc8;
            cp16(sa,            vth + gv);
            cp16(sa + FV_BYTES, vtl + gv);
        }
        CP_COMMIT();
    }

    float mrow[2] = {-1e30f, -1e30f};
    float lrowv[2] = {0.f, 0.f};
    float oacc[8][4];
    #pragma unroll
    for (int j = 0; j < 8; j++)
        #pragma unroll
        for (int q = 0; q < 4; q++) oacc[j][q] = 0.f;

    uint32_t qa_hi[4][4], qa_lo[4][4];
    bool qloaded = false;

    const int grA = it * 128 + wid * 16 + (lane >> 2);
    const int grB = grA + 8;

    for (int jt = 0; jt <= it; jt++) {
        const int s = jt & 1;
        if (jt < it) {
            const uint32_t so = skv0 + (s ^ 1) * FK_STAGE;
            #pragma unroll
            for (int i = 0; i < 4; i++) {
                const int row = lrow + i * 32;
                const uint32_t sa = so + (uint32_t)(row * LDS + lc8) * 2;
                const size_t gk = ((size_t)bh * Sq + (jt + 1) * 128 + row) * DHd + lc8;
                cp16(sa,            kh + gk);
                cp16(sa + FQ_BYTES, kl + gk);
            }
            #pragma unroll
            for (int i = 0; i < 4; i++) {
                const int row = vrow + i * 16;
                const uint32_t sa = so + 2*FQ_BYTES + (uint32_t)(row * LDSV + vc8) * 2;
                const size_t gv = ((size_t)bh * DHd + row) * Sq + (jt + 1) * 128 + vc8;
                cp16(sa,            vth + gv);
                cp16(sa + FV_BYTES, vtl + gv);
            }
            CP_COMMIT();
            CP_WAIT(1);
        } else {
            CP_WAIT(0);
        }
        __syncthreads();

        if (!qloaded) {
            qloaded = true;
            #pragma unroll
            for (int k16 = 0; k16 < 4; k16++) {
                const int arow = wid * 16 + (lane & 15);
                const int acol = k16 * 16 + ((lane >> 4) << 3);
                const uint32_t addr = sq + (uint32_t)(arow * LDS + acol) * 2;
                LDSM_X4(qa_hi[k16][0], qa_hi[k16][1], qa_hi[k16][2], qa_hi[k16][3], addr);
                LDSM_X4(qa_lo[k16][0], qa_lo[k16][1], qa_lo[k16][2], qa_lo[k16][3], addr + FQ_BYTES);
            }
        }

        const uint32_t sk = skv0 + s * FK_STAGE;
        const uint32_t sv = sk + 2 * FQ_BYTES;

        float sacc[16][4];
        #pragma unroll
        for (int j = 0; j < 16; j++)
            #pragma unroll
            for (int q = 0; q < 4; q++) sacc[j][q] = 0.f;

        #pragma unroll
        for (int k16 = 0; k16 < 4; k16++) {
            const int kc = k16 * 16;
            uint32_t kbh[8][4], kbl[8][4];
            #pragma unroll
            for (int p = 0; p < 8; p++) {
                const int nrow = p * 16 + (lane & 7) + ((lane & 16) >> 1);
                const int ncol = kc + (lane & 8);
                const uint32_t addr = sk + (uint32_t)(nrow * LDS + ncol) * 2;
                LDSM_X4(kbh[p][0], kbh[p][1], kbh[p][2], kbh[p][3], addr);
                LDSM_X4(kbl[p][0], kbl[p][1], kbl[p][2], kbl[p][3], addr + FQ_BYTES);
            }
            #pragma unroll
            for (int nt = 0; nt < 16; nt++) {
                const int pr = nt >> 1, ix = (nt & 1) * 2;
                MMA_BF16(sacc[nt], qa_hi[k16], kbh[pr][ix], kbh[pr][ix+1]);
                MMA_BF16(sacc[nt], qa_lo[k16], kbh[pr][ix], kbh[pr][ix+1]);
                MMA_BF16(sacc[nt], qa_hi[k16], kbl[pr][ix], kbl[pr][ix+1]);
            }
        }

        float mxA = -1e30f, mxB = -1e30f;
        #pragma unroll
        for (int nt = 0; nt < 16; nt++) {
            const int col = jt * 128 + nt * 8 + (lane & 3) * 2;
            float v0 = sacc[nt][0] * QK_SCALE;
            float v1 = sacc[nt][1] * QK_SCALE;
            float v2 = sacc[nt][2] * QK_SCALE;
            float v3 = sacc[nt][3] * QK_SCALE;
            if (jt == it) {
                if (col     > grA) v0 = -1e30f;
                if (col + 1 > grA) v1 = -1e30f;
                if (col     > grB) v2 = -1e30f;
                if (col + 1 > grB) v3 = -1e30f;
            }
            sacc[nt][0] = v0; sacc[nt][1] = v1; sacc[nt][2] = v2; sacc[nt][3] = v3;
            mxA = fmaxf(mxA, fmaxf(v0, v1));
            mxB = fmaxf(mxB, fmaxf(v2, v3));
        }
        #pragma unroll
        for (int o = 1; o <= 2; o <<= 1) {
            mxA = fmaxf(mxA, __shfl_xor_sync(0xffffffffu, mxA, o));
            mxB = fmaxf(mxB, __shfl_xor_sync(0xffffffffu, mxB, o));
        }
        const float mnA = fmaxf(mrow[0], mxA);
        const float mnB = fmaxf(mrow[1], mxB);
        const float scA = __expf(mrow[0] - mnA);
        const float scB = __expf(mrow[1] - mnB);
        mrow[0] = mnA; mrow[1] = mnB;

        #pragma unroll
        for (int j = 0; j < 8; j++) {
            oacc[j][0] *= scA; oacc[j][1] *= scA;
            oacc[j][2] *= scB; oacc[j][3] *= scB;
        }

        float rsA = 0.f, rsB = 0.f;
        #pragma unroll
        for (int t = 0; t < 8; t++) {
            float p00 = __expf(sacc[2*t][0]   - mnA);
            float p01 = __expf(sacc[2*t][1]   - mnA);
            float p02 = __expf(sacc[2*t][2]   - mnB);
            float p03 = __expf(sacc[2*t][3]   - mnB);
            float p10 = __expf(sacc[2*t+1][0] - mnA);
            float p11 = __expf(sacc[2*t+1][1] - mnA);
            float p12 = __expf(sacc[2*t+1][2] - mnB);
            float p13 = __expf(sacc[2*t+1][3] - mnB);
            rsA += p00 + p01 + p10 + p11;
            rsB += p02 + p03 + p12 + p13;

            uint32_t pa_hi[4], pa_lo[4];
            pa_hi[0] = pack_bf16(p00, p01);
            pa_hi[1] = pack_bf16(p02, p03);
            pa_hi[2] = pack_bf16(p10, p11);
            pa_hi[3] = pack_bf16(p12, p13);
            {
                __nv_bfloat162* ph = (__nv_bfloat162*)pa_hi;
                pa_lo[0] = pack_bf16(p00 - __bfloat162float(ph[0].x), p01 - __bfloat162float(ph[0].y));
                pa_lo[1] = pack_bf16(p02 - __bfloat162float(ph[1].x), p03 - __bfloat162float(ph[1].y));
                pa_lo[2] = pack_bf16(p10 - __bfloat162float(ph[2].x), p11 - __bfloat162float(ph[2].y));
                pa_lo[3] = pack_bf16(p12 - __bfloat162float(ph[3].x), p13 - __bfloat162float(ph[3].y));
            }

            const int kc = t * 16;
            uint32_t vbh[4][4], vbl[4][4];
            #pragma unroll
            for (int p = 0; p < 4; p++) {
                const int nrow = p * 16 + (lane & 7) + ((lane & 16) >> 1);
                const int ncol = kc + (lane & 8);
                const uint32_t addr = sv + (uint32_t)(nrow * LDSV + ncol) * 2;
                LDSM_X4(vbh[p][0], vbh[p][1], vbh[p][2], vbh[p][3], addr);
                LDSM_X4(vbl[p][0], vbl[p][1], vbl[p][2], vbl[p][3], addr + FV_BYTES);
            }
            #pragma unroll
            for (int nto = 0; nto < 8; nto++) {
                const int pr = nto >> 1, ix = (nto & 1) * 2;
                MMA_BF16(oacc[nto], pa_hi, vbh[pr][ix], vbh[pr][ix+1]);
                MMA_BF16(oacc[nto], pa_lo, vbh[pr][ix], vbh[pr][ix+1]);
                MMA_BF16(oacc[nto], pa_hi, vbl[pr][ix], vbl[pr][ix+1]);
            }
        }
        #pragma unroll
        for (int o = 1; o <= 2; o <<= 1) {
            rsA += __shfl_xor_sync(0xffffffffu, rsA, o);
            rsB += __shfl_xor_sync(0xffffffffu, rsB, o);
        }
        lrowv[0] = lrowv[0] * scA + rsA;
        lrowv[1] = lrowv[1] * scB + rsB;

        __syncthreads();
    }

    const float invA = 1.0f / lrowv[0];
    const float invB = 1.0f / lrowv[1];
    const int sA = it * 128 + wid * 16 + (lane >> 2);
    const int sB = sA + 8;
    #pragma unroll
    for (int nto = 0; nto < 8; nto++) {
        const int d = nto * 8 + (lane & 3) * 2;
        const size_t gA = ((size_t)(b * Sq + sA)) * Dm + h * DHd + d;
        const size_t gB = ((size_t)(b * Sq + sB)) * Dm + h * DHd + d;
        float v0 = oacc[nto][0] * invA, v1 = oacc[nto][1] * invA;
        float v2 = oacc[nto][2] * invB, v3 = oacc[nto][3] * invB;
        __nv_bfloat16 h0 = __float2bfloat16(v0), h1 = __float2bfloat16(v1);
        __nv_bfloat16 h2 = __float2bfloat16(v2), h3 = __float2bfloat16(v3);
        __nv_bfloat162 hhA; hhA.x = h0; hhA.y = h1;
        __nv_bfloat162 hhB; hhB.x = h2; hhB.y = h3;
        __nv_bfloat162 llA, llB;
        llA.x = __float2bfloat16(v0 - __bfloat162float(h0));
        llA.y = __float2bfloat16(v1 - __bfloat162float(h1));
        llB.x = __float2bfloat16(v2 - __bfloat162float(h2));
        llB.y = __float2bfloat16(v3 - __bfloat162float(h3));
        *(__nv_bfloat162*)(aohi + gA) = hhA;
        *(__nv_bfloat162*)(aolo + gA) = llA;
        *(__nv_bfloat162*)(aohi + gB) = hhB;
        *(__nv_bfloat162*)(aolo + gB) = llB;
    }
}

// ---------------- sum experts + final LayerNorm ----------------
__global__ void redln_kernel(const float* __restrict__ expout, const float* __restrict__ g,
                             const float* __restrict__ b, float* __restrict__ out)
{
    __shared__ float buf[Dm];
    __shared__ float red[256];
    const int row = blockIdx.x;
    const int tid = threadIdx.x;
    float s = 0.f;
    for (int i = tid; i < Dm; i += 256) {
        float v = 0.f;
        #pragma unroll
        for (int e = 0; e < Ex; e++)
            v += expout[(size_t)e * ROWS * Dm + (size_t)row * Dm + i];
        buf[i] = v; s += v;
    }
    red[tid] = s; __syncthreads();
    for (int off = 128; off > 0; off >>= 1) { if (tid < off) red[tid] += red[tid+off]; __syncthreads(); }
    const float mean = red[0] * (1.0f / Dm);
    __syncthreads();
    float s2 = 0.f;
    for (int i = tid; i < Dm; i += 256) { float d = buf[i] - mean; s2 += d * d; }
    red[tid] = s2; __syncthreads();
    for (int off = 128; off > 0; off >>= 1) { if (tid < off) red[tid] += red[tid+off]; __syncthreads(); }
    const float inv = rsqrtf(red[0] * (1.0f / Dm) + 1e-5f);
    for (int i = tid; i < Dm; i += 256)
        out[(size_t)row * Dm + i] = (buf[i] - mean) * inv * g[i] + b[i];
}

// ---------------- launch ----------------
extern "C" void kernel_launch(void* const* d_in, const int* in_sizes, int n_in,
                              void* d_out, int out_size)
{
    const float* x       = (const float*)d_in[0];
    const float* ln_g    = (const float*)d_in[1];
    const float* ln_b    = (const float*)d_in[2];
    const float* Wq      = (const float*)d_in[3];
    const float* Wk      = (const float*)d_in[4];
    const float* Wv      = (const float*)d_in[5];
    const float* q_scale = (const float*)d_in[6];
    const float* k_scale = (const float*)d_in[7];
    const float* Wo      = (const float*)d_in[8];
    const float* gate_w  = (const float*)d_in[9];
    const float* gate_b  = (const float*)d_in[10];
    const float* w1      = (const float*)d_in[11];
    const float* b1      = (const float*)d_in[12];
    const float* w2      = (const float*)d_in[13];
    const float* b2      = (const float*)d_in[14];
    float* out = (float*)d_out;

    __nv_bfloat16 *h1hi, *h1lo, *aohi, *aolo;
    __half *h2h16, *hid, *w1Th, *w2Th;
    __nv_bfloat16 *qnh, *qnl, *knh, *knl, *vTh, *vTl;
    __nv_bfloat16 *wqkvThi, *wqkvTlo, *woThi, *woTlo;
    float *qkvf, *o, *h2, *gate, *expout;
    cudaGetSymbolAddress((void**)&h1hi, g_h1hi);   cudaGetSymbolAddress((void**)&h1lo, g_h1lo);
    cudaGetSymbolAddress((void**)&qkvf, g_qkvf);
    cudaGetSymbolAddress((void**)&qnh, g_qnh);     cudaGetSymbolAddress((void**)&qnl, g_qnl);
    cudaGetSymbolAddress((void**)&knh, g_knh);     cudaGetSymbolAddress((void**)&knl, g_knl);
    cudaGetSymbolAddress((void**)&vTh, g_vTh);     cudaGetSymbolAddress((void**)&vTl, g_vTl);
    cudaGetSymbolAddress((void**)&aohi, g_aohi);   cudaGetSymbolAddress((void**)&aolo, g_aolo);
    cudaGetSymbolAddress((void**)&o, g_o);         cudaGetSymbolAddress((void**)&h2, g_h2);
    cudaGetSymbolAddress((void**)&h2h16, g_h2h16);
    cudaGetSymbolAddress((void**)&gate, g_gate);
    cudaGetSymbolAddress((void**)&hid, g_hid);
    cudaGetSymbolAddress((void**)&expout, g_expout);
    cudaGetSymbolAddress((void**)&wqkvThi, g_wqkvThi); cudaGetSymbolAddress((void**)&wqkvTlo, g_wqkvTlo);
    cudaGetSymbolAddress((void**)&woThi, g_woThi);     cudaGetSymbolAddress((void**)&woTlo, g_woTlo);
    cudaGetSymbolAddress((void**)&w1Th, g_w1Th);
    cudaGetSymbolAddress((void**)&w2Th, g_w2Th);

    cudaFuncSetAttribute(bgemm_kernel<0,0>, cudaFuncAttributeMaxDynamicSharedMemorySize, SMEM_M0);
    cudaFuncSetAttribute(bgemm_kernel<1,2>, cudaFuncAttributeMaxDynamicSharedMemorySize, SMEM_M2);
    cudaFuncSetAttribute(bgemm_kernel<2,2>, cudaFuncAttributeMaxDynamicSharedMemorySize, SMEM_M2);
    cudaFuncSetAttribute(flash_kernel,      cudaFuncAttributeMaxDynamicSharedMemorySize, SMEM_FL);

    // ---- side stream: weight prep not needed until step 5/7 -----------------
    cudaStream_t s2;
    cudaStreamCreateWithFlags(&s2, cudaStreamNonBlocking);
    cudaEvent_t evFork, evJoin;
    cudaEventCreateWithFlags(&evFork, cudaEventDisableTiming);
    cudaEventCreateWithFlags(&evJoin, cudaEventDisableTiming);

    // QKV weight prep must complete before step 2 -> keep on main stream
    wprep_kernel<<<dim3(Dm/32, Dm/32, 1), dim3(32,8)>>>(Wq, wqkvThi,           wqkvTlo,           Dm, Dm);
    wprep_kernel<<<dim3(Dm/32, Dm/32, 1), dim3(32,8)>>>(Wk, wqkvThi + Dm*Dm,   wqkvTlo + Dm*Dm,   Dm, Dm);
    wprep_kernel<<<dim3(Dm/32, Dm/32, 1), dim3(32,8)>>>(Wv, wqkvThi + 2*Dm*Dm, wqkvTlo + 2*Dm*Dm, Dm, Dm);

    // fork: Wo/w1/w2 prep runs concurrently with LN + QKV GEMM + attention
    cudaEventRecord(evFork, 0);
    cudaStreamWaitEvent(s2, evFork, 0);
    wprep_kernel<<<dim3(Dm/32, Dm/32, 1), dim3(32,8), 0, s2>>>(Wo, woThi, woTlo, Dm, Dm);
    wprep16_kernel<<<dim3(FFd/32, Dm/64, Ex), 256, 0, s2>>>(w1, w1Th, Dm, FFd);
    wprep16_kernel<<<dim3(Dm/32, FFd/64, Ex), 256, 0, s2>>>(w2, w2Th, FFd, Dm);
    cudaEventRecord(evJoin, s2);

    // 1. pre-attention LN -> bf16 hi/lo
    ln_kernel<<<ROWS, 256>>>(x, ln_g, ln_b, nullptr, h1hi, h1lo, nullptr,
                             nullptr, nullptr, nullptr);

    // 2. fused QKV projection (bf16 3-term)
    bgemm_kernel<0,0><<<dim3(3*Dm/BN, ROWS/BM, 1), 256, SMEM_M0>>>(
        h1hi, h1lo, wqkvThi, wqkvTlo, 3*Dm, Dm, 0, 0, 0,
        qkvf, nullptr, nullptr, 0, nullptr);

    // 3. l2norm -> bf16 hi/lo; v transpose
    l2n_kernel<<<(BH*Sq)/8, 256>>>(qkvf, 0,  q_scale, qnh, qnl);
    l2n_kernel<<<(BH*Sq)/8, 256>>>(qkvf, Dm, k_scale, knh, knl);
    vtrans_kernel<<<dim3(Sq/32, DHd/32, BH), dim3(32,8)>>>(qkvf, vTh, vTl);

    // 4. fused flash attention (heavy tiles first)
    flash_kernel<<<dim3(Sq/128, BH), 256, SMEM_FL>>>(qnh, qnl, knh, knl, vTh, vTl, aohi, aolo);

    // join: Wo/w1/w2 prep must be done before step 5
    cudaStreamWaitEvent(0, evJoin, 0);

    // 5. output projection (bf16 3-term) + mid LN (with fused gate softmax)
    bgemm_kernel<0,0><<<dim3(Dm/BN, ROWS/BM, 1), 256, SMEM_M0>>>(
        aohi, aolo, woThi, woTlo, Dm, Dm, 0, 0, 0,
        o, nullptr, nullptr, 0, nullptr);
    ln_kernel<<<ROWS, 256>>>(o, ln_g, ln_b, nullptr, nullptr, nullptr, h2h16,
                             gate_w, gate_b, gate);

    // 7. MoE GEMM1 (fp16 1-term, 4-stage)
    bgemm_kernel<1,2><<<dim3(FFd/BN, ROWS/BM, Ex), 256, SMEM_M2>>>(
        h2h16, nullptr, w1Th, nullptr, FFd, Dm,
        0, (long long)FFd*Dm, (long long)ROWS*FFd,
        nullptr, hid, b1, FFd, nullptr);

    // 8. MoE GEMM2 (fp16 1-term, 4-stage)
    bgemm_kernel<2,2><<<dim3(Dm/BN, ROWS/BM, Ex), 256, SMEM_M2>>>(
        hid, nullptr, w2Th, nullptr, Dm, FFd,
        (long long)ROWS*FFd, (long long)Dm*FFd, (long long)ROWS*Dm,
        expout, nullptr, b2, Dm, gate);

    // 9. sum experts + final LN -> out
    redln_kernel<<<ROWS, 256>>>(expout, ln_g, ln_b, out);

    cudaEventDestroy(evFork);
    cudaEventDestroy(evJoin);
    cudaStreamDestroy(s2);
}

// round 14
// speedup vs baseline: 1.0111x; 1.0111x over previous
#include <cuda_runtime.h>
#include <cuda_bf16.h>
#include <cuda_fp16.h>
#include <math.h>
#include <stdint.h>

// ---------------- problem constants ----------------
#define Bc   2
#define Sq   1024
#define Dm   1024
#define Hh   16
#define DHd  64
#define Ex   8
#define FFd  4096
#define BH   (Bc*Hh)     // 32
#define ROWS (Bc*Sq)     // 2048
#define QK_SCALE 10.0f

// GEMM tiling (bgemm: 256x128 CTA tile)
#define BM 256
#define BN 128
#define BK 64
#define LDS 72                        // BK + 8 pad (16-bit units)
#define A_BYTES (256*LDS*2)           // 36864
#define B_BYTES (128*LDS*2)           // 18432
#define SMEM_M0 (2*(2*A_BYTES + 2*B_BYTES))  // 221184 (bf16 3-term, 2 stages)
#define SMEM_M2 (3*(A_BYTES + B_BYTES))      // 165888 (fp16 1-term, 3 stages)

// flash attention tiling
#define FQ_BYTES (128*LDS*2)          // 18432
#define LDSV 136
#define FV_BYTES (64*LDSV*2)          // 17408
#define FK_STAGE (2*FQ_BYTES + 2*FV_BYTES)   // 71680
#define SMEM_FL (2*FQ_BYTES + 2*FK_STAGE)    // 180224

// ---------------- low-level helpers ----------------
__device__ __forceinline__ uint32_t smem_u32(const void* p) {
    uint32_t a;
    asm("{ .reg .u64 t; cvta.to.shared.u64 t, %1; cvt.u32.u64 %0, t; }" : "=r"(a) : "l"(p));
    return a;
}
__device__ __forceinline__ void cp16(uint32_t dst, const void* src) {
    asm volatile("cp.async.cg.shared.global [%0], [%1], 16;" :: "r"(dst), "l"(src));
}
#define CP_COMMIT() asm volatile("cp.async.commit_group;" ::: "memory")
#define CP_WAIT(n)  asm volatile("cp.async.wait_group %0;" :: "n"(n) : "memory")

#define LDSM_X4(r0, r1, r2, r3, addr) \
    asm volatile("ldmatrix.sync.aligned.m8n8.x4.shared.b16 {%0,%1,%2,%3}, [%4];" \
        : "=r"(r0), "=r"(r1), "=r"(r2), "=r"(r3) : "r"(addr))

#define MMA_BF16(d, a, b0, b1) \
    asm volatile("mma.sync.aligned.m16n8k16.row.col.f32.bf16.bf16.f32 " \
        "{%0,%1,%2,%3}, {%4,%5,%6,%7}, {%8,%9}, {%0,%1,%2,%3};" \
        : "+f"((d)[0]), "+f"((d)[1]), "+f"((d)[2]), "+f"((d)[3]) \
        : "r"((a)[0]), "r"((a)[1]), "r"((a)[2]), "r"((a)[3]), "r"(b0), "r"(b1))

#define MMA_F16(d, a, b0, b1) \
    asm volatile("mma.sync.aligned.m16n8k16.row.col.f32.f16.f16.f32 " \
        "{%0,%1,%2,%3}, {%4,%5,%6,%7}, {%8,%9}, {%0,%1,%2,%3};" \
        : "+f"((d)[0]), "+f"((d)[1]), "+f"((d)[2]), "+f"((d)[3]) \
        : "r"((a)[0]), "r"((a)[1]), "r"((a)[2]), "r"((a)[3]), "r"(b0), "r"(b1))

__device__ __forceinline__ uint32_t pack_bf16(float a, float b) {
    __nv_bfloat162 t;
    t.x = __float2bfloat16(a);
    t.y = __float2bfloat16(b);
    return *(uint32_t*)&t;
}

// ---------------- scratch (device globals) ----------------
__device__ __nv_bfloat16 g_h1hi[ROWS*Dm], g_h1lo[ROWS*Dm];
__device__ float g_qkvf[ROWS*3*Dm];
__device__ __nv_bfloat16 g_qnh[BH*Sq*DHd], g_qnl[BH*Sq*DHd];
__device__ __nv_bfloat16 g_knh[BH*Sq*DHd], g_knl[BH*Sq*DHd];
__device__ __nv_bfloat16 g_vTh[BH*DHd*Sq], g_vTl[BH*DHd*Sq];
__device__ __nv_bfloat16 g_aohi[ROWS*Dm], g_aolo[ROWS*Dm];
__device__ float g_o[ROWS*Dm];
__device__ __half g_h2h16[ROWS*Dm];
__device__ float g_gate[ROWS*Ex];
__device__ __half g_hid[(size_t)Ex*ROWS*FFd];
__device__ float g_expout[(size_t)Ex*ROWS*Dm];
__device__ __nv_bfloat16 g_wqkvThi[3*Dm*Dm], g_wqkvTlo[3*Dm*Dm];
__device__ __nv_bfloat16 g_woThi[Dm*Dm], g_woTlo[Dm*Dm];
__device__ __half g_w1Th[(size_t)Ex*FFd*Dm];
__device__ __half g_w2Th[(size_t)Ex*Dm*FFd];

// ---------------- math helpers ----------------
__device__ __forceinline__ float gelu_f(float x) {
    float x3 = x * x * x;
    float t  = tanhf(0.7978845608028654f * (x + 0.044715f * x3));
    return 0.5f * x * (1.0f + t);
}

// ---------------- weight transpose + bf16 split (small matrices) -----------
__global__ void wprep_kernel(const float* __restrict__ W, __nv_bfloat16* __restrict__ hi,
                             __nv_bfloat16* __restrict__ lo, int K, int N)
{
    __shared__ float t[32][33];
    const size_t zoff = (size_t)blockIdx.z * K * N;
    const int k0 = blockIdx.y * 32, n0 = blockIdx.x * 32;
    const int tx = threadIdx.x, ty = threadIdx.y;
    #pragma unroll
    for (int i = 0; i < 4; i++)
        t[ty + 8*i][tx] = W[zoff + (size_t)(k0 + ty + 8*i) * N + n0 + tx];
    __syncthreads();
    #pragma unroll
    for (int i = 0; i < 4; i++) {
        float v = t[tx][ty + 8*i];
        const size_t o = zoff + (size_t)(n0 + ty + 8*i) * K + k0 + tx;
        __nv_bfloat16 h = __float2bfloat16(v);
        hi[o] = h;
        lo[o] = __float2bfloat16(v - __bfloat162float(h));
    }
}

// ---------------- FAST weight transpose + fp16: W[K,N] -> fp16 [N,K] -------
__global__ void __launch_bounds__(256)
wprep16_kernel(const float* __restrict__ W, __half* __restrict__ out, int K, int N)
{
    __shared__ float t[64][33];
    const size_t zoff = (size_t)blockIdx.z * K * N;
    const int k0 = blockIdx.y * 64, n0 = blockIdx.x * 32;
    const int tid = threadIdx.x;
    const int lx = tid & 31;
    const int ly = tid >> 5;
    #pragma unroll
    for (int i = 0; i < 8; i++) {
        const int kk = ly + 8 * i;
        t[kk][lx] = W[zoff + (size_t)(k0 + kk) * N + n0 + lx];
    }
    __syncthreads();
    const int n  = tid >> 3;
    const int ks = (tid & 7) * 8;
    __half h[8];
    #pragma unroll
    for (int j = 0; j < 8; j++) h[j] = __float2half(t[ks + j][n]);
    *(uint4*)(out + zoff + (size_t)(n0 + n) * K + k0 + ks) = *(uint4*)h;
}

// ---------------- LayerNorm (+ optional fused gate softmax) ----------------
__global__ void ln_kernel(const float* __restrict__ x, const float* __restrict__ g,
                          const float* __restrict__ b, float* __restrict__ yf,
                          __nv_bfloat16* __restrict__ yhi, __nv_bfloat16* __restrict__ ylo,
                          __half* __restrict__ y16,
                          const float* __restrict__ gw, const float* __restrict__ gb,
                          float* __restrict__ gateOut)
{
    __shared__ float buf[Dm];
    __shared__ float red[256];
    __shared__ float lg[Ex];
    const int row = blockIdx.x;
    const int tid = threadIdx.x;
    const float* xr = x + (size_t)row * Dm;
    float s = 0.f;
    for (int i = tid; i < Dm; i += 256) { float v = xr[i]; buf[i] = v; s += v; }
    red[tid] = s; __syncthreads();
    for (int off = 128; off > 0; off >>= 1) { if (tid < off) red[tid] += red[tid+off]; __syncthreads(); }
    const float mean = red[0] * (1.0f / Dm);
    __syncthreads();
    float s2 = 0.f;
    for (int i = tid; i < Dm; i += 256) { float d = buf[i] - mean; s2 += d * d; }
    red[tid] = s2; __syncthreads();
    for (int off = 128; off > 0; off >>= 1) { if (tid < off) red[tid] += red[tid+off]; __syncthreads(); }
    const float inv = rsqrtf(red[0] * (1.0f / Dm) + 1e-5f);
    for (int i = tid; i < Dm; i += 256) {
        float v = (buf[i] - mean) * inv * g[i] + b[i];
        buf[i] = v;   // keep normalized row for the gate
        if (yf) yf[(size_t)row*Dm + i] = v;
        if (yhi) {
            __nv_bfloat16 h = __float2bfloat16(v);
            yhi[(size_t)row*Dm + i] = h;
            ylo[(size_t)row*Dm + i] = __float2bfloat16(v - __bfloat162float(h));
        }
        if (y16) y16[(size_t)row*Dm + i] = __float2half(v);
    }
    if (gateOut) {
        __syncthreads();
        const int e = tid >> 5, lane = tid & 31;
        float sg = 0.f;
        for (int k = lane; k < Dm; k += 32) sg += buf[k] * gw[k * Ex + e];
        #pragma unroll
        for (int o = 16; o; o >>= 1) sg += __shfl_xor_sync(0xffffffffu, sg, o);
        if (lane == 0) lg[e] = sg + gb[e];
        __syncthreads();
        if (tid == 0) {
            float m = lg[0];
            #pragma unroll
            for (int q = 1; q < Ex; q++) m = fmaxf(m, lg[q]);
            float ex[Ex], sum = 0.f;
            #pragma unroll
            for (int q = 0; q < Ex; q++) { ex[q] = expf(lg[q] - m); sum += ex[q]; }
            const float invs = 1.0f / sum;
            #pragma unroll
            for (int q = 0; q < Ex; q++) gateOut[(size_t)row * Ex + q] = ex[q] * invs;
        }
    }
}

// ---------------- mma.sync GEMM ------------
// MODE 0: bf16 3-term, NSTG=2. MODE 2: fp16 single-term, NSTG=3.
// EPI 0: fp32 store; EPI 1: gelu(acc+bias) -> fp16; EPI 2: gate*(acc+bias) -> fp32
template<int EPI, int MODE>
__global__ void __launch_bounds__(256, 1)
bgemm_kernel(const void* __restrict__ Ahi_, const void* __restrict__ Alo_,
             const void* __restrict__ Bhi_, const void* __restrict__ Blo_,
             int N, int K,
             long long az, long long bz, long long oz,
             float* __restrict__ outf,
             void* __restrict__ outhi_,
             const float* __restrict__ bias, long long biasz,
             const float* __restrict__ gate)
{
    extern __shared__ char smem[];
    const uint32_t sbase = smem_u32(smem);
    const int tid  = threadIdx.x;
    const int wid  = tid >> 5;
    const int lane = tid & 31;
    const int wm   = wid >> 1;
    const int wn   = wid & 1;
    const int m0 = blockIdx.y * BM;
    const int n0 = blockIdx.x * BN;
    const int e  = blockIdx.z;

    constexpr int NSTG = (MODE == 0) ? 2 : 3;
    constexpr int STG = (MODE == 0) ? (2*A_BYTES + 2*B_BYTES) : (A_BYTES + B_BYTES);
    const uint16_t* pAhi = (const uint16_t*)Ahi_ + (size_t)e * az;
    const uint16_t* pAlo = (const uint16_t*)Alo_ + (size_t)e * az;
    const uint16_t* pBhi = (const uint16_t*)Bhi_ + (size_t)e * bz;
    const uint16_t* pBlo = (const uint16_t*)Blo_ + (size_t)e * bz;
    constexpr uint32_t B_OFF = (MODE == 0) ? 2*A_BYTES : A_BYTES;

    const int lrow = tid >> 3;
    const int lc8  = (tid & 7) * 8;

    float acc[4][8][4];
    #pragma unroll
    for (int i = 0; i < 4; i++)
        #pragma unroll
        for (int j = 0; j < 8; j++)
            #pragma unroll
            for (int q = 0; q < 4; q++) acc[i][j][q] = 0.f;

    const int NB = K / BK;

    auto load_stage = [&](int kb, int slot) {
        const int kk = kb * BK;
        const uint32_t so = sbase + slot * STG;
        #pragma unroll
        for (int i = 0; i < 8; i++) {
            const int row = lrow + i * 32;
            const uint32_t sa = so + (uint32_t)(row * LDS + lc8) * 2;
            const size_t ga = (size_t)(m0 + row) * K + kk + lc8;
            cp16(sa, pAhi + ga);
            if (MODE == 0) cp16(sa + A_BYTES, pAlo + ga);
        }
        #pragma unroll
        for (int i = 0; i < 4; i++) {
            const int row = lrow + i * 32;
            const uint32_t sb = so + B_OFF + (uint32_t)(row * LDS + lc8) * 2;
            const size_t gb = (size_t)(n0 + row) * K + kk + lc8;
            cp16(sb, pBhi + gb);
            if (MODE == 0) cp16(sb + B_BYTES, pBlo + gb);
        }
        CP_COMMIT();
    };

    // prefetch NSTG-1 stages
    #pragma unroll
    for (int p = 0; p < NSTG - 1; p++) load_stage(p, p);

    for (int kb = 0; kb < NB; kb++) {
        const int s = kb % NSTG;
        if (kb + NSTG - 1 < NB) {
            load_stage(kb + NSTG - 1, (kb + NSTG - 1) % NSTG);
            CP_WAIT(NSTG - 1);
        } else if (kb + 1 < NB) {
            CP_WAIT(1);
        } else {
            CP_WAIT(0);
        }
        __syncthreads();

        const uint32_t so = sbase + s * STG;
        #pragma unroll
        for (int k16 = 0; k16 < 4; k16++) {
            const int kc = k16 * 16;
            uint32_t ah[4][4], al[4][4], bh[4][4], bl[4][4];
            #pragma unroll
            for (int mt = 0; mt < 4; mt++) {
                const int arow = wm * 64 + mt * 16 + (lane & 15);
                const int acol = kc + ((lane >> 4) << 3);
                const uint32_t addr = so + (uint32_t)(arow * LDS + acol) * 2;
                LDSM_X4(ah[mt][0], ah[mt][1], ah[mt][2], ah[mt][3], addr);
                if (MODE == 0) LDSM_X4(al[mt][0], al[mt][1], al[mt][2], al[mt][3], addr + A_BYTES);
            }
            #pragma unroll
            for (int p = 0; p < 4; p++) {
                const int nrow = wn * 64 + p * 16 + (lane & 7) + ((lane & 16) >> 1);
                const int ncol = kc + (lane & 8);
                const uint32_t addr = so + B_OFF + (uint32_t)(nrow * LDS + ncol) * 2;
                LDSM_X4(bh[p][0], bh[p][1], bh[p][2], bh[p][3], addr);
                if (MODE == 0) LDSM_X4(bl[p][0], bl[p][1], bl[p][2], bl[p][3], addr + B_BYTES);
            }
            #pragma unroll
            for (int mt = 0; mt < 4; mt++) {
                #pragma unroll
                for (int nt = 0; nt < 8; nt++) {
                    const int pr = nt >> 1, ix = (nt & 1) * 2;
                    if (MODE == 0) {
                        MMA_BF16(acc[mt][nt], ah[mt], bh[pr][ix], bh[pr][ix+1]);
                        MMA_BF16(acc[mt][nt], al[mt], bh[pr][ix], bh[pr][ix+1]);
                        MMA_BF16(acc[mt][nt], ah[mt], bl[pr][ix], bl[pr][ix+1]);
                    } else {
                        MMA_F16(acc[mt][nt], ah[mt], bh[pr][ix], bh[pr][ix+1]);
                    }
                }
            }
        }
        __syncthreads();
    }

    #pragma unroll
    for (int mt = 0; mt < 4; mt++) {
        const int rA = m0 + wm * 64 + mt * 16 + (lane >> 2);
        const int rB = rA + 8;
        float gv0 = 0.f, gv1 = 0.f;
        if (EPI == 2) {
            gv0 = gate[(size_t)rA * Ex + e];
            gv1 = gate[(size_t)rB * Ex + e];
        }
        #pragma unroll
        for (int nt = 0; nt < 8; nt++) {
            const int col = n0 + wn * 64 + nt * 8 + (lane & 3) * 2;
            float d0 = acc[mt][nt][0], d1 = acc[mt][nt][1];
            float d2 = acc[mt][nt][2], d3 = acc[mt][nt][3];
            if (EPI == 0) {
                *(float2*)(outf + (size_t)rA * N + col) = make_float2(d0, d1);
                *(float2*)(outf + (size_t)rB * N + col) = make_float2(d2, d3);
            } else if (EPI == 1) {
                const float b0 = bias[(size_t)e * biasz + col];
                const float b1 = bias[(size_t)e * biasz + col + 1];
                float v0 = gelu_f(d0 + b0), v1 = gelu_f(d1 + b1);
                float v2 = gelu_f(d2 + b0), v3 = gelu_f(d3 + b1);
                const size_t gA = (size_t)e * oz + (size_t)rA * N + col;
                const size_t gB = (size_t)e * oz + (size_t)rB * N + col;
                __half* oh = (__half*)outhi_;
                *(__half2*)(oh + gA) = __halves2half2(__float2half(v0), __float2half(v1));
                *(__half2*)(oh + gB) = __halves2half2(__float2half(v2), __float2half(v3));
            } else {
                const float b0 = bias[(size_t)e * biasz + col];
                const float b1 = bias[(size_t)e * biasz + col + 1];
                const size_t gA = (size_t)e * oz + (size_t)rA * N + col;
                const size_t gB = (size_t)e * oz + (size_t)rB * N + col;
                *(float2*)(outf + gA) = make_float2(gv0 * (d0 + b0), gv0 * (d1 + b1));
                *(float2*)(outf + gB) = make_float2(gv1 * (d2 + b0), gv1 * (d3 + b1));
            }
        }
    }
}

// ---------------- l2norm + scale -> bf16 hi/lo ----------------
__global__ void l2n_kernel(const float* __restrict__ qkv, int base,
                           const float* __restrict__ scale,
                           __nv_bfloat16* __restrict__ oh, __nv_bfloat16* __restrict__ ol)
{
    const int r    = blockIdx.x * 8 + (threadIdx.x >> 5);
    const int lane = threadIdx.x & 31;
    const int b = r / (Hh * Sq);
    const int h = (r / Sq) % Hh;
    const int s = r % Sq;
    const float* src = qkv + (size_t)(b * Sq + s) * (3*Dm) + base + h * DHd;
    float v0 = src[lane], v1 = src[lane + 32];
    float ss = v0 * v0 + v1 * v1;
    #pragma unroll
    for (int o = 16; o; o >>= 1) ss += __shfl_xor_sync(0xffffffffu, ss, o);
    const float inv = rsqrtf(ss + 1e-12f);
    float f0 = v0 * inv * scale[h * DHd + lane];
    float f1 = v1 * inv * scale[h * DHd + lane + 32];
    const size_t d = (size_t)r * DHd;
    __nv_bfloat16 h0 = __float2bfloat16(f0);
    __nv_bfloat16 h1 = __float2bfloat16(f1);
    oh[d + lane]      = h0;
    ol[d + lane]      = __float2bfloat16(f0 - __bfloat162float(h0));
    oh[d + lane + 32] = h1;
    ol[d + lane + 32] = __float2bfloat16(f1 - __bfloat162float(h1));
}

// ---------------- V transpose -> vT hi/lo [bh, d, s] ----------------
__global__ void vtrans_kernel(const float* __restrict__ qkv,
                              __nv_bfloat16* __restrict__ vh, __nv_bfloat16* __restrict__ vl)
{
    __shared__ float t[32][33];
    const int bh = blockIdx.z;
    const int b = bh >> 4, h = bh & 15;
    const int s0 = blockIdx.x * 32, d0 = blockIdx.y * 32;
    const int tx = threadIdx.x, ty = threadIdx.y;
    #pragma unroll
    for (int i = 0; i < 4; i++)
        t[ty + 8*i][tx] = qkv[(size_t)(b * Sq + s0 + ty + 8*i) * (3*Dm) + 2*Dm + h * DHd + d0 + tx];
    __syncthreads();
    #pragma unroll
    for (int i = 0; i < 4; i++) {
        float v = t[tx][ty + 8*i];
        const size_t o = ((size_t)bh * DHd + d0 + ty + 8*i) * Sq + s0 + tx;
        __nv_bfloat16 hh = __float2bfloat16(v);
        vh[o] = hh;
        vl[o] = __float2bfloat16(v - __bfloat162float(hh));
    }
}

// ---------------- fused flash attention (heavy tiles scheduled first) -------
__global__ void __launch_bounds__(256, 1)
flash_kernel(const __nv_bfloat16* __restrict__ qh, const __nv_bfloat16* __restrict__ ql,
             const __nv_bfloat16* __restrict__ kh, const __nv_bfloat16* __restrict__ kl,
             const __nv_bfloat16* __restrict__ vth, const __nv_bfloat16* __restrict__ vtl,
             __nv_bfloat16* __restrict__ aohi, __nv_bfloat16* __restrict__ aolo)
{
    extern __shared__ char smem[];
    const uint32_t sbase = smem_u32(smem);
    const int tid  = threadIdx.x;
    const int wid  = tid >> 5;
    const int lane = tid & 31;
    const int it = gridDim.x - 1 - blockIdx.x;   // heavy rows first
    const int bh = blockIdx.y;
    const int b = bh >> 4, h = bh & 15;

    const int lrow = tid >> 3;
    const int lc8  = (tid & 7) * 8;
    const int vrow = tid >> 4;
    const int vc8  = (tid & 15) * 8;

    const uint32_t sq = sbase;
    const uint32_t skv0 = sbase + 2 * FQ_BYTES;

    #pragma unroll
    for (int i = 0; i < 4; i++) {
        const int row = lrow + i * 32;
        const uint32_t sa = sq + (uint32_t)(row * LDS + lc8) * 2;
        const size_t gq = ((size_t)bh * Sq + it * 128 + row) * DHd + lc8;
        cp16(sa,            qh + gq);
        cp16(sa + FQ_BYTES, ql + gq);
    }
    {
        const uint32_t so = skv0;
        #pragma unroll
        for (int i = 0; i < 4; i++) {
            const int row = lrow + i * 32;
            const uint32_t sa = so + (uint32_t)(row * LDS + lc8) * 2;
            const size_t gk = ((size_t)bh * Sq + row) * DHd + lc8;
            cp16(sa,            kh + gk);
            cp16(sa + FQ_BYTES, kl + gk);
        }
        #pragma unroll
        for (int i = 0; i < 4; i++) {
            const int row = vrow + i * 16;
            const uint32_t sa = so + 2*FQ_BYTES + (uint32_t)(row * LDSV + vc8) * 2;
            const size_t gv = ((size_t)bh * DHd + row) * Sq + vc8;
            cp16(sa,            vth + gv);
            cp16(sa + FV_BYTES, vtl + gv);
        }
        CP_COMMIT();
    }

    float mrow[2] = {-1e30f, -1e30f};
    float lrowv[2] = {0.f, 0.f};
    float oacc[8][4];
    #pragma unroll
    for (int j = 0; j < 8; j++)
        #pragma unroll
        for (int q = 0; q < 4; q++) oacc[j][q] = 0.f;

    uint32_t qa_hi[4][4], qa_lo[4][4];
    bool qloaded = false;

    const int grA = it * 128 + wid * 16 + (lane >> 2);
    const int grB = grA + 8;

    for (int jt = 0; jt <= it; jt++) {
        const int s = jt & 1;
        if (jt < it) {
            const uint32_t so = skv0 + (s ^ 1) * FK_STAGE;
            #pragma unroll
            for (int i = 0; i < 4; i++) {
                const int row = lrow + i * 32;
                const uint32_t sa = so + (uint32_t)(row * LDS + lc8) * 2;
                const size_t gk = ((size_t)bh * Sq + (jt + 1) * 128 + row) * DHd + lc8;
                cp16(sa,            kh + gk);
                cp16(sa + FQ_BYTES, kl + gk);
            }
            #pragma unroll
            for (int i = 0; i < 4; i++) {
                const int row = vrow + i * 16;
                const uint32_t sa = so + 2*FQ_BYTES + (uint32_t)(row * LDSV + vc8) * 2;
                const size_t gv = ((size_t)bh * DHd + row) * Sq + (jt + 1) * 128 + vc8;
                cp16(sa,            vth + gv);
                cp16(sa + FV_BYTES, vtl + gv);
            }
            CP_COMMIT();
            CP_WAIT(1);
        } else {
            CP_WAIT(0);
        }
        __syncthreads();

        if (!qloaded) {
            qloaded = true;
            #pragma unroll
            for (int k16 = 0; k16 < 4; k16++) {
                const int arow = wid * 16 + (lane & 15);
                const int acol = k16 * 16 + ((lane >> 4) << 3);
                const uint32_t addr = sq + (uint32_t)(arow * LDS + acol) * 2;
                LDSM_X4(qa_hi[k16][0], qa_hi[k16][1], qa_hi[k16][2], qa_hi[k16][3], addr);
                LDSM_X4(qa_lo[k16][0], qa_lo[k16][1], qa_lo[k16][2], qa_lo[k16][3], addr + FQ_BYTES);
            }
        }

        const uint32_t sk = skv0 + s * FK_STAGE;
        const uint32_t sv = sk + 2 * FQ_BYTES;

        float sacc[16][4];
        #pragma unroll
        for (int j = 0; j < 16; j++)
            #pragma unroll
            for (int q = 0; q < 4; q++) sacc[j][q] = 0.f;

        #pragma unroll
        for (int k16 = 0; k16 < 4; k16++) {
            const int kc = k16 * 16;
            uint32_t kbh[8][4], kbl[8][4];
            #pragma unroll
            for (int p = 0; p < 8; p++) {
                const int nrow = p * 16 + (lane & 7) + ((lane & 16) >> 1);
                const int ncol = kc + (lane & 8);
                const uint32_t addr = sk + (uint32_t)(nrow * LDS + ncol) * 2;
                LDSM_X4(kbh[p][0], kbh[p][1], kbh[p][2], kbh[p][3], addr);
                LDSM_X4(kbl[p][0], kbl[p][1], kbl[p][2], kbl[p][3], addr + FQ_BYTES);
            }
            #pragma unroll
            for (int nt = 0; nt < 16; nt++) {
                const int pr = nt >> 1, ix = (nt & 1) * 2;
                MMA_BF16(sacc[nt], qa_hi[k16], kbh[pr][ix], kbh[pr][ix+1]);
                MMA_BF16(sacc[nt], qa_lo[k16], kbh[pr][ix], kbh[pr][ix+1]);
                MMA_BF16(sacc[nt], qa_hi[k16], kbl[pr][ix], kbl[pr][ix+1]);
            }
        }

        float mxA = -1e30f, mxB = -1e30f;
        #pragma unroll
        for (int nt = 0; nt < 16; nt++) {
            const int col = jt * 128 + nt * 8 + (lane & 3) * 2;
            float v0 = sacc[nt][0] * QK_SCALE;
            float v1 = sacc[nt][1] * QK_SCALE;
            float v2 = sacc[nt][2] * QK_SCALE;
            float v3 = sacc[nt][3] * QK_SCALE;
            if (jt == it) {
                if (col     > grA) v0 = -1e30f;
                if (col + 1 > grA) v1 = -1e30f;
                if (col     > grB) v2 = -1e30f;
                if (col + 1 > grB) v3 = -1e30f;
            }
            sacc[nt][0] = v0; sacc[nt][1] = v1; sacc[nt][2] = v2; sacc[nt][3] = v3;
            mxA = fmaxf(mxA, fmaxf(v0, v1));
            mxB = fmaxf(mxB, fmaxf(v2, v3));
        }
        #pragma unroll
        for (int o = 1; o <= 2; o <<= 1) {
            mxA = fmaxf(mxA, __shfl_xor_sync(0xffffffffu, mxA, o));
            mxB = fmaxf(mxB, __shfl_xor_sync(0xffffffffu, mxB, o));
        }
        const float mnA = fmaxf(mrow[0], mxA);
        const float mnB = fmaxf(mrow[1], mxB);
        const float scA = __expf(mrow[0] - mnA);
        const float scB = __expf(mrow[1] - mnB);
        mrow[0] = mnA; mrow[1] = mnB;

        #pragma unroll
        for (int j = 0; j < 8; j++) {
            oacc[j][0] *= scA; oacc[j][1] *= scA;
            oacc[j][2] *= scB; oacc[j][3] *= scB;
        }

        float rsA = 0.f, rsB = 0.f;
        #pragma unroll
        for (int t = 0; t < 8; t++) {
            float p00 = __expf(sacc[2*t][0]   - mnA);
            float p01 = __expf(sacc[2*t][1]   - mnA);
            float p02 = __expf(sacc[2*t][2]   - mnB);
            float p03 = __expf(sacc[2*t][3]   - mnB);
            float p10 = __expf(sacc[2*t+1][0] - mnA);
            float p11 = __expf(sacc[2*t+1][1] - mnA);
            float p12 = __expf(sacc[2*t+1][2] - mnB);
            float p13 = __expf(sacc[2*t+1][3] - mnB);
            rsA += p00 + p01 + p10 + p11;
            rsB += p02 + p03 + p12 + p13;

            uint32_t pa_hi[4], pa_lo[4];
            pa_hi[0] = pack_bf16(p00, p01);
            pa_hi[1] = pack_bf16(p02, p03);
            pa_hi[2] = pack_bf16(p10, p11);
            pa_hi[3] = pack_bf16(p12, p13);
            {
                __nv_bfloat162* ph = (__nv_bfloat162*)pa_hi;
                pa_lo[0] = pack_bf16(p00 - __bfloat162float(ph[0].x), p01 - __bfloat162float(ph[0].y));
                pa_lo[1] = pack_bf16(p02 - __bfloat162float(ph[1].x), p03 - __bfloat162float(ph[1].y));
                pa_lo[2] = pack_bf16(p10 - __bfloat162float(ph[2].x), p11 - __bfloat162float(ph[2].y));
                pa_lo[3] = pack_bf16(p12 - __bfloat162float(ph[3].x), p13 - __bfloat162float(ph[3].y));
            }

            const int kc = t * 16;
            uint32_t vbh[4][4], vbl[4][4];
            #pragma unroll
            for (int p = 0; p < 4; p++) {
                const int nrow = p * 16 + (lane & 7) + ((lane & 16) >> 1);
                const int ncol = kc + (lane & 8);
                const uint32_t addr = sv + (uint32_t)(nrow * LDSV + ncol) * 2;
                LDSM_X4(vbh[p][0], vbh[p][1], vbh[p][2], vbh[p][3], addr);
                LDSM_X4(vbl[p][0], vbl[p][1], vbl[p][2], vbl[p][3], addr + FV_BYTES);
            }
            #pragma unroll
            for (int nto = 0; nto < 8; nto++) {
                const int pr = nto >> 1, ix = (nto & 1) * 2;
                MMA_BF16(oacc[nto], pa_hi, vbh[pr][ix], vbh[pr][ix+1]);
                MMA_BF16(oacc[nto], pa_lo, vbh[pr][ix], vbh[pr][ix+1]);
                MMA_BF16(oacc[nto], pa_hi, vbl[pr][ix], vbl[pr][ix+1]);
            }
        }
        #pragma unroll
        for (int o = 1; o <= 2; o <<= 1) {
            rsA += __shfl_xor_sync(0xffffffffu, rsA, o);
            rsB += __shfl_xor_sync(0xffffffffu, rsB, o);
        }
        lrowv[0] = lrowv[0] * scA + rsA;
        lrowv[1] = lrowv[1] * scB + rsB;

        __syncthreads();
    }

    const float invA = 1.0f / lrowv[0];
    const float invB = 1.0f / lrowv[1];
    const int sA = it * 128 + wid * 16 + (lane >> 2);
    const int sB = sA + 8;
    #pragma unroll
    for (int nto = 0; nto < 8; nto++) {
        const int d = nto * 8 + (lane & 3) * 2;
        const size_t gA = ((size_t)(b * Sq + sA)) * Dm + h * DHd + d;
        const size_t gB = ((size_t)(b * Sq + sB)) * Dm + h * DHd + d;
        float v0 = oacc[nto][0] * invA, v1 = oacc[nto][1] * invA;
        float v2 = oacc[nto][2] * invB, v3 = oacc[nto][3] * invB;
        __nv_bfloat16 h0 = __float2bfloat16(v0), h1 = __float2bfloat16(v1);
        __nv_bfloat16 h2 = __float2bfloat16(v2), h3 = __float2bfloat16(v3);
        __nv_bfloat162 hhA; hhA.x = h0; hhA.y = h1;
        __nv_bfloat162 hhB; hhB.x = h2; hhB.y = h3;
        __nv_bfloat162 llA, llB;
        llA.x = __float2bfloat16(v0 - __bfloat162float(h0));
        llA.y = __float2bfloat16(v1 - __bfloat162float(h1));
        llB.x = __float2bfloat16(v2 - __bfloat162float(h2));
        llB.y = __float2bfloat16(v3 - __bfloat162float(h3));
        *(__nv_bfloat162*)(aohi + gA) = hhA;
        *(__nv_bfloat162*)(aolo + gA) = llA;
        *(__nv_bfloat162*)(aohi + gB) = hhB;
        *(__nv_bfloat162*)(aolo + gB) = llB;
    }
}

// ---------------- sum experts + final LayerNorm ----------------
__global__ void redln_kernel(const float* __restrict__ expout, const float* __restrict__ g,
                             const float* __restrict__ b, float* __restrict__ out)
{
    __shared__ float buf[Dm];
    __shared__ float red[256];
    const int row = blockIdx.x;
    const int tid = threadIdx.x;
    float s = 0.f;
    for (int i = tid; i < Dm; i += 256) {
        float v = 0.f;
        #pragma unroll
        for (int e = 0; e < Ex; e++)
            v += expout[(size_t)e * ROWS * Dm + (size_t)row * Dm + i];
        buf[i] = v; s += v;
    }
    red[tid] = s; __syncthreads();
    for (int off = 128; off > 0; off >>= 1) { if (tid < off) red[tid] += red[tid+off]; __syncthreads(); }
    const float mean = red[0] * (1.0f / Dm);
    __syncthreads();
    float s2 = 0.f;
    for (int i = tid; i < Dm; i += 256) { float d = buf[i] - mean; s2 += d * d; }
    red[tid] = s2; __syncthreads();
    for (int off = 128; off > 0; off >>= 1) { if (tid < off) red[tid] += red[tid+off]; __syncthreads(); }
    const float inv = rsqrtf(red[0] * (1.0f / Dm) + 1e-5f);
    for (int i = tid; i < Dm; i += 256)
        out[(size_t)row * Dm + i] = (buf[i] - mean) * inv * g[i] + b[i];
}

// ---------------- launch ----------------
extern "C" void kernel_launch(void* const* d_in, const int* in_sizes, int n_in,
                              void* d_out, int out_size)
{
    const float* x       = (const float*)d_in[0];
    const float* ln_g    = (const float*)d_in[1];
    const float* ln_b    = (const float*)d_in[2];
    const float* Wq      = (const float*)d_in[3];
    const float* Wk      = (const float*)d_in[4];
    const float* Wv      = (const float*)d_in[5];
    const float* q_scale = (const float*)d_in[6];
    const float* k_scale = (const float*)d_in[7];
    const float* Wo      = (const float*)d_in[8];
    const float* gate_w  = (const float*)d_in[9];
    const float* gate_b  = (const float*)d_in[10];
    const float* w1      = (const float*)d_in[11];
    const float* b1      = (const float*)d_in[12];
    const float* w2      = (const float*)d_in[13];
    const float* b2      = (const float*)d_in[14];
    float* out = (float*)d_out;

    __nv_bfloat16 *h1hi, *h1lo, *aohi, *aolo;
    __half *h2h16, *hid, *w1Th, *w2Th;
    __nv_bfloat16 *qnh, *qnl, *knh, *knl, *vTh, *vTl;
    __nv_bfloat16 *wqkvThi, *wqkvTlo, *woThi, *woTlo;
    float *qkvf, *o, *gate, *expout;
    cudaGetSymbolAddress((void**)&h1hi, g_h1hi);   cudaGetSymbolAddress((void**)&h1lo, g_h1lo);
    cudaGetSymbolAddress((void**)&qkvf, g_qkvf);
    cudaGetSymbolAddress((void**)&qnh, g_qnh);     cudaGetSymbolAddress((void**)&qnl, g_qnl);
    cudaGetSymbolAddress((void**)&knh, g_knh);     cudaGetSymbolAddress((void**)&knl, g_knl);
    cudaGetSymbolAddress((void**)&vTh, g_vTh);     cudaGetSymbolAddress((void**)&vTl, g_vTl);
    cudaGetSymbolAddress((void**)&aohi, g_aohi);   cudaGetSymbolAddress((void**)&aolo, g_aolo);
    cudaGetSymbolAddress((void**)&o, g_o);
    cudaGetSymbolAddress((void**)&h2h16, g_h2h16);
    cudaGetSymbolAddress((void**)&gate, g_gate);
    cudaGetSymbolAddress((void**)&hid, g_hid);
    cudaGetSymbolAddress((void**)&expout, g_expout);
    cudaGetSymbolAddress((void**)&wqkvThi, g_wqkvThi); cudaGetSymbolAddress((void**)&wqkvTlo, g_wqkvTlo);
    cudaGetSymbolAddress((void**)&woThi, g_woThi);     cudaGetSymbolAddress((void**)&woTlo, g_woTlo);
    cudaGetSymbolAddress((void**)&w1Th, g_w1Th);
    cudaGetSymbolAddress((void**)&w2Th, g_w2Th);

    cudaFuncSetAttribute(bgemm_kernel<0,0>, cudaFuncAttributeMaxDynamicSharedMemorySize, SMEM_M0);
    cudaFuncSetAttribute(bgemm_kernel<1,2>, cudaFuncAttributeMaxDynamicSharedMemorySize, SMEM_M2);
    cudaFuncSetAttribute(bgemm_kernel<2,2>, cudaFuncAttributeMaxDynamicSharedMemorySize, SMEM_M2);
    cudaFuncSetAttribute(flash_kernel,      cudaFuncAttributeMaxDynamicSharedMemorySize, SMEM_FL);

    // ---- side stream: weight prep not needed until step 5/7 -----------------
    cudaStream_t s2;
    cudaStreamCreateWithFlags(&s2, cudaStreamNonBlocking);
    cudaEvent_t evFork, evJoin;
    cudaEventCreateWithFlags(&evFork, cudaEventDisableTiming);
    cudaEventCreateWithFlags(&evJoin, cudaEventDisableTiming);

    // QKV weight prep must complete before step 2 -> keep on main stream
    wprep_kernel<<<dim3(Dm/32, Dm/32, 1), dim3(32,8)>>>(Wq, wqkvThi,           wqkvTlo,           Dm, Dm);
    wprep_kernel<<<dim3(Dm/32, Dm/32, 1), dim3(32,8)>>>(Wk, wqkvThi + Dm*Dm,   wqkvTlo + Dm*Dm,   Dm, Dm);
    wprep_kernel<<<dim3(Dm/32, Dm/32, 1), dim3(32,8)>>>(Wv, wqkvThi + 2*Dm*Dm, wqkvTlo + 2*Dm*Dm, Dm, Dm);

    // fork: Wo/w1/w2 prep runs concurrently with LN + QKV GEMM + attention
    cudaEventRecord(evFork, 0);
    cudaStreamWaitEvent(s2, evFork, 0);
    wprep_kernel<<<dim3(Dm/32, Dm/32, 1), dim3(32,8), 0, s2>>>(Wo, woThi, woTlo, Dm, Dm);
    wprep16_kernel<<<dim3(FFd/32, Dm/64, Ex), 256, 0, s2>>>(w1, w1Th, Dm, FFd);
    wprep16_kernel<<<dim3(Dm/32, FFd/64, Ex), 256, 0, s2>>>(w2, w2Th, FFd, Dm);
    cudaEventRecord(evJoin, s2);

    // 1. pre-attention LN -> bf16 hi/lo
    ln_kernel<<<ROWS, 256>>>(x, ln_g, ln_b, nullptr, h1hi, h1lo, nullptr,
                             nullptr, nullptr, nullptr);

    // 2. fused QKV projection (bf16 3-term)
    bgemm_kernel<0,0><<<dim3(3*Dm/BN, ROWS/BM, 1), 256, SMEM_M0>>>(
        h1hi, h1lo, wqkvThi, wqkvTlo, 3*Dm, Dm, 0, 0, 0,
        qkvf, nullptr, nullptr, 0, nullptr);

    // 3. l2norm -> bf16 hi/lo; v transpose
    l2n_kernel<<<(BH*Sq)/8, 256>>>(qkvf, 0,  q_scale, qnh, qnl);
    l2n_kernel<<<(BH*Sq)/8, 256>>>(qkvf, Dm, k_scale, knh, knl);
    vtrans_kernel<<<dim3(Sq/32, DHd/32, BH), dim3(32,8)>>>(qkvf, vTh, vTl);

    // 4. fused flash attention (heavy tiles first)
    flash_kernel<<<dim3(Sq/128, BH), 256, SMEM_FL>>>(qnh, qnl, knh, knl, vTh, vTl, aohi, aolo);

    // join: Wo/w1/w2 prep must be done before step 5
    cudaStreamWaitEvent(0, evJoin, 0);

    // 5. output projection (bf16 3-term) + mid LN (with fused gate softmax)
    bgemm_kernel<0,0><<<dim3(Dm/BN, ROWS/BM, 1), 256, SMEM_M0>>>(
        aohi, aolo, woThi, woTlo, Dm, Dm, 0, 0, 0,
        o, nullptr, nullptr, 0, nullptr);
    ln_kernel<<<ROWS, 256>>>(o, ln_g, ln_b, nullptr, nullptr, nullptr, h2h16,
                             gate_w, gate_b, gate);

    // 7. MoE GEMM1 (fp16 1-term, 3-stage)
    bgemm_kernel<1,2><<<dim3(FFd/BN, ROWS/BM, Ex), 256, SMEM_M2>>>(
        h2h16, nullptr, w1Th, nullptr, FFd, Dm,
        0, (long long)FFd*Dm, (long long)ROWS*FFd,
        nullptr, hid, b1, FFd, nullptr);

    // 8. MoE GEMM2 (fp16 1-term, 3-stage)
    bgemm_kernel<2,2><<<dim3(Dm/BN, ROWS/BM, Ex), 256, SMEM_M2>>>(
        hid, nullptr, w2Th, nullptr, Dm, FFd,
        (long long)ROWS*FFd, (long long)Dm*FFd, (long long)ROWS*Dm,
        expout, nullptr, b2, Dm, gate);

    // 9. sum experts + final LN -> out
    redln_kernel<<<ROWS, 256>>>(expout, ln_g, ln_b, out);

    cudaEventDestroy(evFork);
    cudaEventDestroy(evJoin);
    cudaStreamDestroy(s2);
}

// round 15
// speedup vs baseline: 1.0148x; 1.0037x over previous
#include <cuda_runtime.h>
#include <cuda_bf16.h>
#include <cuda_fp16.h>
#include <math.h>
#include <stdint.h>

// ---------------- problem constants ----------------
#define Bc   2
#define Sq   1024
#define Dm   1024
#define Hh   16
#define DHd  64
#define Ex   8
#define FFd  4096
#define BH   (Bc*Hh)     // 32
#define ROWS (Bc*Sq)     // 2048
#define QK_SCALE 10.0f

// GEMM tiling (bgemm: 256x128 CTA tile)
#define BM 256
#define BN 128
#define BK 64
#define LDS 72                        // BK + 8 pad (16-bit units)
#define A_BYTES (256*LDS*2)           // 36864
#define B_BYTES (128*LDS*2)           // 18432
#define SMEM_M0 (2*(2*A_BYTES + 2*B_BYTES))  // 221184 (bf16 3-term, 2 stages)
#define SMEM_M2 (3*(A_BYTES + B_BYTES))      // 165888 (fp16 1-term, 3 stages)

// flash attention tiling
#define FQ_BYTES (128*LDS*2)          // 18432
#define LDSV 136
#define FV_BYTES (64*LDSV*2)          // 17408
#define FK_STAGE (2*FQ_BYTES + 2*FV_BYTES)   // 71680
#define SMEM_FL (2*FQ_BYTES + 2*FK_STAGE)    // 180224

// ---------------- low-level helpers ----------------
__device__ __forceinline__ uint32_t smem_u32(const void* p) {
    uint32_t a;
    asm("{ .reg .u64 t; cvta.to.shared.u64 t, %1; cvt.u32.u64 %0, t; }" : "=r"(a) : "l"(p));
    return a;
}
__device__ __forceinline__ void cp16(uint32_t dst, const void* src) {
    asm volatile("cp.async.cg.shared.global [%0], [%1], 16;" :: "r"(dst), "l"(src));
}
#define CP_COMMIT() asm volatile("cp.async.commit_group;" ::: "memory")
#define CP_WAIT(n)  asm volatile("cp.async.wait_group %0;" :: "n"(n) : "memory")

#define LDSM_X4(r0, r1, r2, r3, addr) \
    asm volatile("ldmatrix.sync.aligned.m8n8.x4.shared.b16 {%0,%1,%2,%3}, [%4];" \
        : "=r"(r0), "=r"(r1), "=r"(r2), "=r"(r3) : "r"(addr))

#define MMA_BF16(d, a, b0, b1) \
    asm volatile("mma.sync.aligned.m16n8k16.row.col.f32.bf16.bf16.f32 " \
        "{%0,%1,%2,%3}, {%4,%5,%6,%7}, {%8,%9}, {%0,%1,%2,%3};" \
        : "+f"((d)[0]), "+f"((d)[1]), "+f"((d)[2]), "+f"((d)[3]) \
        : "r"((a)[0]), "r"((a)[1]), "r"((a)[2]), "r"((a)[3]), "r"(b0), "r"(b1))

#define MMA_F16(d, a, b0, b1) \
    asm volatile("mma.sync.aligned.m16n8k16.row.col.f32.f16.f16.f32 " \
        "{%0,%1,%2,%3}, {%4,%5,%6,%7}, {%8,%9}, {%0,%1,%2,%3};" \
        : "+f"((d)[0]), "+f"((d)[1]), "+f"((d)[2]), "+f"((d)[3]) \
        : "r"((a)[0]), "r"((a)[1]), "r"((a)[2]), "r"((a)[3]), "r"(b0), "r"(b1))

__device__ __forceinline__ uint32_t pack_bf16(float a, float b) {
    __nv_bfloat162 t;
    t.x = __float2bfloat16(a);
    t.y = __float2bfloat16(b);
    return *(uint32_t*)&t;
}

// ---------------- scratch (device globals) ----------------
__device__ __nv_bfloat16 g_h1hi[ROWS*Dm], g_h1lo[ROWS*Dm];
__device__ float g_qkvf[ROWS*3*Dm];
__device__ __nv_bfloat16 g_qnh[BH*Sq*DHd], g_qnl[BH*Sq*DHd];
__device__ __nv_bfloat16 g_knh[BH*Sq*DHd], g_knl[BH*Sq*DHd];
__device__ __nv_bfloat16 g_vTh[BH*DHd*Sq], g_vTl[BH*DHd*Sq];
__device__ __nv_bfloat16 g_aohi[ROWS*Dm], g_aolo[ROWS*Dm];
__device__ float g_o[ROWS*Dm];
__device__ __half g_h2h16[ROWS*Dm];
__device__ float g_gate[ROWS*Ex];
__device__ __half g_hid[(size_t)Ex*ROWS*FFd];
__device__ __half g_expout[(size_t)Ex*ROWS*Dm];
__device__ __nv_bfloat16 g_wqkvThi[3*Dm*Dm], g_wqkvTlo[3*Dm*Dm];
__device__ __nv_bfloat16 g_woThi[Dm*Dm], g_woTlo[Dm*Dm];
__device__ __half g_w1Th[(size_t)Ex*FFd*Dm];
__device__ __half g_w2Th[(size_t)Ex*Dm*FFd];

// ---------------- math helpers ----------------
__device__ __forceinline__ float gelu_f(float x) {
    float x3 = x * x * x;
    float t  = tanhf(0.7978845608028654f * (x + 0.044715f * x3));
    return 0.5f * x * (1.0f + t);
}

// ---------------- weight transpose + bf16 split (small matrices) -----------
__global__ void wprep_kernel(const float* __restrict__ W, __nv_bfloat16* __restrict__ hi,
                             __nv_bfloat16* __restrict__ lo, int K, int N)
{
    __shared__ float t[32][33];
    const size_t zoff = (size_t)blockIdx.z * K * N;
    const int k0 = blockIdx.y * 32, n0 = blockIdx.x * 32;
    const int tx = threadIdx.x, ty = threadIdx.y;
    #pragma unroll
    for (int i = 0; i < 4; i++)
        t[ty + 8*i][tx] = W[zoff + (size_t)(k0 + ty + 8*i) * N + n0 + tx];
    __syncthreads();
    #pragma unroll
    for (int i = 0; i < 4; i++) {
        float v = t[tx][ty + 8*i];
        const size_t o = zoff + (size_t)(n0 + ty + 8*i) * K + k0 + tx;
        __nv_bfloat16 h = __float2bfloat16(v);
        hi[o] = h;
        lo[o] = __float2bfloat16(v - __bfloat162float(h));
    }
}

// ---------------- FAST weight transpose + fp16: W[K,N] -> fp16 [N,K] -------
__global__ void __launch_bounds__(256)
wprep16_kernel(const float* __restrict__ W, __half* __restrict__ out, int K, int N)
{
    __shared__ float t[64][33];
    const size_t zoff = (size_t)blockIdx.z * K * N;
    const int k0 = blockIdx.y * 64, n0 = blockIdx.x * 32;
    const int tid = threadIdx.x;
    const int lx = tid & 31;
    const int ly = tid >> 5;
    #pragma unroll
    for (int i = 0; i < 8; i++) {
        const int kk = ly + 8 * i;
        t[kk][lx] = W[zoff + (size_t)(k0 + kk) * N + n0 + lx];
    }
    __syncthreads();
    const int n  = tid >> 3;
    const int ks = (tid & 7) * 8;
    __half h[8];
    #pragma unroll
    for (int j = 0; j < 8; j++) h[j] = __float2half(t[ks + j][n]);
    *(uint4*)(out + zoff + (size_t)(n0 + n) * K + k0 + ks) = *(uint4*)h;
}

// ---------------- LayerNorm (+ optional fused gate softmax) ----------------
__global__ void ln_kernel(const float* __restrict__ x, const float* __restrict__ g,
                          const float* __restrict__ b, float* __restrict__ yf,
                          __nv_bfloat16* __restrict__ yhi, __nv_bfloat16* __restrict__ ylo,
                          __half* __restrict__ y16,
                          const float* __restrict__ gw, const float* __restrict__ gb,
                          float* __restrict__ gateOut)
{
    __shared__ float buf[Dm];
    __shared__ float red[256];
    __shared__ float lg[Ex];
    const int row = blockIdx.x;
    const int tid = threadIdx.x;
    const float* xr = x + (size_t)row * Dm;
    float s = 0.f;
    for (int i = tid; i < Dm; i += 256) { float v = xr[i]; buf[i] = v; s += v; }
    red[tid] = s; __syncthreads();
    for (int off = 128; off > 0; off >>= 1) { if (tid < off) red[tid] += red[tid+off]; __syncthreads(); }
    const float mean = red[0] * (1.0f / Dm);
    __syncthreads();
    float s2 = 0.f;
    for (int i = tid; i < Dm; i += 256) { float d = buf[i] - mean; s2 += d * d; }
    red[tid] = s2; __syncthreads();
    for (int off = 128; off > 0; off >>= 1) { if (tid < off) red[tid] += red[tid+off]; __syncthreads(); }
    const float inv = rsqrtf(red[0] * (1.0f / Dm) + 1e-5f);
    for (int i = tid; i < Dm; i += 256) {
        float v = (buf[i] - mean) * inv * g[i] + b[i];
        buf[i] = v;   // keep normalized row for the gate
        if (yf) yf[(size_t)row*Dm + i] = v;
        if (yhi) {
            __nv_bfloat16 h = __float2bfloat16(v);
            yhi[(size_t)row*Dm + i] = h;
            ylo[(size_t)row*Dm + i] = __float2bfloat16(v - __bfloat162float(h));
        }
        if (y16) y16[(size_t)row*Dm + i] = __float2half(v);
    }
    if (gateOut) {
        __syncthreads();
        const int e = tid >> 5, lane = tid & 31;
        float sg = 0.f;
        for (int k = lane; k < Dm; k += 32) sg += buf[k] * gw[k * Ex + e];
        #pragma unroll
        for (int o = 16; o; o >>= 1) sg += __shfl_xor_sync(0xffffffffu, sg, o);
        if (lane == 0) lg[e] = sg + gb[e];
        __syncthreads();
        if (tid == 0) {
            float m = lg[0];
            #pragma unroll
            for (int q = 1; q < Ex; q++) m = fmaxf(m, lg[q]);
            float ex[Ex], sum = 0.f;
            #pragma unroll
            for (int q = 0; q < Ex; q++) { ex[q] = expf(lg[q] - m); sum += ex[q]; }
            const float invs = 1.0f / sum;
            #pragma unroll
            for (int q = 0; q < Ex; q++) gateOut[(size_t)row * Ex + q] = ex[q] * invs;
        }
    }
}

// ---------------- mma.sync GEMM ------------
// MODE 0: bf16 3-term, NSTG=2. MODE 2: fp16 single-term, NSTG=3.
// EPI 0: fp32 store; EPI 1: gelu(acc+bias) -> fp16; EPI 2: gate*(acc+bias) -> fp16
template<int EPI, int MODE>
__global__ void __launch_bounds__(256, 1)
bgemm_kernel(const void* __restrict__ Ahi_, const void* __restrict__ Alo_,
             const void* __restrict__ Bhi_, const void* __restrict__ Blo_,
             int N, int K,
             long long az, long long bz, long long oz,
             float* __restrict__ outf,
             void* __restrict__ outhi_,
             const float* __restrict__ bias, long long biasz,
             const float* __restrict__ gate)
{
    extern __shared__ char smem[];
    const uint32_t sbase = smem_u32(smem);
    const int tid  = threadIdx.x;
    const int wid  = tid >> 5;
    const int lane = tid & 31;
    const int wm   = wid >> 1;
    const int wn   = wid & 1;
    const int m0 = blockIdx.y * BM;
    const int n0 = blockIdx.x * BN;
    const int e  = blockIdx.z;

    constexpr int NSTG = (MODE == 0) ? 2 : 3;
    constexpr int STG = (MODE == 0) ? (2*A_BYTES + 2*B_BYTES) : (A_BYTES + B_BYTES);
    const uint16_t* pAhi = (const uint16_t*)Ahi_ + (size_t)e * az;
    const uint16_t* pAlo = (const uint16_t*)Alo_ + (size_t)e * az;
    const uint16_t* pBhi = (const uint16_t*)Bhi_ + (size_t)e * bz;
    const uint16_t* pBlo = (const uint16_t*)Blo_ + (size_t)e * bz;
    constexpr uint32_t B_OFF = (MODE == 0) ? 2*A_BYTES : A_BYTES;

    const int lrow = tid >> 3;
    const int lc8  = (tid & 7) * 8;

    float acc[4][8][4];
    #pragma unroll
    for (int i = 0; i < 4; i++)
        #pragma unroll
        for (int j = 0; j < 8; j++)
            #pragma unroll
            for (int q = 0; q < 4; q++) acc[i][j][q] = 0.f;

    const int NB = K / BK;

    auto load_stage = [&](int kb, int slot) {
        const int kk = kb * BK;
        const uint32_t so = sbase + slot * STG;
        #pragma unroll
        for (int i = 0; i < 8; i++) {
            const int row = lrow + i * 32;
            const uint32_t sa = so + (uint32_t)(row * LDS + lc8) * 2;
            const size_t ga = (size_t)(m0 + row) * K + kk + lc8;
            cp16(sa, pAhi + ga);
            if (MODE == 0) cp16(sa + A_BYTES, pAlo + ga);
        }
        #pragma unroll
        for (int i = 0; i < 4; i++) {
            const int row = lrow + i * 32;
            const uint32_t sb = so + B_OFF + (uint32_t)(row * LDS + lc8) * 2;
            const size_t gb = (size_t)(n0 + row) * K + kk + lc8;
            cp16(sb, pBhi + gb);
            if (MODE == 0) cp16(sb + B_BYTES, pBlo + gb);
        }
        CP_COMMIT();
    };

    // prefetch NSTG-1 stages
    #pragma unroll
    for (int p = 0; p < NSTG - 1; p++) load_stage(p, p);

    for (int kb = 0; kb < NB; kb++) {
        const int s = kb % NSTG;
        if (kb + NSTG - 1 < NB) {
            load_stage(kb + NSTG - 1, (kb + NSTG - 1) % NSTG);
            CP_WAIT(NSTG - 1);
        } else if (kb + 1 < NB) {
            CP_WAIT(1);
        } else {
            CP_WAIT(0);
        }
        __syncthreads();

        const uint32_t so = sbase + s * STG;
        #pragma unroll
        for (int k16 = 0; k16 < 4; k16++) {
            const int kc = k16 * 16;
            uint32_t ah[4][4], al[4][4], bh[4][4], bl[4][4];
            #pragma unroll
            for (int mt = 0; mt < 4; mt++) {
                const int arow = wm * 64 + mt * 16 + (lane & 15);
                const int acol = kc + ((lane >> 4) << 3);
                const uint32_t addr = so + (uint32_t)(arow * LDS + acol) * 2;
                LDSM_X4(ah[mt][0], ah[mt][1], ah[mt][2], ah[mt][3], addr);
                if (MODE == 0) LDSM_X4(al[mt][0], al[mt][1], al[mt][2], al[mt][3], addr + A_BYTES);
            }
            #pragma unroll
            for (int p = 0; p < 4; p++) {
                const int nrow = wn * 64 + p * 16 + (lane & 7) + ((lane & 16) >> 1);
                const int ncol = kc + (lane & 8);
                const uint32_t addr = so + B_OFF + (uint32_t)(nrow * LDS + ncol) * 2;
                LDSM_X4(bh[p][0], bh[p][1], bh[p][2], bh[p][3], addr);
                if (MODE == 0) LDSM_X4(bl[p][0], bl[p][1], bl[p][2], bl[p][3], addr + B_BYTES);
            }
            #pragma unroll
            for (int mt = 0; mt < 4; mt++) {
                #pragma unroll
                for (int nt = 0; nt < 8; nt++) {
                    const int pr = nt >> 1, ix = (nt & 1) * 2;
                    if (MODE == 0) {
                        MMA_BF16(acc[mt][nt], ah[mt], bh[pr][ix], bh[pr][ix+1]);
                        MMA_BF16(acc[mt][nt], al[mt], bh[pr][ix], bh[pr][ix+1]);
                        MMA_BF16(acc[mt][nt], ah[mt], bl[pr][ix], bl[pr][ix+1]);
                    } else {
                        MMA_F16(acc[mt][nt], ah[mt], bh[pr][ix], bh[pr][ix+1]);
                    }
                }
            }
        }
        __syncthreads();
    }

    #pragma unroll
    for (int mt = 0; mt < 4; mt++) {
        const int rA = m0 + wm * 64 + mt * 16 + (lane >> 2);
        const int rB = rA + 8;
        float gv0 = 0.f, gv1 = 0.f;
        if (EPI == 2) {
            gv0 = gate[(size_t)rA * Ex + e];
            gv1 = gate[(size_t)rB * Ex + e];
        }
        #pragma unroll
        for (int nt = 0; nt < 8; nt++) {
            const int col = n0 + wn * 64 + nt * 8 + (lane & 3) * 2;
            float d0 = acc[mt][nt][0], d1 = acc[mt][nt][1];
            float d2 = acc[mt][nt][2], d3 = acc[mt][nt][3];
            if (EPI == 0) {
                *(float2*)(outf + (size_t)rA * N + col) = make_float2(d0, d1);
                *(float2*)(outf + (size_t)rB * N + col) = make_float2(d2, d3);
            } else if (EPI == 1) {
                const float b0 = bias[(size_t)e * biasz + col];
                const float b1 = bias[(size_t)e * biasz + col + 1];
                float v0 = gelu_f(d0 + b0), v1 = gelu_f(d1 + b1);
                float v2 = gelu_f(d2 + b0), v3 = gelu_f(d3 + b1);
                const size_t gA = (size_t)e * oz + (size_t)rA * N + col;
                const size_t gB = (size_t)e * oz + (size_t)rB * N + col;
                __half* oh = (__half*)outhi_;
                *(__half2*)(oh + gA) = __halves2half2(__float2half(v0), __float2half(v1));
                *(__half2*)(oh + gB) = __halves2half2(__float2half(v2), __float2half(v3));
            } else {
                const float b0 = bias[(size_t)e * biasz + col];
                const float b1 = bias[(size_t)e * biasz + col + 1];
                const size_t gA = (size_t)e * oz + (size_t)rA * N + col;
                const size_t gB = (size_t)e * oz + (size_t)rB * N + col;
                __half* oh = (__half*)outhi_;
                *(__half2*)(oh + gA) = __halves2half2(__float2half(gv0 * (d0 + b0)),
                                                      __float2half(gv0 * (d1 + b1)));
                *(__half2*)(oh + gB) = __halves2half2(__float2half(gv1 * (d2 + b0)),
                                                      __float2half(gv1 * (d3 + b1)));
            }
        }
    }
}

// ---------------- l2norm + scale -> bf16 hi/lo (q and k in one launch) -----
__global__ void l2n_kernel(const float* __restrict__ qkv,
                           const float* __restrict__ q_scale, const float* __restrict__ k_scale,
                           __nv_bfloat16* __restrict__ qh, __nv_bfloat16* __restrict__ ql,
                           __nv_bfloat16* __restrict__ kh, __nv_bfloat16* __restrict__ kl)
{
    const int r    = blockIdx.x * 8 + (threadIdx.x >> 5);
    const int lane = threadIdx.x & 31;
    const int sel  = blockIdx.y;           // 0 = q, 1 = k
    const int base = sel * Dm;
    const float* scale = sel ? k_scale : q_scale;
    __nv_bfloat16* oh = sel ? kh : qh;
    __nv_bfloat16* ol = sel ? kl : ql;
    const int b = r / (Hh * Sq);
    const int h = (r / Sq) % Hh;
    const int s = r % Sq;
    const float* src = qkv + (size_t)(b * Sq + s) * (3*Dm) + base + h * DHd;
    float v0 = src[lane], v1 = src[lane + 32];
    float ss = v0 * v0 + v1 * v1;
    #pragma unroll
    for (int o = 16; o; o >>= 1) ss += __shfl_xor_sync(0xffffffffu, ss, o);
    const float inv = rsqrtf(ss + 1e-12f);
    float f0 = v0 * inv * scale[h * DHd + lane];
    float f1 = v1 * inv * scale[h * DHd + lane + 32];
    const size_t d = (size_t)r * DHd;
    __nv_bfloat16 h0 = __float2bfloat16(f0);
    __nv_bfloat16 h1 = __float2bfloat16(f1);
    oh[d + lane]      = h0;
    ol[d + lane]      = __float2bfloat16(f0 - __bfloat162float(h0));
    oh[d + lane + 32] = h1;
    ol[d + lane + 32] = __float2bfloat16(f1 - __bfloat162float(h1));
}

// ---------------- V transpose -> vT hi/lo [bh, d, s] ----------------
__global__ void vtrans_kernel(const float* __restrict__ qkv,
                              __nv_bfloat16* __restrict__ vh, __nv_bfloat16* __restrict__ vl)
{
    __shared__ float t[32][33];
    const int bh = blockIdx.z;
    const int b = bh >> 4, h = bh & 15;
    const int s0 = blockIdx.x * 32, d0 = blockIdx.y * 32;
    const int tx = threadIdx.x, ty = threadIdx.y;
    #pragma unroll
    for (int i = 0; i < 4; i++)
        t[ty + 8*i][tx] = qkv[(size_t)(b * Sq + s0 + ty + 8*i) * (3*Dm) + 2*Dm + h * DHd + d0 + tx];
    __syncthreads();
    #pragma unroll
    for (int i = 0; i < 4; i++) {
        float v = t[tx][ty + 8*i];
        const size_t o = ((size_t)bh * DHd + d0 + ty + 8*i) * Sq + s0 + tx;
        __nv_bfloat16 hh = __float2bfloat16(v);
        vh[o] = hh;
        vl[o] = __float2bfloat16(v - __bfloat162float(hh));
    }
}

// ---------------- fused flash attention (heavy tiles scheduled first) -------
__global__ void __launch_bounds__(256, 1)
flash_kernel(const __nv_bfloat16* __restrict__ qh, const __nv_bfloat16* __restrict__ ql,
             const __nv_bfloat16* __restrict__ kh, const __nv_bfloat16* __restrict__ kl,
             const __nv_bfloat16* __restrict__ vth, const __nv_bfloat16* __restrict__ vtl,
             __nv_bfloat16* __restrict__ aohi, __nv_bfloat16* __restrict__ aolo)
{
    extern __shared__ char smem[];
    const uint32_t sbase = smem_u32(smem);
    const int tid  = threadIdx.x;
    const int wid  = tid >> 5;
    const int lane = tid & 31;
    const int it = gridDim.x - 1 - blockIdx.x;   // heavy rows first
    const int bh = blockIdx.y;
    const int b = bh >> 4, h = bh & 15;

    const int lrow = tid >> 3;
    const int lc8  = (tid & 7) * 8;
    const int vrow = tid >> 4;
    const int vc8  = (tid & 15) * 8;

    const uint32_t sq = sbase;
    const uint32_t skv0 = sbase + 2 * FQ_BYTES;

    #pragma unroll
    for (int i = 0; i < 4; i++) {
        const int row = lrow + i * 32;
        const uint32_t sa = sq + (uint32_t)(row * LDS + lc8) * 2;
        const size_t gq = ((size_t)bh * Sq + it * 128 + row) * DHd + lc8;
        cp16(sa,            qh + gq);
        cp16(sa + FQ_BYTES, ql + gq);
    }
    {
        const uint32_t so = skv0;
        #pragma unroll
        for (int i = 0; i < 4; i++) {
            const int row = lrow + i * 32;
            const uint32_t sa = so + (uint32_t)(row * LDS + lc8) * 2;
            const size_t gk = ((size_t)bh * Sq + row) * DHd + lc8;
            cp16(sa,            kh + gk);
            cp16(sa + FQ_BYTES, kl + gk);
        }
        #pragma unroll
        for (int i = 0; i < 4; i++) {
            const int row = vrow + i * 16;
            const uint32_t sa = so + 2*FQ_BYTES + (uint32_t)(row * LDSV + vc8) * 2;
            const size_t gv = ((size_t)bh * DHd + row) * Sq + vc8;
            cp16(sa,            vth + gv);
            cp16(sa + FV_BYTES, vtl + gv);
        }
        CP_COMMIT();
    }

    float mrow[2] = {-1e30f, -1e30f};
    float lrowv[2] = {0.f, 0.f};
    float oacc[8][4];
    #pragma unroll
    for (int j = 0; j < 8; j++)
        #pragma unroll
        for (int q = 0; q < 4; q++) oacc[j][q] = 0.f;

    uint32_t qa_hi[4][4], qa_lo[4][4];
    bool qloaded = false;

    const int grA = it * 128 + wid * 16 + (lane >> 2);
    const int grB = grA + 8;

    for (int jt = 0; jt <= it; jt++) {
        const int s = jt & 1;
        if (jt < it) {
            const uint32_t so = skv0 + (s ^ 1) * FK_STAGE;
            #pragma unroll
            for (int i = 0; i < 4; i++) {
                const int row = lrow + i * 32;
                const uint32_t sa = so + (uint32_t)(row * LDS + lc8) * 2;
                const size_t gk = ((size_t)bh * Sq + (jt + 1) * 128 + row) * DHd + lc8;
                cp16(sa,            kh + gk);
                cp16(sa + FQ_BYTES, kl + gk);
            }
            #pragma unroll
            for (int i = 0; i < 4; i++) {
                const int row = vrow + i * 16;
                const uint32_t sa = so + 2*FQ_BYTES + (uint32_t)(row * LDSV + vc8) * 2;
                const size_t gv = ((size_t)bh * DHd + row) * Sq + (jt + 1) * 128 + vc8;
                cp16(sa,            vth + gv);
                cp16(sa + FV_BYTES, vtl + gv);
            }
            CP_COMMIT();
            CP_WAIT(1);
        } else {
            CP_WAIT(0);
        }
        __syncthreads();

        if (!qloaded) {
            qloaded = true;
            #pragma unroll
            for (int k16 = 0; k16 < 4; k16++) {
                const int arow = wid * 16 + (lane & 15);
                const int acol = k16 * 16 + ((lane >> 4) << 3);
                const uint32_t addr = sq + (uint32_t)(arow * LDS + acol) * 2;
                LDSM_X4(qa_hi[k16][0], qa_hi[k16][1], qa_hi[k16][2], qa_hi[k16][3], addr);
                LDSM_X4(qa_lo[k16][0], qa_lo[k16][1], qa_lo[k16][2], qa_lo[k16][3], addr + FQ_BYTES);
            }
        }

        const uint32_t sk = skv0 + s * FK_STAGE;
        const uint32_t sv = sk + 2 * FQ_BYTES;

        float sacc[16][4];
        #pragma unroll
        for (int j = 0; j < 16; j++)
            #pragma unroll
            for (int q = 0; q < 4; q++) sacc[j][q] = 0.f;

        #pragma unroll
        for (int k16 = 0; k16 < 4; k16++) {
            const int kc = k16 * 16;
            uint32_t kbh[8][4], kbl[8][4];
            #pragma unroll
            for (int p = 0; p < 8; p++) {
                const int nrow = p * 16 + (lane & 7) + ((lane & 16) >> 1);
                const int ncol = kc + (lane & 8);
                const uint32_t addr = sk + (uint32_t)(nrow * LDS + ncol) * 2;
                LDSM_X4(kbh[p][0], kbh[p][1], kbh[p][2], kbh[p][3], addr);
                LDSM_X4(kbl[p][0], kbl[p][1], kbl[p][2], kbl[p][3], addr + FQ_BYTES);
            }
            #pragma unroll
            for (int nt = 0; nt < 16; nt++) {
                const int pr = nt >> 1, ix = (nt & 1) * 2;
                MMA_BF16(sacc[nt], qa_hi[k16], kbh[pr][ix], kbh[pr][ix+1]);
                MMA_BF16(sacc[nt], qa_lo[k16], kbh[pr][ix], kbh[pr][ix+1]);
                MMA_BF16(sacc[nt], qa_hi[k16], kbl[pr][ix], kbl[pr][ix+1]);
            }
        }

        float mxA = -1e30f, mxB = -1e30f;
        #pragma unroll
        for (int nt = 0; nt < 16; nt++) {
            const int col = jt * 128 + nt * 8 + (lane & 3) * 2;
            float v0 = sacc[nt][0] * QK_SCALE;
            float v1 = sacc[nt][1] * QK_SCALE;
            float v2 = sacc[nt][2] * QK_SCALE;
            float v3 = sacc[nt][3] * QK_SCALE;
            if (jt == it) {
                if (col     > grA) v0 = -1e30f;
                if (col + 1 > grA) v1 = -1e30f;
                if (col     > grB) v2 = -1e30f;
                if (col + 1 > grB) v3 = -1e30f;
            }
            sacc[nt][0] = v0; sacc[nt][1] = v1; sacc[nt][2] = v2; sacc[nt][3] = v3;
            mxA = fmaxf(mxA, fmaxf(v0, v1));
            mxB = fmaxf(mxB, fmaxf(v2, v3));
        }
        #pragma unroll
        for (int o = 1; o <= 2; o <<= 1) {
            mxA = fmaxf(mxA, __shfl_xor_sync(0xffffffffu, mxA, o));
            mxB = fmaxf(mxB, __shfl_xor_sync(0xffffffffu, mxB, o));
        }
        const float mnA = fmaxf(mrow[0], mxA);
        const float mnB = fmaxf(mrow[1], mxB);
        const float scA = __expf(mrow[0] - mnA);
        const float scB = __expf(mrow[1] - mnB);
        mrow[0] = mnA; mrow[1] = mnB;

        #pragma unroll
        for (int j = 0; j < 8; j++) {
            oacc[j][0] *= scA; oacc[j][1] *= scA;
            oacc[j][2] *= scB; oacc[j][3] *= scB;
        }

        float rsA = 0.f, rsB = 0.f;
        #pragma unroll
        for (int t = 0; t < 8; t++) {
            float p00 = __expf(sacc[2*t][0]   - mnA);
            float p01 = __expf(sacc[2*t][1]   - mnA);
            float p02 = __expf(sacc[2*t][2]   - mnB);
            float p03 = __expf(sacc[2*t][3]   - mnB);
            float p10 = __expf(sacc[2*t+1][0] - mnA);
            float p11 = __expf(sacc[2*t+1][1] - mnA);
            float p12 = __expf(sacc[2*t+1][2] - mnB);
            float p13 = __expf(sacc[2*t+1][3] - mnB);
            rsA += p00 + p01 + p10 + p11;
            rsB += p02 + p03 + p12 + p13;

            uint32_t pa_hi[4], pa_lo[4];
            pa_hi[0] = pack_bf16(p00, p01);
            pa_hi[1] = pack_bf16(p02, p03);
            pa_hi[2] = pack_bf16(p10, p11);
            pa_hi[3] = pack_bf16(p12, p13);
            {
                __nv_bfloat162* ph = (__nv_bfloat162*)pa_hi;
                pa_lo[0] = pack_bf16(p00 - __bfloat162float(ph[0].x), p01 - __bfloat162float(ph[0].y));
                pa_lo[1] = pack_bf16(p02 - __bfloat162float(ph[1].x), p03 - __bfloat162float(ph[1].y));
                pa_lo[2] = pack_bf16(p10 - __bfloat162float(ph[2].x), p11 - __bfloat162float(ph[2].y));
                pa_lo[3] = pack_bf16(p12 - __bfloat162float(ph[3].x), p13 - __bfloat162float(ph[3].y));
            }

            const int kc = t * 16;
            uint32_t vbh[4][4], vbl[4][4];
            #pragma unroll
            for (int p = 0; p < 4; p++) {
                const int nrow = p * 16 + (lane & 7) + ((lane & 16) >> 1);
                const int ncol = kc + (lane & 8);
                const uint32_t addr = sv + (uint32_t)(nrow * LDSV + ncol) * 2;
                LDSM_X4(vbh[p][0], vbh[p][1], vbh[p][2], vbh[p][3], addr);
                LDSM_X4(vbl[p][0], vbl[p][1], vbl[p][2], vbl[p][3], addr + FV_BYTES);
            }
            #pragma unroll
            for (int nto = 0; nto < 8; nto++) {
                const int pr = nto >> 1, ix = (nto & 1) * 2;
                MMA_BF16(oacc[nto], pa_hi, vbh[pr][ix], vbh[pr][ix+1]);
                MMA_BF16(oacc[nto], pa_lo, vbh[pr][ix], vbh[pr][ix+1]);
                MMA_BF16(oacc[nto], pa_hi, vbl[pr][ix], vbl[pr][ix+1]);
            }
        }
        #pragma unroll
        for (int o = 1; o <= 2; o <<= 1) {
            rsA += __shfl_xor_sync(0xffffffffu, rsA, o);
            rsB += __shfl_xor_sync(0xffffffffu, rsB, o);
        }
        lrowv[0] = lrowv[0] * scA + rsA;
        lrowv[1] = lrowv[1] * scB + rsB;

        __syncthreads();
    }

    const float invA = 1.0f / lrowv[0];
    const float invB = 1.0f / lrowv[1];
    const int sA = it * 128 + wid * 16 + (lane >> 2);
    const int sB = sA + 8;
    #pragma unroll
    for (int nto = 0; nto < 8; nto++) {
        const int d = nto * 8 + (lane & 3) * 2;
        const size_t gA = ((size_t)(b * Sq + sA)) * Dm + h * DHd + d;
        const size_t gB = ((size_t)(b * Sq + sB)) * Dm + h * DHd + d;
        float v0 = oacc[nto][0] * invA, v1 = oacc[nto][1] * invA;
        float v2 = oacc[nto][2] * invB, v3 = oacc[nto][3] * invB;
        __nv_bfloat16 h0 = __float2bfloat16(v0), h1 = __float2bfloat16(v1);
        __nv_bfloat16 h2 = __float2bfloat16(v2), h3 = __float2bfloat16(v3);
        __nv_bfloat162 hhA; hhA.x = h0; hhA.y = h1;
        __nv_bfloat162 hhB; hhB.x = h2; hhB.y = h3;
        __nv_bfloat162 llA, llB;
        llA.x = __float2bfloat16(v0 - __bfloat162float(h0));
        llA.y = __float2bfloat16(v1 - __bfloat162float(h1));
        llB.x = __float2bfloat16(v2 - __bfloat162float(h2));
        llB.y = __float2bfloat16(v3 - __bfloat162float(h3));
        *(__nv_bfloat162*)(aohi + gA) = hhA;
        *(__nv_bfloat162*)(aolo + gA) = llA;
        *(__nv_bfloat162*)(aohi + gB) = hhB;
        *(__nv_bfloat162*)(aolo + gB) = llB;
    }
}

// ---------------- sum experts (fp16) + final LayerNorm ----------------
__global__ void redln_kernel(const __half* __restrict__ expout, const float* __restrict__ g,
                             const float* __restrict__ b, float* __restrict__ out)
{
    __shared__ float buf[Dm];
    __shared__ float red[256];
    const int row = blockIdx.x;
    const int tid = threadIdx.x;
    float s = 0.f;
    for (int i = tid; i < Dm; i += 256) {
        float v = 0.f;
        #pragma unroll
        for (int e = 0; e < Ex; e++)
            v += __half2float(expout[(size_t)e * ROWS * Dm + (size_t)row * Dm + i]);
        buf[i] = v; s += v;
    }
    red[tid] = s; __syncthreads();
    for (int off = 128; off > 0; off >>= 1) { if (tid < off) red[tid] += red[tid+off]; __syncthreads(); }
    const float mean = red[0] * (1.0f / Dm);
    __syncthreads();
    float s2 = 0.f;
    for (int i = tid; i < Dm; i += 256) { float d = buf[i] - mean; s2 += d * d; }
    red[tid] = s2; __syncthreads();
    for (int off = 128; off > 0; off >>= 1) { if (tid < off) red[tid] += red[tid+off]; __syncthreads(); }
    const float inv = rsqrtf(red[0] * (1.0f / Dm) + 1e-5f);
    for (int i = tid; i < Dm; i += 256)
        out[(size_t)row * Dm + i] = (buf[i] - mean) * inv * g[i] + b[i];
}

// ---------------- launch ----------------
extern "C" void kernel_launch(void* const* d_in, const int* in_sizes, int n_in,
                              void* d_out, int out_size)
{
    const float* x       = (const float*)d_in[0];
    const float* ln_g    = (const float*)d_in[1];
    const float* ln_b    = (const float*)d_in[2];
    const float* Wq      = (const float*)d_in[3];
    const float* Wk      = (const float*)d_in[4];
    const float* Wv      = (const float*)d_in[5];
    const float* q_scale = (const float*)d_in[6];
    const float* k_scale = (const float*)d_in[7];
    const float* Wo      = (const float*)d_in[8];
    const float* gate_w  = (const float*)d_in[9];
    const float* gate_b  = (const float*)d_in[10];
    const float* w1      = (const float*)d_in[11];
    const float* b1      = (const float*)d_in[12];
    const float* w2      = (const float*)d_in[13];
    const float* b2      = (const float*)d_in[14];
    float* out = (float*)d_out;

    __nv_bfloat16 *h1hi, *h1lo, *aohi, *aolo;
    __half *h2h16, *hid, *w1Th, *w2Th, *expout;
    __nv_bfloat16 *qnh, *qnl, *knh, *knl, *vTh, *vTl;
    __nv_bfloat16 *wqkvThi, *wqkvTlo, *woThi, *woTlo;
    float *qkvf, *o, *gate;
    cudaGetSymbolAddress((void**)&h1hi, g_h1hi);   cudaGetSymbolAddress((void**)&h1lo, g_h1lo);
    cudaGetSymbolAddress((void**)&qkvf, g_qkvf);
    cudaGetSymbolAddress((void**)&qnh, g_qnh);     cudaGetSymbolAddress((void**)&qnl, g_qnl);
    cudaGetSymbolAddress((void**)&knh, g_knh);     cudaGetSymbolAddress((void**)&knl, g_knl);
    cudaGetSymbolAddress((void**)&vTh, g_vTh);     cudaGetSymbolAddress((void**)&vTl, g_vTl);
    cudaGetSymbolAddress((void**)&aohi, g_aohi);   cudaGetSymbolAddress((void**)&aolo, g_aolo);
    cudaGetSymbolAddress((void**)&o, g_o);
    cudaGetSymbolAddress((void**)&h2h16, g_h2h16);
    cudaGetSymbolAddress((void**)&gate, g_gate);
    cudaGetSymbolAddress((void**)&hid, g_hid);
    cudaGetSymbolAddress((void**)&expout, g_expout);
    cudaGetSymbolAddress((void**)&wqkvThi, g_wqkvThi); cudaGetSymbolAddress((void**)&wqkvTlo, g_wqkvTlo);
    cudaGetSymbolAddress((void**)&woThi, g_woThi);     cudaGetSymbolAddress((void**)&woTlo, g_woTlo);
    cudaGetSymbolAddress((void**)&w1Th, g_w1Th);
    cudaGetSymbolAddress((void**)&w2Th, g_w2Th);

    cudaFuncSetAttribute(bgemm_kernel<0,0>, cudaFuncAttributeMaxDynamicSharedMemorySize, SMEM_M0);
    cudaFuncSetAttribute(bgemm_kernel<1,2>, cudaFuncAttributeMaxDynamicSharedMemorySize, SMEM_M2);
    cudaFuncSetAttribute(bgemm_kernel<2,2>, cudaFuncAttributeMaxDynamicSharedMemorySize, SMEM_M2);
    cudaFuncSetAttribute(flash_kernel,      cudaFuncAttributeMaxDynamicSharedMemorySize, SMEM_FL);

    // ---- side stream: weight prep not needed until step 5/7 -----------------
    cudaStream_t s2;
    cudaStreamCreateWithFlags(&s2, cudaStreamNonBlocking);
    cudaEvent_t evFork, evJoin;
    cudaEventCreateWithFlags(&evFork, cudaEventDisableTiming);
    cudaEventCreateWithFlags(&evJoin, cudaEventDisableTiming);

    // QKV weight prep must complete before step 2 -> keep on main stream
    wprep_kernel<<<dim3(Dm/32, Dm/32, 1), dim3(32,8)>>>(Wq, wqkvThi,           wqkvTlo,           Dm, Dm);
    wprep_kernel<<<dim3(Dm/32, Dm/32, 1), dim3(32,8)>>>(Wk, wqkvThi + Dm*Dm,   wqkvTlo + Dm*Dm,   Dm, Dm);
    wprep_kernel<<<dim3(Dm/32, Dm/32, 1), dim3(32,8)>>>(Wv, wqkvThi + 2*Dm*Dm, wqkvTlo + 2*Dm*Dm, Dm, Dm);

    // fork: Wo/w1/w2 prep runs concurrently with LN + QKV GEMM + attention
    cudaEventRecord(evFork, 0);
    cudaStreamWaitEvent(s2, evFork, 0);
    wprep_kernel<<<dim3(Dm/32, Dm/32, 1), dim3(32,8), 0, s2>>>(Wo, woThi, woTlo, Dm, Dm);
    wprep16_kernel<<<dim3(FFd/32, Dm/64, Ex), 256, 0, s2>>>(w1, w1Th, Dm, FFd);
    wprep16_kernel<<<dim3(Dm/32, FFd/64, Ex), 256, 0, s2>>>(w2, w2Th, FFd, Dm);
    cudaEventRecord(evJoin, s2);

    // 1. pre-attention LN -> bf16 hi/lo
    ln_kernel<<<ROWS, 256>>>(x, ln_g, ln_b, nullptr, h1hi, h1lo, nullptr,
                             nullptr, nullptr, nullptr);

    // 2. fused QKV projection (bf16 3-term)
    bgemm_kernel<0,0><<<dim3(3*Dm/BN, ROWS/BM, 1), 256, SMEM_M0>>>(
        h1hi, h1lo, wqkvThi, wqkvTlo, 3*Dm, Dm, 0, 0, 0,
        qkvf, nullptr, nullptr, 0, nullptr);

    // 3. l2norm q+k (one launch) -> bf16 hi/lo; v transpose
    l2n_kernel<<<dim3((BH*Sq)/8, 2), 256>>>(qkvf, q_scale, k_scale, qnh, qnl, knh, knl);
    vtrans_kernel<<<dim3(Sq/32, DHd/32, BH), dim3(32,8)>>>(qkvf, vTh, vTl);

    // 4. fused flash attention (heavy tiles first)
    flash_kernel<<<dim3(Sq/128, BH), 256, SMEM_FL>>>(qnh, qnl, knh, knl, vTh, vTl, aohi, aolo);

    // join: Wo/w1/w2 prep must be done before step 5
    cudaStreamWaitEvent(0, evJoin, 0);

    // 5. output projection (bf16 3-term) + mid LN (with fused gate softmax)
    bgemm_kernel<0,0><<<dim3(Dm/BN, ROWS/BM, 1), 256, SMEM_M0>>>(
        aohi, aolo, woThi, woTlo, Dm, Dm, 0, 0, 0,
        o, nullptr, nullptr, 0, nullptr);
    ln_kernel<<<ROWS, 256>>>(o, ln_g, ln_b, nullptr, nullptr, nullptr, h2h16,
                             gate_w, gate_b, gate);

    // 7. MoE GEMM1 (fp16 1-term, 3-stage)
    bgemm_kernel<1,2><<<dim3(FFd/BN, ROWS/BM, Ex), 256, SMEM_M2>>>(
        h2h16, nullptr, w1Th, nullptr, FFd, Dm,
        0, (long long)FFd*Dm, (long long)ROWS*FFd,
        nullptr, hid, b1, FFd, nullptr);

    // 8. MoE GEMM2 (fp16 1-term, 3-stage) -> fp16 gated expert outputs
    bgemm_kernel<2,2><<<dim3(Dm/BN, ROWS/BM, Ex), 256, SMEM_M2>>>(
        hid, nullptr, w2Th, nullptr, Dm, FFd,
        (long long)ROWS*FFd, (long long)Dm*FFd, (long long)ROWS*Dm,
        nullptr, expout, b2, Dm, gate);

    // 9. sum experts (fp16) + final LN -> out
    redln_kernel<<<ROWS, 256>>>(expout, ln_g, ln_b, out);

    cudaEventDestroy(evFork);
    cudaEventDestroy(evJoin);
    cudaStreamDestroy(s2);
}

// round 16
// speedup vs baseline: 1.0212x; 1.0063x over previous
#include <cuda_runtime.h>
#include <cuda_bf16.h>
#include <cuda_fp16.h>
#include <math.h>
#include <stdint.h>

// ---------------- problem constants ----------------
#define Bc   2
#define Sq   1024
#define Dm   1024
#define Hh   16
#define DHd  64
#define Ex   8
#define FFd  4096
#define BH   (Bc*Hh)     // 32
#define ROWS (Bc*Sq)     // 2048
#define QK_SCALE 10.0f

// GEMM tiling (bgemm: 256x128 CTA tile)
#define BM 256
#define BN 128
#define BK 64
#define LDS 72                        // BK + 8 pad (16-bit units)
#define A_BYTES (256*LDS*2)           // 36864
#define B_BYTES (128*LDS*2)           // 18432
#define SMEM_M0 (2*(2*A_BYTES + 2*B_BYTES))  // 221184 (bf16 3-term, 2 stages)
#define SMEM_M2 (3*(A_BYTES + B_BYTES))      // 165888 (fp16 1-term, 3 stages)

// flash attention tiling
#define FQ_BYTES (128*LDS*2)          // 18432
#define LDSV 136
#define FV_BYTES (64*LDSV*2)          // 17408
#define FK_STAGE (2*FQ_BYTES + 2*FV_BYTES)   // 71680
#define SMEM_FL (2*FQ_BYTES + 2*FK_STAGE)    // 180224

// ---------------- low-level helpers ----------------
__device__ __forceinline__ uint32_t smem_u32(const void* p) {
    uint32_t a;
    asm("{ .reg .u64 t; cvta.to.shared.u64 t, %1; cvt.u32.u64 %0, t; }" : "=r"(a) : "l"(p));
    return a;
}
__device__ __forceinline__ void cp16(uint32_t dst, const void* src) {
    asm volatile("cp.async.cg.shared.global [%0], [%1], 16;" :: "r"(dst), "l"(src));
}
#define CP_COMMIT() asm volatile("cp.async.commit_group;" ::: "memory")
#define CP_WAIT(n)  asm volatile("cp.async.wait_group %0;" :: "n"(n) : "memory")

#define LDSM_X4(r0, r1, r2, r3, addr) \
    asm volatile("ldmatrix.sync.aligned.m8n8.x4.shared.b16 {%0,%1,%2,%3}, [%4];" \
        : "=r"(r0), "=r"(r1), "=r"(r2), "=r"(r3) : "r"(addr))

#define MMA_BF16(d, a, b0, b1) \
    asm volatile("mma.sync.aligned.m16n8k16.row.col.f32.bf16.bf16.f32 " \
        "{%0,%1,%2,%3}, {%4,%5,%6,%7}, {%8,%9}, {%0,%1,%2,%3};" \
        : "+f"((d)[0]), "+f"((d)[1]), "+f"((d)[2]), "+f"((d)[3]) \
        : "r"((a)[0]), "r"((a)[1]), "r"((a)[2]), "r"((a)[3]), "r"(b0), "r"(b1))

#define MMA_F16(d, a, b0, b1) \
    asm volatile("mma.sync.aligned.m16n8k16.row.col.f32.f16.f16.f32 " \
        "{%0,%1,%2,%3}, {%4,%5,%6,%7}, {%8,%9}, {%0,%1,%2,%3};" \
        : "+f"((d)[0]), "+f"((d)[1]), "+f"((d)[2]), "+f"((d)[3]) \
        : "r"((a)[0]), "r"((a)[1]), "r"((a)[2]), "r"((a)[3]), "r"(b0), "r"(b1))

__device__ __forceinline__ uint32_t pack_bf16(float a, float b) {
    __nv_bfloat162 t;
    t.x = __float2bfloat16(a);
    t.y = __float2bfloat16(b);
    return *(uint32_t*)&t;
}

// ---------------- scratch (device globals) ----------------
__device__ __nv_bfloat16 g_h1hi[ROWS*Dm], g_h1lo[ROWS*Dm];
__device__ float g_qkvf[ROWS*3*Dm];
__device__ __nv_bfloat16 g_qnh[BH*Sq*DHd], g_qnl[BH*Sq*DHd];
__device__ __nv_bfloat16 g_knh[BH*Sq*DHd], g_knl[BH*Sq*DHd];
__device__ __nv_bfloat16 g_vTh[BH*DHd*Sq], g_vTl[BH*DHd*Sq];
__device__ __nv_bfloat16 g_aohi[ROWS*Dm], g_aolo[ROWS*Dm];
__device__ float g_o[ROWS*Dm];
__device__ __half g_h2h16[ROWS*Dm];
__device__ float g_gate[ROWS*Ex];
__device__ __half g_hid[(size_t)Ex*ROWS*FFd];
__device__ __half g_expout[(size_t)Ex*ROWS*Dm];
__device__ __nv_bfloat16 g_wqkvThi[3*Dm*Dm], g_wqkvTlo[3*Dm*Dm];
__device__ __nv_bfloat16 g_woThi[Dm*Dm], g_woTlo[Dm*Dm];
__device__ __half g_w1Th[(size_t)Ex*FFd*Dm];
__device__ __half g_w2Th[(size_t)Ex*Dm*FFd];

// ---------------- math helpers ----------------
__device__ __forceinline__ float gelu_f(float x) {
    float x3 = x * x * x;
    float t  = tanhf(0.7978845608028654f * (x + 0.044715f * x3));
    return 0.5f * x * (1.0f + t);
}

// ---------------- weight transpose + bf16 split (small matrices) -----------
__global__ void wprep_kernel(const float* __restrict__ W, __nv_bfloat16* __restrict__ hi,
                             __nv_bfloat16* __restrict__ lo, int K, int N)
{
    __shared__ float t[32][33];
    const size_t zoff = (size_t)blockIdx.z * K * N;
    const int k0 = blockIdx.y * 32, n0 = blockIdx.x * 32;
    const int tx = threadIdx.x, ty = threadIdx.y;
    #pragma unroll
    for (int i = 0; i < 4; i++)
        t[ty + 8*i][tx] = W[zoff + (size_t)(k0 + ty + 8*i) * N + n0 + tx];
    __syncthreads();
    #pragma unroll
    for (int i = 0; i < 4; i++) {
        float v = t[tx][ty + 8*i];
        const size_t o = zoff + (size_t)(n0 + ty + 8*i) * K + k0 + tx;
        __nv_bfloat16 h = __float2bfloat16(v);
        hi[o] = h;
        lo[o] = __float2bfloat16(v - __bfloat162float(h));
    }
}

// ---------------- FAST weight transpose + fp16: W[K,N] -> fp16 [N,K] -------
__global__ void __launch_bounds__(256)
wprep16_kernel(const float* __restrict__ W, __half* __restrict__ out, int K, int N)
{
    __shared__ float t[64][33];
    const size_t zoff = (size_t)blockIdx.z * K * N;
    const int k0 = blockIdx.y * 64, n0 = blockIdx.x * 32;
    const int tid = threadIdx.x;
    const int lx = tid & 31;
    const int ly = tid >> 5;
    #pragma unroll
    for (int i = 0; i < 8; i++) {
        const int kk = ly + 8 * i;
        t[kk][lx] = W[zoff + (size_t)(k0 + kk) * N + n0 + lx];
    }
    __syncthreads();
    const int n  = tid >> 3;
    const int ks = (tid & 7) * 8;
    __half h[8];
    #pragma unroll
    for (int j = 0; j < 8; j++) h[j] = __float2half(t[ks + j][n]);
    *(uint4*)(out + zoff + (size_t)(n0 + n) * K + k0 + ks) = *(uint4*)h;
}

// ---------------- LayerNorm (vectorized, + optional fused gate softmax) ----
__global__ void ln_kernel(const float* __restrict__ x, const float* __restrict__ g,
                          const float* __restrict__ b, float* __restrict__ yf,
                          __nv_bfloat16* __restrict__ yhi, __nv_bfloat16* __restrict__ ylo,
                          __half* __restrict__ y16,
                          const float* __restrict__ gw, const float* __restrict__ gb,
                          float* __restrict__ gateOut)
{
    __shared__ float buf[Dm];
    __shared__ float red[256];
    __shared__ float lg[Ex];
    const int row = blockIdx.x;
    const int tid = threadIdx.x;
    const int i0  = tid * 4;          // 256 threads x 4 = 1024 = Dm
    const float* xr = x + (size_t)row * Dm;

    float4 v4 = *(const float4*)(xr + i0);
    buf[i0] = v4.x; buf[i0+1] = v4.y; buf[i0+2] = v4.z; buf[i0+3] = v4.w;
    float s = v4.x + v4.y + v4.z + v4.w;
    red[tid] = s; __syncthreads();
    for (int off = 128; off > 0; off >>= 1) { if (tid < off) red[tid] += red[tid+off]; __syncthreads(); }
    const float mean = red[0] * (1.0f / Dm);
    __syncthreads();
    float s2 = 0.f;
    #pragma unroll
    for (int j = 0; j < 4; j++) { float d = buf[i0+j] - mean; s2 += d * d; }
    red[tid] = s2; __syncthreads();
    for (int off = 128; off > 0; off >>= 1) { if (tid < off) red[tid] += red[tid+off]; __syncthreads(); }
    const float inv = rsqrtf(red[0] * (1.0f / Dm) + 1e-5f);

    const float4 g4 = *(const float4*)(g + i0);
    const float4 b4 = *(const float4*)(b + i0);
    float vv[4];
    vv[0] = (buf[i0]   - mean) * inv * g4.x + b4.x;
    vv[1] = (buf[i0+1] - mean) * inv * g4.y + b4.y;
    vv[2] = (buf[i0+2] - mean) * inv * g4.z + b4.z;
    vv[3] = (buf[i0+3] - mean) * inv * g4.w + b4.w;
    buf[i0] = vv[0]; buf[i0+1] = vv[1]; buf[i0+2] = vv[2]; buf[i0+3] = vv[3];
    if (yf) *(float4*)(yf + (size_t)row * Dm + i0) = make_float4(vv[0], vv[1], vv[2], vv[3]);
    if (yhi) {
        __nv_bfloat162 h0, h1, l0, l1;
        h0.x = __float2bfloat16(vv[0]); h0.y = __float2bfloat16(vv[1]);
        h1.x = __float2bfloat16(vv[2]); h1.y = __float2bfloat16(vv[3]);
        l0.x = __float2bfloat16(vv[0] - __bfloat162float(h0.x));
        l0.y = __float2bfloat16(vv[1] - __bfloat162float(h0.y));
        l1.x = __float2bfloat16(vv[2] - __bfloat162float(h1.x));
        l1.y = __float2bfloat16(vv[3] - __bfloat162float(h1.y));
        *(__nv_bfloat162*)(yhi + (size_t)row*Dm + i0)     = h0;
        *(__nv_bfloat162*)(yhi + (size_t)row*Dm + i0 + 2) = h1;
        *(__nv_bfloat162*)(ylo + (size_t)row*Dm + i0)     = l0;
        *(__nv_bfloat162*)(ylo + (size_t)row*Dm + i0 + 2) = l1;
    }
    if (y16) {
        __half2 a = __halves2half2(__float2half(vv[0]), __float2half(vv[1]));
        __half2 c = __halves2half2(__float2half(vv[2]), __float2half(vv[3]));
        *(__half2*)(y16 + (size_t)row*Dm + i0)     = a;
        *(__half2*)(y16 + (size_t)row*Dm + i0 + 2) = c;
    }
    if (gateOut) {
        __syncthreads();
        const int e = tid >> 5, lane = tid & 31;
        float sg = 0.f;
        for (int k = lane; k < Dm; k += 32) sg += buf[k] * gw[k * Ex + e];
        #pragma unroll
        for (int o = 16; o; o >>= 1) sg += __shfl_xor_sync(0xffffffffu, sg, o);
        if (lane == 0) lg[e] = sg + gb[e];
        __syncthreads();
        if (tid == 0) {
            float m = lg[0];
            #pragma unroll
            for (int q = 1; q < Ex; q++) m = fmaxf(m, lg[q]);
            float ex[Ex], sum = 0.f;
            #pragma unroll
            for (int q = 0; q < Ex; q++) { ex[q] = expf(lg[q] - m); sum += ex[q]; }
            const float invs = 1.0f / sum;
            #pragma unroll
            for (int q = 0; q < Ex; q++) gateOut[(size_t)row * Ex + q] = ex[q] * invs;
        }
    }
}

// ---------------- mma.sync GEMM ------------
// MODE 0: bf16 3-term, NSTG=2. MODE 2: fp16 single-term, NSTG=3.
// EPI 0: fp32 store; EPI 1: gelu(acc+bias) -> fp16; EPI 2: gate*(acc+bias) -> fp16
template<int EPI, int MODE>
__global__ void __launch_bounds__(256, 1)
bgemm_kernel(const void* __restrict__ Ahi_, const void* __restrict__ Alo_,
             const void* __restrict__ Bhi_, const void* __restrict__ Blo_,
             int N, int K,
             long long az, long long bz, long long oz,
             float* __restrict__ outf,
             void* __restrict__ outhi_,
             const float* __restrict__ bias, long long biasz,
             const float* __restrict__ gate)
{
    extern __shared__ char smem[];
    const uint32_t sbase = smem_u32(smem);
    const int tid  = threadIdx.x;
    const int wid  = tid >> 5;
    const int lane = tid & 31;
    const int wm   = wid >> 1;
    const int wn   = wid & 1;
    const int m0 = blockIdx.y * BM;
    const int n0 = blockIdx.x * BN;
    const int e  = blockIdx.z;

    constexpr int NSTG = (MODE == 0) ? 2 : 3;
    constexpr int STG = (MODE == 0) ? (2*A_BYTES + 2*B_BYTES) : (A_BYTES + B_BYTES);
    const uint16_t* pAhi = (const uint16_t*)Ahi_ + (size_t)e * az;
    const uint16_t* pAlo = (const uint16_t*)Alo_ + (size_t)e * az;
    const uint16_t* pBhi = (const uint16_t*)Bhi_ + (size_t)e * bz;
    const uint16_t* pBlo = (const uint16_t*)Blo_ + (size_t)e * bz;
    constexpr uint32_t B_OFF = (MODE == 0) ? 2*A_BYTES : A_BYTES;

    const int lrow = tid >> 3;
    const int lc8  = (tid & 7) * 8;

    float acc[4][8][4];
    #pragma unroll
    for (int i = 0; i < 4; i++)
        #pragma unroll
        for (int j = 0; j < 8; j++)
            #pragma unroll
            for (int q = 0; q < 4; q++) acc[i][j][q] = 0.f;

    const int NB = K / BK;

    auto load_stage = [&](int kb, int slot) {
        const int kk = kb * BK;
        const uint32_t so = sbase + slot * STG;
        #pragma unroll
        for (int i = 0; i < 8; i++) {
            const int row = lrow + i * 32;
            const uint32_t sa = so + (uint32_t)(row * LDS + lc8) * 2;
            const size_t ga = (size_t)(m0 + row) * K + kk + lc8;
            cp16(sa, pAhi + ga);
            if (MODE == 0) cp16(sa + A_BYTES, pAlo + ga);
        }
        #pragma unroll
        for (int i = 0; i < 4; i++) {
            const int row = lrow + i * 32;
            const uint32_t sb = so + B_OFF + (uint32_t)(row * LDS + lc8) * 2;
            const size_t gb = (size_t)(n0 + row) * K + kk + lc8;
            cp16(sb, pBhi + gb);
            if (MODE == 0) cp16(sb + B_BYTES, pBlo + gb);
        }
        CP_COMMIT();
    };

    // prefetch NSTG-1 stages
    #pragma unroll
    for (int p = 0; p < NSTG - 1; p++) load_stage(p, p);

    for (int kb = 0; kb < NB; kb++) {
        const int s = kb % NSTG;
        if (kb + NSTG - 1 < NB) {
            load_stage(kb + NSTG - 1, (kb + NSTG - 1) % NSTG);
            CP_WAIT(NSTG - 1);
        } else if (kb + 1 < NB) {
            CP_WAIT(1);
        } else {
            CP_WAIT(0);
        }
        __syncthreads();

        const uint32_t so = sbase + s * STG;
        #pragma unroll
        for (int k16 = 0; k16 < 4; k16++) {
            const int kc = k16 * 16;
            uint32_t ah[4][4], al[4][4], bh[4][4], bl[4][4];
            #pragma unroll
            for (int mt = 0; mt < 4; mt++) {
                const int arow = wm * 64 + mt * 16 + (lane & 15);
                const int acol = kc + ((lane >> 4) << 3);
                const uint32_t addr = so + (uint32_t)(arow * LDS + acol) * 2;
                LDSM_X4(ah[mt][0], ah[mt][1], ah[mt][2], ah[mt][3], addr);
                if (MODE == 0) LDSM_X4(al[mt][0], al[mt][1], al[mt][2], al[mt][3], addr + A_BYTES);
            }
            #pragma unroll
            for (int p = 0; p < 4; p++) {
                const int nrow = wn * 64 + p * 16 + (lane & 7) + ((lane & 16) >> 1);
                const int ncol = kc + (lane & 8);
                const uint32_t addr = so + B_OFF + (uint32_t)(nrow * LDS + ncol) * 2;
                LDSM_X4(bh[p][0], bh[p][1], bh[p][2], bh[p][3], addr);
                if (MODE == 0) LDSM_X4(bl[p][0], bl[p][1], bl[p][2], bl[p][3], addr + B_BYTES);
            }
            #pragma unroll
            for (int mt = 0; mt < 4; mt++) {
                #pragma unroll
                for (int nt = 0; nt < 8; nt++) {
                    const int pr = nt >> 1, ix = (nt & 1) * 2;
                    if (MODE == 0) {
                        MMA_BF16(acc[mt][nt], ah[mt], bh[pr][ix], bh[pr][ix+1]);
                        MMA_BF16(acc[mt][nt], al[mt], bh[pr][ix], bh[pr][ix+1]);
                        MMA_BF16(acc[mt][nt], ah[mt], bl[pr][ix], bl[pr][ix+1]);
                    } else {
                        MMA_F16(acc[mt][nt], ah[mt], bh[pr][ix], bh[pr][ix+1]);
                    }
                }
            }
        }
        __syncthreads();
    }

    #pragma unroll
    for (int mt = 0; mt < 4; mt++) {
        const int rA = m0 + wm * 64 + mt * 16 + (lane >> 2);
        const int rB = rA + 8;
        float gv0 = 0.f, gv1 = 0.f;
        if (EPI == 2) {
            gv0 = gate[(size_t)rA * Ex + e];
            gv1 = gate[(size_t)rB * Ex + e];
        }
        #pragma unroll
        for (int nt = 0; nt < 8; nt++) {
            const int col = n0 + wn * 64 + nt * 8 + (lane & 3) * 2;
            float d0 = acc[mt][nt][0], d1 = acc[mt][nt][1];
            float d2 = acc[mt][nt][2], d3 = acc[mt][nt][3];
            if (EPI == 0) {
                *(float2*)(outf + (size_t)rA * N + col) = make_float2(d0, d1);
                *(float2*)(outf + (size_t)rB * N + col) = make_float2(d2, d3);
            } else if (EPI == 1) {
                const float b0 = bias[(size_t)e * biasz + col];
                const float b1 = bias[(size_t)e * biasz + col + 1];
                float v0 = gelu_f(d0 + b0), v1 = gelu_f(d1 + b1);
                float v2 = gelu_f(d2 + b0), v3 = gelu_f(d3 + b1);
                const size_t gA = (size_t)e * oz + (size_t)rA * N + col;
                const size_t gB = (size_t)e * oz + (size_t)rB * N + col;
                __half* oh = (__half*)outhi_;
                *(__half2*)(oh + gA) = __halves2half2(__float2half(v0), __float2half(v1));
                *(__half2*)(oh + gB) = __halves2half2(__float2half(v2), __float2half(v3));
            } else {
                const float b0 = bias[(size_t)e * biasz + col];
                const float b1 = bias[(size_t)e * biasz + col + 1];
                const size_t gA = (size_t)e * oz + (size_t)rA * N + col;
                const size_t gB = (size_t)e * oz + (size_t)rB * N + col;
                __half* oh = (__half*)outhi_;
                *(__half2*)(oh + gA) = __halves2half2(__float2half(gv0 * (d0 + b0)),
                                                      __float2half(gv0 * (d1 + b1)));
                *(__half2*)(oh + gB) = __halves2half2(__float2half(gv1 * (d2 + b0)),
                                                      __float2half(gv1 * (d3 + b1)));
            }
        }
    }
}

// ---------------- l2norm q/k + v transpose, one launch ----------------
// blockIdx.y: 0 = l2n(q), 1 = l2n(k), 2 = vtrans
__global__ void qkvprep_kernel(const float* __restrict__ qkv,
                               const float* __restrict__ q_scale, const float* __restrict__ k_scale,
                               __nv_bfloat16* __restrict__ qh, __nv_bfloat16* __restrict__ ql,
                               __nv_bfloat16* __restrict__ kh, __nv_bfloat16* __restrict__ kl,
                               __nv_bfloat16* __restrict__ vh, __nv_bfloat16* __restrict__ vl)
{
    __shared__ float t[32][33];
    const int sel = blockIdx.y;
    const int tid = threadIdx.x;
    if (sel < 2) {
        const int r    = blockIdx.x * 8 + (tid >> 5);
        const int lane = tid & 31;
        const int base = sel * Dm;
        const float* scale = sel ? k_scale : q_scale;
        __nv_bfloat16* oh = sel ? kh : qh;
        __nv_bfloat16* ol = sel ? kl : ql;
        const int b = r / (Hh * Sq);
        const int h = (r / Sq) % Hh;
        const int s = r % Sq;
        const float* src = qkv + (size_t)(b * Sq + s) * (3*Dm) + base + h * DHd;
        float v0 = src[lane], v1 = src[lane + 32];
        float ss = v0 * v0 + v1 * v1;
        #pragma unroll
        for (int o = 16; o; o >>= 1) ss += __shfl_xor_sync(0xffffffffu, ss, o);
        const float inv = rsqrtf(ss + 1e-12f);
        float f0 = v0 * inv * scale[h * DHd + lane];
        float f1 = v1 * inv * scale[h * DHd + lane + 32];
        const size_t d = (size_t)r * DHd;
        __nv_bfloat16 h0 = __float2bfloat16(f0);
        __nv_bfloat16 h1 = __float2bfloat16(f1);
        oh[d + lane]      = h0;
        ol[d + lane]      = __float2bfloat16(f0 - __bfloat162float(h0));
        oh[d + lane + 32] = h1;
        ol[d + lane + 32] = __float2bfloat16(f1 - __bfloat162float(h1));
    } else {
        // vtrans: 2048 tiles -> blockIdx.x in [0, 2048)
        if (blockIdx.x >= 2048) return;
        const int bh = blockIdx.x & 31;          // 32 bh
        const int d0 = ((blockIdx.x >> 5) & 1) * 32;  // 2 d-tiles
        const int s0 = (blockIdx.x >> 6) * 32;   // 32 s-tiles
        const int b = bh >> 4, h = bh & 15;
        const int tx = tid & 31, ty = tid >> 5;
        #pragma unroll
        for (int i = 0; i < 4; i++)
            t[ty + 8*i][tx] = qkv[(size_t)(b * Sq + s0 + ty + 8*i) * (3*Dm) + 2*Dm + h * DHd + d0 + tx];
        __syncthreads();
        #pragma unroll
        for (int i = 0; i < 4; i++) {
            float v = t[tx][ty + 8*i];
            const size_t o = ((size_t)bh * DHd + d0 + ty + 8*i) * Sq + s0 + tx;
            __nv_bfloat16 hh = __float2bfloat16(v);
            vh[o] = hh;
            vl[o] = __float2bfloat16(v - __bfloat162float(hh));
        }
    }
}

// ---------------- fused flash attention (heavy tiles scheduled first) -------
__global__ void __launch_bounds__(256, 1)
flash_kernel(const __nv_bfloat16* __restrict__ qh, const __nv_bfloat16* __restrict__ ql,
             const __nv_bfloat16* __restrict__ kh, const __nv_bfloat16* __restrict__ kl,
             const __nv_bfloat16* __restrict__ vth, const __nv_bfloat16* __restrict__ vtl,
             __nv_bfloat16* __restrict__ aohi, __nv_bfloat16* __restrict__ aolo)
{
    extern __shared__ char smem[];
    const uint32_t sbase = smem_u32(smem);
    const int tid  = threadIdx.x;
    const int wid  = tid >> 5;
    const int lane = tid & 31;
    const int it = gridDim.x - 1 - blockIdx.x;   // heavy rows first
    const int bh = blockIdx.y;
    const int b = bh >> 4, h = bh & 15;

    const int lrow = tid >> 3;
    const int lc8  = (tid & 7) * 8;
    const int vrow = tid >> 4;
    const int vc8  = (tid & 15) * 8;

    const uint32_t sq = sbase;
    const uint32_t skv0 = sbase + 2 * FQ_BYTES;

    #pragma unroll
    for (int i = 0; i < 4; i++) {
        const int row = lrow + i * 32;
        const uint32_t sa = sq + (uint32_t)(row * LDS + lc8) * 2;
        const size_t gq = ((size_t)bh * Sq + it * 128 + row) * DHd + lc8;
        cp16(sa,            qh + gq);
        cp16(sa + FQ_BYTES, ql + gq);
    }
    {
        const uint32_t so = skv0;
        #pragma unroll
        for (int i = 0; i < 4; i++) {
            const int row = lrow + i * 32;
            const uint32_t sa = so + (uint32_t)(row * LDS + lc8) * 2;
            const size_t gk = ((size_t)bh * Sq + row) * DHd + lc8;
            cp16(sa,            kh + gk);
            cp16(sa + FQ_BYTES, kl + gk);
        }
        #pragma unroll
        for (int i = 0; i < 4; i++) {
            const int row = vrow + i * 16;
            const uint32_t sa = so + 2*FQ_BYTES + (uint32_t)(row * LDSV + vc8) * 2;
            const size_t gv = ((size_t)bh * DHd + row) * Sq + vc8;
            cp16(sa,            vth + gv);
            cp16(sa + FV_BYTES, vtl + gv);
        }
        CP_COMMIT();
    }

    float mrow[2] = {-1e30f, -1e30f};
    float lrowv[2] = {0.f, 0.f};
    float oacc[8][4];
    #pragma unroll
    for (int j = 0; j < 8; j++)
        #pragma unroll
        for (int q = 0; q < 4; q++) oacc[j][q] = 0.f;

    uint32_t qa_hi[4][4], qa_lo[4][4];
    bool qloaded = false;

    const int grA = it * 128 + wid * 16 + (lane >> 2);
    const int grB = grA + 8;

    for (int jt = 0; jt <= it; jt++) {
        const int s = jt & 1;
        if (jt < it) {
            const uint32_t so = skv0 + (s ^ 1) * FK_STAGE;
            #pragma unroll
            for (int i = 0; i < 4; i++) {
                const int row = lrow + i * 32;
                const uint32_t sa = so + (uint32_t)(row * LDS + lc8) * 2;
                const size_t gk = ((size_t)bh * Sq + (jt + 1) * 128 + row) * DHd + lc8;
                cp16(sa,            kh + gk);
                cp16(sa + FQ_BYTES, kl + gk);
            }
            #pragma unroll
            for (int i = 0; i < 4; i++) {
                const int row = vrow + i * 16;
                const uint32_t sa = so + 2*FQ_BYTES + (uint32_t)(row * LDSV + vc8) * 2;
                const size_t gv = ((size_t)bh * DHd + row) * Sq + (jt + 1) * 128 + vc8;
                cp16(sa,            vth + gv);
                cp16(sa + FV_BYTES, vtl + gv);
            }
            CP_COMMIT();
            CP_WAIT(1);
        } else {
            CP_WAIT(0);
        }
        __syncthreads();

        if (!qloaded) {
            qloaded = true;
            #pragma unroll
            for (int k16 = 0; k16 < 4; k16++) {
                const int arow = wid * 16 + (lane & 15);
                const int acol = k16 * 16 + ((lane >> 4) << 3);
                const uint32_t addr = sq + (uint32_t)(arow * LDS + acol) * 2;
                LDSM_X4(qa_hi[k16][0], qa_hi[k16][1], qa_hi[k16][2], qa_hi[k16][3], addr);
                LDSM_X4(qa_lo[k16][0], qa_lo[k16][1], qa_lo[k16][2], qa_lo[k16][3], addr + FQ_BYTES);
            }
        }

        const uint32_t sk = skv0 + s * FK_STAGE;
        const uint32_t sv = sk + 2 * FQ_BYTES;

        float sacc[16][4];
        #pragma unroll
        for (int j = 0; j < 16; j++)
            #pragma unroll
            for (int q = 0; q < 4; q++) sacc[j][q] = 0.f;

        #pragma unroll
        for (int k16 = 0; k16 < 4; k16++) {
            const int kc = k16 * 16;
            uint32_t kbh[8][4], kbl[8][4];
            #pragma unroll
            for (int p = 0; p < 8; p++) {
                const int nrow = p * 16 + (lane & 7) + ((lane & 16) >> 1);
                const int ncol = kc + (lane & 8);
                const uint32_t addr = sk + (uint32_t)(nrow * LDS + ncol) * 2;
                LDSM_X4(kbh[p][0], kbh[p][1], kbh[p][2], kbh[p][3], addr);
                LDSM_X4(kbl[p][0], kbl[p][1], kbl[p][2], kbl[p][3], addr + FQ_BYTES);
            }
            #pragma unroll
            for (int nt = 0; nt < 16; nt++) {
                const int pr = nt >> 1, ix = (nt & 1) * 2;
                MMA_BF16(sacc[nt], qa_hi[k16], kbh[pr][ix], kbh[pr][ix+1]);
                MMA_BF16(sacc[nt], qa_lo[k16], kbh[pr][ix], kbh[pr][ix+1]);
                MMA_BF16(sacc[nt], qa_hi[k16], kbl[pr][ix], kbl[pr][ix+1]);
            }
        }

        float mxA = -1e30f, mxB = -1e30f;
        #pragma unroll
        for (int nt = 0; nt < 16; nt++) {
            const int col = jt * 128 + nt * 8 + (lane & 3) * 2;
            float v0 = sacc[nt][0] * QK_SCALE;
            float v1 = sacc[nt][1] * QK_SCALE;
            float v2 = sacc[nt][2] * QK_SCALE;
            float v3 = sacc[nt][3] * QK_SCALE;
            if (jt == it) {
                if (col     > grA) v0 = -1e30f;
                if (col + 1 > grA) v1 = -1e30f;
                if (col     > grB) v2 = -1e30f;
                if (col + 1 > grB) v3 = -1e30f;
            }
            sacc[nt][0] = v0; sacc[nt][1] = v1; sacc[nt][2] = v2; sacc[nt][3] = v3;
            mxA = fmaxf(mxA, fmaxf(v0, v1));
            mxB = fmaxf(mxB, fmaxf(v2, v3));
        }
        #pragma unroll
        for (int o = 1; o <= 2; o <<= 1) {
            mxA = fmaxf(mxA, __shfl_xor_sync(0xffffffffu, mxA, o));
            mxB = fmaxf(mxB, __shfl_xor_sync(0xffffffffu, mxB, o));
        }
        const float mnA = fmaxf(mrow[0], mxA);
        const float mnB = fmaxf(mrow[1], mxB);
        const float scA = __expf(mrow[0] - mnA);
        const float scB = __expf(mrow[1] - mnB);
        mrow[0] = mnA; mrow[1] = mnB;

        #pragma unroll
        for (int j = 0; j < 8; j++) {
            oacc[j][0] *= scA; oacc[j][1] *= scA;
            oacc[j][2] *= scB; oacc[j][3] *= scB;
        }

        float rsA = 0.f, rsB = 0.f;
        #pragma unroll
        for (int t = 0; t < 8; t++) {
            float p00 = __expf(sacc[2*t][0]   - mnA);
            float p01 = __expf(sacc[2*t][1]   - mnA);
            float p02 = __expf(sacc[2*t][2]   - mnB);
            float p03 = __expf(sacc[2*t][3]   - mnB);
            float p10 = __expf(sacc[2*t+1][0] - mnA);
            float p11 = __expf(sacc[2*t+1][1] - mnA);
            float p12 = __expf(sacc[2*t+1][2] - mnB);
            float p13 = __expf(sacc[2*t+1][3] - mnB);
            rsA += p00 + p01 + p10 + p11;
            rsB += p02 + p03 + p12 + p13;

            uint32_t pa_hi[4], pa_lo[4];
            pa_hi[0] = pack_bf16(p00, p01);
            pa_hi[1] = pack_bf16(p02, p03);
            pa_hi[2] = pack_bf16(p10, p11);
            pa_hi[3] = pack_bf16(p12, p13);
            {
                __nv_bfloat162* ph = (__nv_bfloat162*)pa_hi;
                pa_lo[0] = pack_bf16(p00 - __bfloat162float(ph[0].x), p01 - __bfloat162float(ph[0].y));
                pa_lo[1] = pack_bf16(p02 - __bfloat162float(ph[1].x), p03 - __bfloat162float(ph[1].y));
                pa_lo[2] = pack_bf16(p10 - __bfloat162float(ph[2].x), p11 - __bfloat162float(ph[2].y));
                pa_lo[3] = pack_bf16(p12 - __bfloat162float(ph[3].x), p13 - __bfloat162float(ph[3].y));
            }

            const int kc = t * 16;
            uint32_t vbh[4][4], vbl[4][4];
            #pragma unroll
            for (int p = 0; p < 4; p++) {
                const int nrow = p * 16 + (lane & 7) + ((lane & 16) >> 1);
                const int ncol = kc + (lane & 8);
                const uint32_t addr = sv + (uint32_t)(nrow * LDSV + ncol) * 2;
                LDSM_X4(vbh[p][0], vbh[p][1], vbh[p][2], vbh[p][3], addr);
                LDSM_X4(vbl[p][0], vbl[p][1], vbl[p][2], vbl[p][3], addr + FV_BYTES);
            }
            #pragma unroll
            for (int nto = 0; nto < 8; nto++) {
                const int pr = nto >> 1, ix = (nto & 1) * 2;
                MMA_BF16(oacc[nto], pa_hi, vbh[pr][ix], vbh[pr][ix+1]);
                MMA_BF16(oacc[nto], pa_lo, vbh[pr][ix], vbh[pr][ix+1]);
                MMA_BF16(oacc[nto], pa_hi, vbl[pr][ix], vbl[pr][ix+1]);
            }
        }
        #pragma unroll
        for (int o = 1; o <= 2; o <<= 1) {
            rsA += __shfl_xor_sync(0xffffffffu, rsA, o);
            rsB += __shfl_xor_sync(0xffffffffu, rsB, o);
        }
        lrowv[0] = lrowv[0] * scA + rsA;
        lrowv[1] = lrowv[1] * scB + rsB;

        __syncthreads();
    }

    const float invA = 1.0f / lrowv[0];
    const float invB = 1.0f / lrowv[1];
    const int sA = it * 128 + wid * 16 + (lane >> 2);
    const int sB = sA + 8;
    #pragma unroll
    for (int nto = 0; nto < 8; nto++) {
        const int d = nto * 8 + (lane & 3) * 2;
        const size_t gA = ((size_t)(b * Sq + sA)) * Dm + h * DHd + d;
        const size_t gB = ((size_t)(b * Sq + sB)) * Dm + h * DHd + d;
        float v0 = oacc[nto][0] * invA, v1 = oacc[nto][1] * invA;
        float v2 = oacc[nto][2] * invB, v3 = oacc[nto][3] * invB;
        __nv_bfloat16 h0 = __float2bfloat16(v0), h1 = __float2bfloat16(v1);
        __nv_bfloat16 h2 = __float2bfloat16(v2), h3 = __float2bfloat16(v3);
        __nv_bfloat162 hhA; hhA.x = h0; hhA.y = h1;
        __nv_bfloat162 hhB; hhB.x = h2; hhB.y = h3;
        __nv_bfloat162 llA, llB;
        llA.x = __float2bfloat16(v0 - __bfloat162float(h0));
        llA.y = __float2bfloat16(v1 - __bfloat162float(h1));
        llB.x = __float2bfloat16(v2 - __bfloat162float(h2));
        llB.y = __float2bfloat16(v3 - __bfloat162float(h3));
        *(__nv_bfloat162*)(aohi + gA) = hhA;
        *(__nv_bfloat162*)(aolo + gA) = llA;
        *(__nv_bfloat162*)(aohi + gB) = hhB;
        *(__nv_bfloat162*)(aolo + gB) = llB;
    }
}

// ---------------- sum experts (fp16, vectorized) + final LayerNorm ----------
__global__ void redln_kernel(const __half* __restrict__ expout, const float* __restrict__ g,
                             const float* __restrict__ b, float* __restrict__ out)
{
    __shared__ float buf[Dm];
    __shared__ float red[256];
    const int row = blockIdx.x;
    const int tid = threadIdx.x;
    const int i0  = tid * 4;          // 4 contiguous elems per thread
    float v[4] = {0.f, 0.f, 0.f, 0.f};
    #pragma unroll
    for (int e = 0; e < Ex; e++) {
        const __half* p = expout + (size_t)e * ROWS * Dm + (size_t)row * Dm + i0;
        uint2 raw = *(const uint2*)p;
        __half2 a = *(__half2*)&raw.x;
        __half2 c = *(__half2*)&raw.y;
        v[0] += __half2float(a.x); v[1] += __half2float(a.y);
        v[2] += __half2float(c.x); v[3] += __half2float(c.y);
    }
    buf[i0] = v[0]; buf[i0+1] = v[1]; buf[i0+2] = v[2]; buf[i0+3] = v[3];
    float s = v[0] + v[1] + v[2] + v[3];
    red[tid] = s; __syncthreads();
    for (int off = 128; off > 0; off >>= 1) { if (tid < off) red[tid] += red[tid+off]; __syncthreads(); }
    const float mean = red[0] * (1.0f / Dm);
    __syncthreads();
    float s2 = 0.f;
    #pragma unroll
    for (int j = 0; j < 4; j++) { float d = buf[i0+j] - mean; s2 += d * d; }
    red[tid] = s2; __syncthreads();
    for (int off = 128; off > 0; off >>= 1) { if (tid < off) red[tid] += red[tid+off]; __syncthreads(); }
    const float inv = rsqrtf(red[0] * (1.0f / Dm) + 1e-5f);
    const float4 g4 = *(const float4*)(g + i0);
    const float4 b4 = *(const float4*)(b + i0);
    float4 o4;
    o4.x = (buf[i0]   - mean) * inv * g4.x + b4.x;
    o4.y = (buf[i0+1] - mean) * inv * g4.y + b4.y;
    o4.z = (buf[i0+2] - mean) * inv * g4.z + b4.z;
    o4.w = (buf[i0+3] - mean) * inv * g4.w + b4.w;
    *(float4*)(out + (size_t)row * Dm + i0) = o4;
}

// ---------------- launch ----------------
extern "C" void kernel_launch(void* const* d_in, const int* in_sizes, int n_in,
                              void* d_out, int out_size)
{
    const float* x       = (const float*)d_in[0];
    const float* ln_g    = (const float*)d_in[1];
    const float* ln_b    = (const float*)d_in[2];
    const float* Wq      = (const float*)d_in[3];
    const float* Wk      = (const float*)d_in[4];
    const float* Wv      = (const float*)d_in[5];
    const float* q_scale = (const float*)d_in[6];
    const float* k_scale = (const float*)d_in[7];
    const float* Wo      = (const float*)d_in[8];
    const float* gate_w  = (const float*)d_in[9];
    const float* gate_b  = (const float*)d_in[10];
    const float* w1      = (const float*)d_in[11];
    const float* b1      = (const float*)d_in[12];
    const float* w2      = (const float*)d_in[13];
    const float* b2      = (const float*)d_in[14];
    float* out = (float*)d_out;

    __nv_bfloat16 *h1hi, *h1lo, *aohi, *aolo;
    __half *h2h16, *hid, *w1Th, *w2Th, *expout;
    __nv_bfloat16 *qnh, *qnl, *knh, *knl, *vTh, *vTl;
    __nv_bfloat16 *wqkvThi, *wqkvTlo, *woThi, *woTlo;
    float *qkvf, *o, *gate;
    cudaGetSymbolAddress((void**)&h1hi, g_h1hi);   cudaGetSymbolAddress((void**)&h1lo, g_h1lo);
    cudaGetSymbolAddress((void**)&qkvf, g_qkvf);
    cudaGetSymbolAddress((void**)&qnh, g_qnh);     cudaGetSymbolAddress((void**)&qnl, g_qnl);
    cudaGetSymbolAddress((void**)&knh, g_knh);     cudaGetSymbolAddress((void**)&knl, g_knl);
    cudaGetSymbolAddress((void**)&vTh, g_vTh);     cudaGetSymbolAddress((void**)&vTl, g_vTl);
    cudaGetSymbolAddress((void**)&aohi, g_aohi);   cudaGetSymbolAddress((void**)&aolo, g_aolo);
    cudaGetSymbolAddress((void**)&o, g_o);
    cudaGetSymbolAddress((void**)&h2h16, g_h2h16);
    cudaGetSymbolAddress((void**)&gate, g_gate);
    cudaGetSymbolAddress((void**)&hid, g_hid);
    cudaGetSymbolAddress((void**)&expout, g_expout);
    cudaGetSymbolAddress((void**)&wqkvThi, g_wqkvThi); cudaGetSymbolAddress((void**)&wqkvTlo, g_wqkvTlo);
    cudaGetSymbolAddress((void**)&woThi, g_woThi);     cudaGetSymbolAddress((void**)&woTlo, g_woTlo);
    cudaGetSymbolAddress((void**)&w1Th, g_w1Th);
    cudaGetSymbolAddress((void**)&w2Th, g_w2Th);

    cudaFuncSetAttribute(bgemm_kernel<0,0>, cudaFuncAttributeMaxDynamicSharedMemorySize, SMEM_M0);
    cudaFuncSetAttribute(bgemm_kernel<1,2>, cudaFuncAttributeMaxDynamicSharedMemorySize, SMEM_M2);
    cudaFuncSetAttribute(bgemm_kernel<2,2>, cudaFuncAttributeMaxDynamicSharedMemorySize, SMEM_M2);
    cudaFuncSetAttribute(flash_kernel,      cudaFuncAttributeMaxDynamicSharedMemorySize, SMEM_FL);

    // ---- side stream: weight prep not needed until step 5/7 -----------------
    cudaStream_t s2;
    cudaStreamCreateWithFlags(&s2, cudaStreamNonBlocking);
    cudaEvent_t evFork, evJoin;
    cudaEventCreateWithFlags(&evFork, cudaEventDisableTiming);
    cudaEventCreateWithFlags(&evJoin, cudaEventDisableTiming);

    // QKV weight prep must complete before step 2 -> keep on main stream
    wprep_kernel<<<dim3(Dm/32, Dm/32, 1), dim3(32,8)>>>(Wq, wqkvThi,           wqkvTlo,           Dm, Dm);
    wprep_kernel<<<dim3(Dm/32, Dm/32, 1), dim3(32,8)>>>(Wk, wqkvThi + Dm*Dm,   wqkvTlo + Dm*Dm,   Dm, Dm);
    wprep_kernel<<<dim3(Dm/32, Dm/32, 1), dim3(32,8)>>>(Wv, wqkvThi + 2*Dm*Dm, wqkvTlo + 2*Dm*Dm, Dm, Dm);

    // fork: Wo/w1/w2 prep runs concurrently with LN + QKV GEMM + attention
    cudaEventRecord(evFork, 0);
    cudaStreamWaitEvent(s2, evFork, 0);
    wprep_kernel<<<dim3(Dm/32, Dm/32, 1), dim3(32,8), 0, s2>>>(Wo, woThi, woTlo, Dm, Dm);
    wprep16_kernel<<<dim3(FFd/32, Dm/64, Ex), 256, 0, s2>>>(w1, w1Th, Dm, FFd);
    wprep16_kernel<<<dim3(Dm/32, FFd/64, Ex), 256, 0, s2>>>(w2, w2Th, FFd, Dm);
    cudaEventRecord(evJoin, s2);

    // 1. pre-attention LN -> bf16 hi/lo
    ln_kernel<<<ROWS, 256>>>(x, ln_g, ln_b, nullptr, h1hi, h1lo, nullptr,
                             nullptr, nullptr, nullptr);

    // 2. fused QKV projection (bf16 3-term)
    bgemm_kernel<0,0><<<dim3(3*Dm/BN, ROWS/BM, 1), 256, SMEM_M0>>>(
        h1hi, h1lo, wqkvThi, wqkvTlo, 3*Dm, Dm, 0, 0, 0,
        qkvf, nullptr, nullptr, 0, nullptr);

    // 3. l2norm q+k + v transpose, one launch
    qkvprep_kernel<<<dim3((BH*Sq)/8, 3), 256>>>(qkvf, q_scale, k_scale,
                                                qnh, qnl, knh, knl, vTh, vTl);

    // 4. fused flash attention (heavy tiles first)
    flash_kernel<<<dim3(Sq/128, BH), 256, SMEM_FL>>>(qnh, qnl, knh, knl, vTh, vTl, aohi, aolo);

    // join: Wo/w1/w2 prep must be done before step 5
    cudaStreamWaitEvent(0, evJoin, 0);

    // 5. output projection (bf16 3-term) + mid LN (with fused gate softmax)
    bgemm_kernel<0,0><<<dim3(Dm/BN, ROWS/BM, 1), 256, SMEM_M0>>>(
        aohi, aolo, woThi, woTlo, Dm, Dm, 0, 0, 0,
        o, nullptr, nullptr, 0, nullptr);
    ln_kernel<<<ROWS, 256>>>(o, ln_g, ln_b, nullptr, nullptr, nullptr, h2h16,
                             gate_w, gate_b, gate);

    // 7. MoE GEMM1 (fp16 1-term, 3-stage)
    bgemm_kernel<1,2><<<dim3(FFd/BN, ROWS/BM, Ex), 256, SMEM_M2>>>(
        h2h16, nullptr, w1Th, nullptr, FFd, Dm,
        0, (long long)FFd*Dm, (long long)ROWS*FFd,
        nullptr, hid, b1, FFd, nullptr);

    // 8. MoE GEMM2 (fp16 1-term, 3-stage) -> fp16 gated expert outputs
    bgemm_kernel<2,2><<<dim3(Dm/BN, ROWS/BM, Ex), 256, SMEM_M2>>>(
        hid, nullptr, w2Th, nullptr, Dm, FFd,
        (long long)ROWS*FFd, (long long)Dm*FFd, (long long)ROWS*Dm,
        nullptr, expout, b2, Dm, gate);

    // 9. sum experts (fp16, vectorized) + final LN -> out
    redln_kernel<<<ROWS, 256>>>(expout, ln_g, ln_b, out);

    cudaEventDestroy(evFork);
    cudaEventDestroy(evJoin);
    cudaStreamDestroy(s2);
}

// round 17
// speedup vs baseline: 1.0538x; 1.0320x over previous
#include <cuda_runtime.h>
#include <cuda_bf16.h>
#include <cuda_fp16.h>
#include <math.h>
#include <stdint.h>

// ---------------- problem constants ----------------
#define Bc   2
#define Sq   1024
#define Dm   1024
#define Hh   16
#define DHd  64
#define Ex   8
#define FFd  4096
#define BH   (Bc*Hh)     // 32
#define ROWS (Bc*Sq)     // 2048
#define QK_SCALE 10.0f

// GEMM tiling (bgemm: 256x128 CTA tile)
#define BM 256
#define BN 128
#define BK 64
#define LDS 72                        // BK + 8 pad (16-bit units)
#define A_BYTES (256*LDS*2)           // 36864
#define B_BYTES (128*LDS*2)           // 18432
#define SMEM_M0 (2*(2*A_BYTES + 2*B_BYTES))  // 221184 (bf16 3-term, 2 stages)
#define SMEM_M2 (3*(A_BYTES + B_BYTES))      // 165888 (fp16 1-term, 3 stages)
#define SMEM_M3 (2*(2*A_BYTES + B_BYTES))    // 184320 (fp16 2-term, 2 stages)

// flash attention tiling
#define FQ_BYTES (128*LDS*2)          // 18432
#define LDSV 136
#define FV_BYTES (64*LDSV*2)          // 17408
#define FK_STAGE (2*FQ_BYTES + 2*FV_BYTES)   // 71680
#define SMEM_FL (2*FQ_BYTES + 2*FK_STAGE)    // 180224

// ---------------- low-level helpers ----------------
__device__ __forceinline__ uint32_t smem_u32(const void* p) {
    uint32_t a;
    asm("{ .reg .u64 t; cvta.to.shared.u64 t, %1; cvt.u32.u64 %0, t; }" : "=r"(a) : "l"(p));
    return a;
}
__device__ __forceinline__ void cp16(uint32_t dst, const void* src) {
    asm volatile("cp.async.cg.shared.global [%0], [%1], 16;" :: "r"(dst), "l"(src));
}
#define CP_COMMIT() asm volatile("cp.async.commit_group;" ::: "memory")
#define CP_WAIT(n)  asm volatile("cp.async.wait_group %0;" :: "n"(n) : "memory")

#define LDSM_X4(r0, r1, r2, r3, addr) \
    asm volatile("ldmatrix.sync.aligned.m8n8.x4.shared.b16 {%0,%1,%2,%3}, [%4];" \
        : "=r"(r0), "=r"(r1), "=r"(r2), "=r"(r3) : "r"(addr))

#define MMA_BF16(d, a, b0, b1) \
    asm volatile("mma.sync.aligned.m16n8k16.row.col.f32.bf16.bf16.f32 " \
        "{%0,%1,%2,%3}, {%4,%5,%6,%7}, {%8,%9}, {%0,%1,%2,%3};" \
        : "+f"((d)[0]), "+f"((d)[1]), "+f"((d)[2]), "+f"((d)[3]) \
        : "r"((a)[0]), "r"((a)[1]), "r"((a)[2]), "r"((a)[3]), "r"(b0), "r"(b1))

#define MMA_F16(d, a, b0, b1) \
    asm volatile("mma.sync.aligned.m16n8k16.row.col.f32.f16.f16.f32 " \
        "{%0,%1,%2,%3}, {%4,%5,%6,%7}, {%8,%9}, {%0,%1,%2,%3};" \
        : "+f"((d)[0]), "+f"((d)[1]), "+f"((d)[2]), "+f"((d)[3]) \
        : "r"((a)[0]), "r"((a)[1]), "r"((a)[2]), "r"((a)[3]), "r"(b0), "r"(b1))

__device__ __forceinline__ uint32_t pack_bf16(float a, float b) {
    __nv_bfloat162 t;
    t.x = __float2bfloat16(a);
    t.y = __float2bfloat16(b);
    return *(uint32_t*)&t;
}

// ---------------- scratch (device globals) ----------------
__device__ __nv_bfloat16 g_h1hi[ROWS*Dm], g_h1lo[ROWS*Dm];
__device__ float g_qkvf[ROWS*3*Dm];
__device__ __nv_bfloat16 g_qnh[BH*Sq*DHd], g_qnl[BH*Sq*DHd];
__device__ __nv_bfloat16 g_knh[BH*Sq*DHd], g_knl[BH*Sq*DHd];
__device__ __nv_bfloat16 g_vTh[BH*DHd*Sq], g_vTl[BH*DHd*Sq];
__device__ __half g_aohi[ROWS*Dm], g_aolo[ROWS*Dm];
__device__ float g_o[ROWS*Dm];
__device__ __half g_h2h16[ROWS*Dm];
__device__ float g_gate[ROWS*Ex];
__device__ __half g_hid[(size_t)Ex*ROWS*FFd];
__device__ __half g_expout[(size_t)Ex*ROWS*Dm];
__device__ __nv_bfloat16 g_wqkvThi[3*Dm*Dm], g_wqkvTlo[3*Dm*Dm];
__device__ __half g_woT[Dm*Dm];
__device__ __half g_w1Th[(size_t)Ex*FFd*Dm];
__device__ __half g_w2Th[(size_t)Ex*Dm*FFd];

// ---------------- math helpers ----------------
__device__ __forceinline__ float gelu_f(float x) {
    float x3 = x * x * x;
    float t  = tanhf(0.7978845608028654f * (x + 0.044715f * x3));
    return 0.5f * x * (1.0f + t);
}

// ---------------- weight transpose + bf16 split (QKV weights) --------------
__global__ void wprep_kernel(const float* __restrict__ W, __nv_bfloat16* __restrict__ hi,
                             __nv_bfloat16* __restrict__ lo, int K, int N)
{
    __shared__ float t[32][33];
    const size_t zoff = (size_t)blockIdx.z * K * N;
    const int k0 = blockIdx.y * 32, n0 = blockIdx.x * 32;
    const int tx = threadIdx.x, ty = threadIdx.y;
    #pragma unroll
    for (int i = 0; i < 4; i++)
        t[ty + 8*i][tx] = W[zoff + (size_t)(k0 + ty + 8*i) * N + n0 + tx];
    __syncthreads();
    #pragma unroll
    for (int i = 0; i < 4; i++) {
        float v = t[tx][ty + 8*i];
        const size_t o = zoff + (size_t)(n0 + ty + 8*i) * K + k0 + tx;
        __nv_bfloat16 h = __float2bfloat16(v);
        hi[o] = h;
        lo[o] = __float2bfloat16(v - __bfloat162float(h));
    }
}

// ---------------- FAST weight transpose + fp16: W[K,N] -> fp16 [N,K] -------
__global__ void __launch_bounds__(256)
wprep16_kernel(const float* __restrict__ W, __half* __restrict__ out, int K, int N)
{
    __shared__ float t[64][33];
    const size_t zoff = (size_t)blockIdx.z * K * N;
    const int k0 = blockIdx.y * 64, n0 = blockIdx.x * 32;
    const int tid = threadIdx.x;
    const int lx = tid & 31;
    const int ly = tid >> 5;
    #pragma unroll
    for (int i = 0; i < 8; i++) {
        const int kk = ly + 8 * i;
        t[kk][lx] = W[zoff + (size_t)(k0 + kk) * N + n0 + lx];
    }
    __syncthreads();
    const int n  = tid >> 3;
    const int ks = (tid & 7) * 8;
    __half h[8];
    #pragma unroll
    for (int j = 0; j < 8; j++) h[j] = __float2half(t[ks + j][n]);
    *(uint4*)(out + zoff + (size_t)(n0 + n) * K + k0 + ks) = *(uint4*)h;
}

// ---------------- LayerNorm (vectorized, + optional fused gate softmax) ----
__global__ void ln_kernel(const float* __restrict__ x, const float* __restrict__ g,
                          const float* __restrict__ b, float* __restrict__ yf,
                          __nv_bfloat16* __restrict__ yhi, __nv_bfloat16* __restrict__ ylo,
                          __half* __restrict__ y16,
                          const float* __restrict__ gw, const float* __restrict__ gb,
                          float* __restrict__ gateOut)
{
    __shared__ float buf[Dm];
    __shared__ float red[256];
    __shared__ float lg[Ex];
    const int row = blockIdx.x;
    const int tid = threadIdx.x;
    const int i0  = tid * 4;
    const float* xr = x + (size_t)row * Dm;

    float4 v4 = *(const float4*)(xr + i0);
    buf[i0] = v4.x; buf[i0+1] = v4.y; buf[i0+2] = v4.z; buf[i0+3] = v4.w;
    float s = v4.x + v4.y + v4.z + v4.w;
    red[tid] = s; __syncthreads();
    for (int off = 128; off > 0; off >>= 1) { if (tid < off) red[tid] += red[tid+off]; __syncthreads(); }
    const float mean = red[0] * (1.0f / Dm);
    __syncthreads();
    float s2 = 0.f;
    #pragma unroll
    for (int j = 0; j < 4; j++) { float d = buf[i0+j] - mean; s2 += d * d; }
    red[tid] = s2; __syncthreads();
    for (int off = 128; off > 0; off >>= 1) { if (tid < off) red[tid] += red[tid+off]; __syncthreads(); }
    const float inv = rsqrtf(red[0] * (1.0f / Dm) + 1e-5f);

    const float4 g4 = *(const float4*)(g + i0);
    const float4 b4 = *(const float4*)(b + i0);
    float vv[4];
    vv[0] = (buf[i0]   - mean) * inv * g4.x + b4.x;
    vv[1] = (buf[i0+1] - mean) * inv * g4.y + b4.y;
    vv[2] = (buf[i0+2] - mean) * inv * g4.z + b4.z;
    vv[3] = (buf[i0+3] - mean) * inv * g4.w + b4.w;
    buf[i0] = vv[0]; buf[i0+1] = vv[1]; buf[i0+2] = vv[2]; buf[i0+3] = vv[3];
    if (yf) *(float4*)(yf + (size_t)row * Dm + i0) = make_float4(vv[0], vv[1], vv[2], vv[3]);
    if (yhi) {
        __nv_bfloat162 h0, h1, l0, l1;
        h0.x = __float2bfloat16(vv[0]); h0.y = __float2bfloat16(vv[1]);
        h1.x = __float2bfloat16(vv[2]); h1.y = __float2bfloat16(vv[3]);
        l0.x = __float2bfloat16(vv[0] - __bfloat162float(h0.x));
        l0.y = __float2bfloat16(vv[1] - __bfloat162float(h0.y));
        l1.x = __float2bfloat16(vv[2] - __bfloat162float(h1.x));
        l1.y = __float2bfloat16(vv[3] - __bfloat162float(h1.y));
        *(__nv_bfloat162*)(yhi + (size_t)row*Dm + i0)     = h0;
        *(__nv_bfloat162*)(yhi + (size_t)row*Dm + i0 + 2) = h1;
        *(__nv_bfloat162*)(ylo + (size_t)row*Dm + i0)     = l0;
        *(__nv_bfloat162*)(ylo + (size_t)row*Dm + i0 + 2) = l1;
    }
    if (y16) {
        __half2 a = __halves2half2(__float2half(vv[0]), __float2half(vv[1]));
        __half2 c = __halves2half2(__float2half(vv[2]), __float2half(vv[3]));
        *(__half2*)(y16 + (size_t)row*Dm + i0)     = a;
        *(__half2*)(y16 + (size_t)row*Dm + i0 + 2) = c;
    }
    if (gateOut) {
        __syncthreads();
        const int e = tid >> 5, lane = tid & 31;
        float sg = 0.f;
        for (int k = lane; k < Dm; k += 32) sg += buf[k] * gw[k * Ex + e];
        #pragma unroll
        for (int o = 16; o; o >>= 1) sg += __shfl_xor_sync(0xffffffffu, sg, o);
        if (lane == 0) lg[e] = sg + gb[e];
        __syncthreads();
        if (tid == 0) {
            float m = lg[0];
            #pragma unroll
            for (int q = 1; q < Ex; q++) m = fmaxf(m, lg[q]);
            float ex[Ex], sum = 0.f;
            #pragma unroll
            for (int q = 0; q < Ex; q++) { ex[q] = expf(lg[q] - m); sum += ex[q]; }
            const float invs = 1.0f / sum;
            #pragma unroll
            for (int q = 0; q < Ex; q++) gateOut[(size_t)row * Ex + q] = ex[q] * invs;
        }
    }
}

// ---------------- mma.sync GEMM ------------
// MODE 0: bf16 3-term (A hi/lo, B hi/lo), 2 stages.
// MODE 2: fp16 1-term (A, B), 3 stages.
// MODE 3: fp16 2-term (A hi/lo, B single), 2 stages.
// EPI 0: fp32 store; EPI 1: gelu(acc+bias) -> fp16; EPI 2: gate*(acc+bias) -> fp16
template<int EPI, int MODE>
__global__ void __launch_bounds__(256, 1)
bgemm_kernel(const void* __restrict__ Ahi_, const void* __restrict__ Alo_,
             const void* __restrict__ Bhi_, const void* __restrict__ Blo_,
             int N, int K,
             long long az, long long bz, long long oz,
             float* __restrict__ outf,
             void* __restrict__ outhi_,
             const float* __restrict__ bias, long long biasz,
             const float* __restrict__ gate)
{
    extern __shared__ char smem[];
    const uint32_t sbase = smem_u32(smem);
    const int tid  = threadIdx.x;
    const int wid  = tid >> 5;
    const int lane = tid & 31;
    const int wm   = wid >> 1;
    const int wn   = wid & 1;
    const int m0 = blockIdx.y * BM;
    const int n0 = blockIdx.x * BN;
    const int e  = blockIdx.z;

    constexpr bool ALO = (MODE == 0) || (MODE == 3);
    constexpr bool BLO = (MODE == 0);
    constexpr int NSTG = (MODE == 2) ? 3 : 2;
    constexpr int STG = (ALO ? 2 : 1) * A_BYTES + (BLO ? 2 : 1) * B_BYTES;
    constexpr uint32_t B_OFF = (ALO ? 2 : 1) * A_BYTES;
    const uint16_t* pAhi = (const uint16_t*)Ahi_ + (size_t)e * az;
    const uint16_t* pAlo = (const uint16_t*)Alo_ + (size_t)e * az;
    const uint16_t* pBhi = (const uint16_t*)Bhi_ + (size_t)e * bz;
    const uint16_t* pBlo = (const uint16_t*)Blo_ + (size_t)e * bz;

    const int lrow = tid >> 3;
    const int lc8  = (tid & 7) * 8;

    float acc[4][8][4];
    #pragma unroll
    for (int i = 0; i < 4; i++)
        #pragma unroll
        for (int j = 0; j < 8; j++)
            #pragma unroll
            for (int q = 0; q < 4; q++) acc[i][j][q] = 0.f;

    const int NB = K / BK;

    auto load_stage = [&](int kb, int slot) {
        const int kk = kb * BK;
        const uint32_t so = sbase + slot * STG;
        #pragma unroll
        for (int i = 0; i < 8; i++) {
            const int row = lrow + i * 32;
            const uint32_t sa = so + (uint32_t)(row * LDS + lc8) * 2;
            const size_t ga = (size_t)(m0 + row) * K + kk + lc8;
            cp16(sa, pAhi + ga);
            if (ALO) cp16(sa + A_BYTES, pAlo + ga);
        }
        #pragma unroll
        for (int i = 0; i < 4; i++) {
            const int row = lrow + i * 32;
            const uint32_t sb = so + B_OFF + (uint32_t)(row * LDS + lc8) * 2;
            const size_t gb = (size_t)(n0 + row) * K + kk + lc8;
            cp16(sb, pBhi + gb);
            if (BLO) cp16(sb + B_BYTES, pBlo + gb);
        }
        CP_COMMIT();
    };

    #pragma unroll
    for (int p = 0; p < NSTG - 1; p++) load_stage(p, p);

    for (int kb = 0; kb < NB; kb++) {
        const int s = kb % NSTG;
        if (kb + NSTG - 1 < NB) {
            load_stage(kb + NSTG - 1, (kb + NSTG - 1) % NSTG);
            CP_WAIT(NSTG - 1);
        } else if (kb + 1 < NB) {
            CP_WAIT(1);
        } else {
            CP_WAIT(0);
        }
        __syncthreads();

        const uint32_t so = sbase + s * STG;
        #pragma unroll
        for (int k16 = 0; k16 < 4; k16++) {
            const int kc = k16 * 16;
            uint32_t ah[4][4], al[4][4], bh[4][4], bl[4][4];
            #pragma unroll
            for (int mt = 0; mt < 4; mt++) {
                const int arow = wm * 64 + mt * 16 + (lane & 15);
                const int acol = kc + ((lane >> 4) << 3);
                const uint32_t addr = so + (uint32_t)(arow * LDS + acol) * 2;
                LDSM_X4(ah[mt][0], ah[mt][1], ah[mt][2], ah[mt][3], addr);
                if (ALO) LDSM_X4(al[mt][0], al[mt][1], al[mt][2], al[mt][3], addr + A_BYTES);
            }
            #pragma unroll
            for (int p = 0; p < 4; p++) {
                const int nrow = wn * 64 + p * 16 + (lane & 7) + ((lane & 16) >> 1);
                const int ncol = kc + (lane & 8);
                const uint32_t addr = so + B_OFF + (uint32_t)(nrow * LDS + ncol) * 2;
                LDSM_X4(bh[p][0], bh[p][1], bh[p][2], bh[p][3], addr);
                if (BLO) LDSM_X4(bl[p][0], bl[p][1], bl[p][2], bl[p][3], addr + B_BYTES);
            }
            #pragma unroll
            for (int mt = 0; mt < 4; mt++) {
                #pragma unroll
                for (int nt = 0; nt < 8; nt++) {
                    const int pr = nt >> 1, ix = (nt & 1) * 2;
                    if (MODE == 0) {
                        MMA_BF16(acc[mt][nt], ah[mt], bh[pr][ix], bh[pr][ix+1]);
                        MMA_BF16(acc[mt][nt], al[mt], bh[pr][ix], bh[pr][ix+1]);
                        MMA_BF16(acc[mt][nt], ah[mt], bl[pr][ix], bl[pr][ix+1]);
                    } else if (MODE == 3) {
                        MMA_F16(acc[mt][nt], ah[mt], bh[pr][ix], bh[pr][ix+1]);
                        MMA_F16(acc[mt][nt], al[mt], bh[pr][ix], bh[pr][ix+1]);
                    } else {
                        MMA_F16(acc[mt][nt], ah[mt], bh[pr][ix], bh[pr][ix+1]);
                    }
                }
            }
        }
        __syncthreads();
    }

    #pragma unroll
    for (int mt = 0; mt < 4; mt++) {
        const int rA = m0 + wm * 64 + mt * 16 + (lane >> 2);
        const int rB = rA + 8;
        float gv0 = 0.f, gv1 = 0.f;
        if (EPI == 2) {
            gv0 = gate[(size_t)rA * Ex + e];
            gv1 = gate[(size_t)rB * Ex + e];
        }
        #pragma unroll
        for (int nt = 0; nt < 8; nt++) {
            const int col = n0 + wn * 64 + nt * 8 + (lane & 3) * 2;
            float d0 = acc[mt][nt][0], d1 = acc[mt][nt][1];
            float d2 = acc[mt][nt][2], d3 = acc[mt][nt][3];
            if (EPI == 0) {
                *(float2*)(outf + (size_t)rA * N + col) = make_float2(d0, d1);
                *(float2*)(outf + (size_t)rB * N + col) = make_float2(d2, d3);
            } else if (EPI == 1) {
                const float b0 = bias[(size_t)e * biasz + col];
                const float b1 = bias[(size_t)e * biasz + col + 1];
                float v0 = gelu_f(d0 + b0), v1 = gelu_f(d1 + b1);
                float v2 = gelu_f(d2 + b0), v3 = gelu_f(d3 + b1);
                const size_t gA = (size_t)e * oz + (size_t)rA * N + col;
                const size_t gB = (size_t)e * oz + (size_t)rB * N + col;
                __half* oh = (__half*)outhi_;
                *(__half2*)(oh + gA) = __halves2half2(__float2half(v0), __float2half(v1));
                *(__half2*)(oh + gB) = __halves2half2(__float2half(v2), __float2half(v3));
            } else {
                const float b0 = bias[(size_t)e * biasz + col];
                const float b1 = bias[(size_t)e * biasz + col + 1];
                const size_t gA = (size_t)e * oz + (size_t)rA * N + col;
                const size_t gB = (size_t)e * oz + (size_t)rB * N + col;
                __half* oh = (__half*)outhi_;
                *(__half2*)(oh + gA) = __halves2half2(__float2half(gv0 * (d0 + b0)),
                                                      __float2half(gv0 * (d1 + b1)));
                *(__half2*)(oh + gB) = __halves2half2(__float2half(gv1 * (d2 + b0)),
                                                      __float2half(gv1 * (d3 + b1)));
            }
        }
    }
}

// ---------------- l2norm q/k + v transpose, one launch ----------------
__global__ void qkvprep_kernel(const float* __restrict__ qkv,
                               const float* __restrict__ q_scale, const float* __restrict__ k_scale,
                               __nv_bfloat16* __restrict__ qh, __nv_bfloat16* __restrict__ ql,
                               __nv_bfloat16* __restrict__ kh, __nv_bfloat16* __restrict__ kl,
                               __nv_bfloat16* __restrict__ vh, __nv_bfloat16* __restrict__ vl)
{
    __shared__ float t[32][33];
    const int sel = blockIdx.y;
    const int tid = threadIdx.x;
    if (sel < 2) {
        const int r    = blockIdx.x * 8 + (tid >> 5);
        const int lane = tid & 31;
        const int base = sel * Dm;
        const float* scale = sel ? k_scale : q_scale;
        __nv_bfloat16* oh = sel ? kh : qh;
        __nv_bfloat16* ol = sel ? kl : ql;
        const int b = r / (Hh * Sq);
        const int h = (r / Sq) % Hh;
        const int s = r % Sq;
        const float* src = qkv + (size_t)(b * Sq + s) * (3*Dm) + base + h * DHd;
        float v0 = src[lane], v1 = src[lane + 32];
        float ss = v0 * v0 + v1 * v1;
        #pragma unroll
        for (int o = 16; o; o >>= 1) ss += __shfl_xor_sync(0xffffffffu, ss, o);
        const float inv = rsqrtf(ss + 1e-12f);
        float f0 = v0 * inv * scale[h * DHd + lane];
        float f1 = v1 * inv * scale[h * DHd + lane + 32];
        const size_t d = (size_t)r * DHd;
        __nv_bfloat16 h0 = __float2bfloat16(f0);
        __nv_bfloat16 h1 = __float2bfloat16(f1);
        oh[d + lane]      = h0;
        ol[d + lane]      = __float2bfloat16(f0 - __bfloat162float(h0));
        oh[d + lane + 32] = h1;
        ol[d + lane + 32] = __float2bfloat16(f1 - __bfloat162float(h1));
    } else {
        if (blockIdx.x >= 2048) return;
        const int bh = blockIdx.x & 31;
        const int d0 = ((blockIdx.x >> 5) & 1) * 32;
        const int s0 = (blockIdx.x >> 6) * 32;
        const int b = bh >> 4, h = bh & 15;
        const int tx = tid & 31, ty = tid >> 5;
        #pragma unroll
        for (int i = 0; i < 4; i++)
            t[ty + 8*i][tx] = qkv[(size_t)(b * Sq + s0 + ty + 8*i) * (3*Dm) + 2*Dm + h * DHd + d0 + tx];
        __syncthreads();
        #pragma unroll
        for (int i = 0; i < 4; i++) {
            float v = t[tx][ty + 8*i];
            const size_t o = ((size_t)bh * DHd + d0 + ty + 8*i) * Sq + s0 + tx;
            __nv_bfloat16 hh = __float2bfloat16(v);
            vh[o] = hh;
            vl[o] = __float2bfloat16(v - __bfloat162float(hh));
        }
    }
}

// ---------------- fused flash attention (fp16 hi/lo output) -----------------
__global__ void __launch_bounds__(256, 1)
flash_kernel(const __nv_bfloat16* __restrict__ qh, const __nv_bfloat16* __restrict__ ql,
             const __nv_bfloat16* __restrict__ kh, const __nv_bfloat16* __restrict__ kl,
             const __nv_bfloat16* __restrict__ vth, const __nv_bfloat16* __restrict__ vtl,
             __half* __restrict__ aohi, __half* __restrict__ aolo)
{
    extern __shared__ char smem[];
    const uint32_t sbase = smem_u32(smem);
    const int tid  = threadIdx.x;
    const int wid  = tid >> 5;
    const int lane = tid & 31;
    const int it = gridDim.x - 1 - blockIdx.x;   // heavy rows first
    const int bh = blockIdx.y;
    const int b = bh >> 4, h = bh & 15;

    const int lrow = tid >> 3;
    const int lc8  = (tid & 7) * 8;
    const int vrow = tid >> 4;
    const int vc8  = (tid & 15) * 8;

    const uint32_t sq = sbase;
    const uint32_t skv0 = sbase + 2 * FQ_BYTES;

    #pragma unroll
    for (int i = 0; i < 4; i++) {
        const int row = lrow + i * 32;
        const uint32_t sa = sq + (uint32_t)(row * LDS + lc8) * 2;
        const size_t gq = ((size_t)bh * Sq + it * 128 + row) * DHd + lc8;
        cp16(sa,            qh + gq);
        cp16(sa + FQ_BYTES, ql + gq);
    }
    {
        const uint32_t so = skv0;
        #pragma unroll
        for (int i = 0; i < 4; i++) {
            const int row = lrow + i * 32;
            const uint32_t sa = so + (uint32_t)(row * LDS + lc8) * 2;
            const size_t gk = ((size_t)bh * Sq + row) * DHd + lc8;
            cp16(sa,            kh + gk);
            cp16(sa + FQ_BYTES, kl + gk);
        }
        #pragma unroll
        for (int i = 0; i < 4; i++) {
            const int row = vrow + i * 16;
            const uint32_t sa = so + 2*FQ_BYTES + (uint32_t)(row * LDSV + vc8) * 2;
            const size_t gv = ((size_t)bh * DHd + row) * Sq + vc8;
            cp16(sa,            vth + gv);
            cp16(sa + FV_BYTES, vtl + gv);
        }
        CP_COMMIT();
    }

    float mrow[2] = {-1e30f, -1e30f};
    float lrowv[2] = {0.f, 0.f};
    float oacc[8][4];
    #pragma unroll
    for (int j = 0; j < 8; j++)
        #pragma unroll
        for (int q = 0; q < 4; q++) oacc[j][q] = 0.f;

    uint32_t qa_hi[4][4], qa_lo[4][4];
    bool qloaded = false;

    const int grA = it * 128 + wid * 16 + (lane >> 2);
    const int grB = grA + 8;

    for (int jt = 0; jt <= it; jt++) {
        const int s = jt & 1;
        if (jt < it) {
            const uint32_t so = skv0 + (s ^ 1) * FK_STAGE;
            #pragma unroll
            for (int i = 0; i < 4; i++) {
                const int row = lrow + i * 32;
                const uint32_t sa = so + (uint32_t)(row * LDS + lc8) * 2;
                const size_t gk = ((size_t)bh * Sq + (jt + 1) * 128 + row) * DHd + lc8;
                cp16(sa,            kh + gk);
                cp16(sa + FQ_BYTES, kl + gk);
            }
            #pragma unroll
            for (int i = 0; i < 4; i++) {
                const int row = vrow + i * 16;
                const uint32_t sa = so + 2*FQ_BYTES + (uint32_t)(row * LDSV + vc8) * 2;
                const size_t gv = ((size_t)bh * DHd + row) * Sq + (jt + 1) * 128 + vc8;
                cp16(sa,            vth + gv);
                cp16(sa + FV_BYTES, vtl + gv);
            }
            CP_COMMIT();
            CP_WAIT(1);
        } else {
            CP_WAIT(0);
        }
        __syncthreads();

        if (!qloaded) {
            qloaded = true;
            #pragma unroll
            for (int k16 = 0; k16 < 4; k16++) {
                const int arow = wid * 16 + (lane & 15);
                const int acol = k16 * 16 + ((lane >> 4) << 3);
                const uint32_t addr = sq + (uint32_t)(arow * LDS + acol) * 2;
                LDSM_X4(qa_hi[k16][0], qa_hi[k16][1], qa_hi[k16][2], qa_hi[k16][3], addr);
                LDSM_X4(qa_lo[k16][0], qa_lo[k16][1], qa_lo[k16][2], qa_lo[k16][3], addr + FQ_BYTES);
            }
        }

        const uint32_t sk = skv0 + s * FK_STAGE;
        const uint32_t sv = sk + 2 * FQ_BYTES;

        float sacc[16][4];
        #pragma unroll
        for (int j = 0; j < 16; j++)
            #pragma unroll
            for (int q = 0; q < 4; q++) sacc[j][q] = 0.f;

        #pragma unroll
        for (int k16 = 0; k16 < 4; k16++) {
            const int kc = k16 * 16;
            uint32_t kbh[8][4], kbl[8][4];
            #pragma unroll
            for (int p = 0; p < 8; p++) {
                const int nrow = p * 16 + (lane & 7) + ((lane & 16) >> 1);
                const int ncol = kc + (lane & 8);
                const uint32_t addr = sk + (uint32_t)(nrow * LDS + ncol) * 2;
                LDSM_X4(kbh[p][0], kbh[p][1], kbh[p][2], kbh[p][3], addr);
                LDSM_X4(kbl[p][0], kbl[p][1], kbl[p][2], kbl[p][3], addr + FQ_BYTES);
            }
            #pragma unroll
            for (int nt = 0; nt < 16; nt++) {
                const int pr = nt >> 1, ix = (nt & 1) * 2;
                MMA_BF16(sacc[nt], qa_hi[k16], kbh[pr][ix], kbh[pr][ix+1]);
                MMA_BF16(sacc[nt], qa_lo[k16], kbh[pr][ix], kbh[pr][ix+1]);
                MMA_BF16(sacc[nt], qa_hi[k16], kbl[pr][ix], kbl[pr][ix+1]);
            }
        }

        float mxA = -1e30f, mxB = -1e30f;
        #pragma unroll
        for (int nt = 0; nt < 16; nt++) {
            const int col = jt * 128 + nt * 8 + (lane & 3) * 2;
            float v0 = sacc[nt][0] * QK_SCALE;
            float v1 = sacc[nt][1] * QK_SCALE;
            float v2 = sacc[nt][2] * QK_SCALE;
            float v3 = sacc[nt][3] * QK_SCALE;
            if (jt == it) {
                if (col     > grA) v0 = -1e30f;
                if (col + 1 > grA) v1 = -1e30f;
                if (col     > grB) v2 = -1e30f;
                if (col + 1 > grB) v3 = -1e30f;
            }
            sacc[nt][0] = v0; sacc[nt][1] = v1; sacc[nt][2] = v2; sacc[nt][3] = v3;
            mxA = fmaxf(mxA, fmaxf(v0, v1));
            mxB = fmaxf(mxB, fmaxf(v2, v3));
        }
        #pragma unroll
        for (int o = 1; o <= 2; o <<= 1) {
            mxA = fmaxf(mxA, __shfl_xor_sync(0xffffffffu, mxA, o));
            mxB = fmaxf(mxB, __shfl_xor_sync(0xffffffffu, mxB, o));
        }
        const float mnA = fmaxf(mrow[0], mxA);
        const float mnB = fmaxf(mrow[1], mxB);
        const float scA = __expf(mrow[0] - mnA);
        const float scB = __expf(mrow[1] - mnB);
        mrow[0] = mnA; mrow[1] = mnB;

        #pragma unroll
        for (int j = 0; j < 8; j++) {
            oacc[j][0] *= scA; oacc[j][1] *= scA;
            oacc[j][2] *= scB; oacc[j][3] *= scB;
        }

        float rsA = 0.f, rsB = 0.f;
        #pragma unroll
        for (int t = 0; t < 8; t++) {
            float p00 = __expf(sacc[2*t][0]   - mnA);
            float p01 = __expf(sacc[2*t][1]   - mnA);
            float p02 = __expf(sacc[2*t][2]   - mnB);
            float p03 = __expf(sacc[2*t][3]   - mnB);
            float p10 = __expf(sacc[2*t+1][0] - mnA);
            float p11 = __expf(sacc[2*t+1][1] - mnA);
            float p12 = __expf(sacc[2*t+1][2] - mnB);
            float p13 = __expf(sacc[2*t+1][3] - mnB);
            rsA += p00 + p01 + p10 + p11;
            rsB += p02 + p03 + p12 + p13;

            uint32_t pa_hi[4], pa_lo[4];
            pa_hi[0] = pack_bf16(p00, p01);
            pa_hi[1] = pack_bf16(p02, p03);
            pa_hi[2] = pack_bf16(p10, p11);
            pa_hi[3] = pack_bf16(p12, p13);
            {
                __nv_bfloat162* ph = (__nv_bfloat162*)pa_hi;
                pa_lo[0] = pack_bf16(p00 - __bfloat162float(ph[0].x), p01 - __bfloat162float(ph[0].y));
                pa_lo[1] = pack_bf16(p02 - __bfloat162float(ph[1].x), p03 - __bfloat162float(ph[1].y));
                pa_lo[2] = pack_bf16(p10 - __bfloat162float(ph[2].x), p11 - __bfloat162float(ph[2].y));
                pa_lo[3] = pack_bf16(p12 - __bfloat162float(ph[3].x), p13 - __bfloat162float(ph[3].y));
            }

            const int kc = t * 16;
            uint32_t vbh[4][4], vbl[4][4];
            #pragma unroll
            for (int p = 0; p < 4; p++) {
                const int nrow = p * 16 + (lane & 7) + ((lane & 16) >> 1);
                const int ncol = kc + (lane & 8);
                const uint32_t addr = sv + (uint32_t)(nrow * LDSV + ncol) * 2;
                LDSM_X4(vbh[p][0], vbh[p][1], vbh[p][2], vbh[p][3], addr);
                LDSM_X4(vbl[p][0], vbl[p][1], vbl[p][2], vbl[p][3], addr + FV_BYTES);
            }
            #pragma unroll
            for (int nto = 0; nto < 8; nto++) {
                const int pr = nto >> 1, ix = (nto & 1) * 2;
                MMA_BF16(oacc[nto], pa_hi, vbh[pr][ix], vbh[pr][ix+1]);
                MMA_BF16(oacc[nto], pa_lo, vbh[pr][ix], vbh[pr][ix+1]);
                MMA_BF16(oacc[nto], pa_hi, vbl[pr][ix], vbl[pr][ix+1]);
            }
        }
        #pragma unroll
        for (int o = 1; o <= 2; o <<= 1) {
            rsA += __shfl_xor_sync(0xffffffffu, rsA, o);
            rsB += __shfl_xor_sync(0xffffffffu, rsB, o);
        }
        lrowv[0] = lrowv[0] * scA + rsA;
        lrowv[1] = lrowv[1] * scB + rsB;

        __syncthreads();
    }

    const float invA = 1.0f / lrowv[0];
    const float invB = 1.0f / lrowv[1];
    const int sA = it * 128 + wid * 16 + (lane >> 2);
    const int sB = sA + 8;
    #pragma unroll
    for (int nto = 0; nto < 8; nto++) {
        const int d = nto * 8 + (lane & 3) * 2;
        const size_t gA = ((size_t)(b * Sq + sA)) * Dm + h * DHd + d;
        const size_t gB = ((size_t)(b * Sq + sB)) * Dm + h * DHd + d;
        float v0 = oacc[nto][0] * invA, v1 = oacc[nto][1] * invA;
        float v2 = oacc[nto][2] * invB, v3 = oacc[nto][3] * invB;
        __half h0 = __float2half(v0), h1 = __float2half(v1);
        __half h2 = __float2half(v2), h3 = __float2half(v3);
        __half l0 = __float2half(v0 - __half2float(h0));
        __half l1 = __float2half(v1 - __half2float(h1));
        __half l2 = __float2half(v2 - __half2float(h2));
        __half l3 = __float2half(v3 - __half2float(h3));
        *(__half2*)(aohi + gA) = __halves2half2(h0, h1);
        *(__half2*)(aolo + gA) = __halves2half2(l0, l1);
        *(__half2*)(aohi + gB) = __halves2half2(h2, h3);
        *(__half2*)(aolo + gB) = __halves2half2(l2, l3);
    }
}

// ---------------- sum experts (fp16, vectorized) + final LayerNorm ----------
__global__ void redln_kernel(const __half* __restrict__ expout, const float* __restrict__ g,
                             const float* __restrict__ b, float* __restrict__ out)
{
    __shared__ float buf[Dm];
    __shared__ float red[256];
    const int row = blockIdx.x;
    const int tid = threadIdx.x;
    const int i0  = tid * 4;
    float v[4] = {0.f, 0.f, 0.f, 0.f};
    #pragma unroll
    for (int e = 0; e < Ex; e++) {
        const __half* p = expout + (size_t)e * ROWS * Dm + (size_t)row * Dm + i0;
        uint2 raw = *(const uint2*)p;
        __half2 a = *(__half2*)&raw.x;
        __half2 c = *(__half2*)&raw.y;
        v[0] += __half2float(a.x); v[1] += __half2float(a.y);
        v[2] += __half2float(c.x); v[3] += __half2float(c.y);
    }
    buf[i0] = v[0]; buf[i0+1] = v[1]; buf[i0+2] = v[2]; buf[i0+3] = v[3];
    float s = v[0] + v[1] + v[2] + v[3];
    red[tid] = s; __syncthreads();
    for (int off = 128; off > 0; off >>= 1) { if (tid < off) red[tid] += red[tid+off]; __syncthreads(); }
    const float mean = red[0] * (1.0f / Dm);
    __syncthreads();
    float s2 = 0.f;
    #pragma unroll
    for (int j = 0; j < 4; j++) { float d = buf[i0+j] - mean; s2 += d * d; }
    red[tid] = s2; __syncthreads();
    for (int off = 128; off > 0; off >>= 1) { if (tid < off) red[tid] += red[tid+off]; __syncthreads(); }
    const float inv = rsqrtf(red[0] * (1.0f / Dm) + 1e-5f);
    const float4 g4 = *(const float4*)(g + i0);
    const float4 b4 = *(const float4*)(b + i0);
    float4 o4;
    o4.x = (buf[i0]   - mean) * inv * g4.x + b4.x;
    o4.y = (buf[i0+1] - mean) * inv * g4.y + b4.y;
    o4.z = (buf[i0+2] - mean) * inv * g4.z + b4.z;
    o4.w = (buf[i0+3] - mean) * inv * g4.w + b4.w;
    *(float4*)(out + (size_t)row * Dm + i0) = o4;
}

// ---------------- launch ----------------
extern "C" void kernel_launch(void* const* d_in, const int* in_sizes, int n_in,
                              void* d_out, int out_size)
{
    const float* x       = (const float*)d_in[0];
    const float* ln_g    = (const float*)d_in[1];
    const float* ln_b    = (const float*)d_in[2];
    const float* Wq      = (const float*)d_in[3];
    const float* Wk      = (const float*)d_in[4];
    const float* Wv      = (const float*)d_in[5];
    const float* q_scale = (const float*)d_in[6];
    const float* k_scale = (const float*)d_in[7];
    const float* Wo      = (const float*)d_in[8];
    const float* gate_w  = (const float*)d_in[9];
    const float* gate_b  = (const float*)d_in[10];
    const float* w1      = (const float*)d_in[11];
    const float* b1      = (const float*)d_in[12];
    const float* w2      = (const float*)d_in[13];
    const float* b2      = (const float*)d_in[14];
    float* out = (float*)d_out;

    __nv_bfloat16 *h1hi, *h1lo;
    __half *aohi, *aolo, *h2h16, *hid, *w1Th, *w2Th, *expout, *woT;
    __nv_bfloat16 *qnh, *qnl, *knh, *knl, *vTh, *vTl;
    __nv_bfloat16 *wqkvThi, *wqkvTlo;
    float *qkvf, *o, *gate;
    cudaGetSymbolAddress((void**)&h1hi, g_h1hi);   cudaGetSymbolAddress((void**)&h1lo, g_h1lo);
    cudaGetSymbolAddress((void**)&qkvf, g_qkvf);
    cudaGetSymbolAddress((void**)&qnh, g_qnh);     cudaGetSymbolAddress((void**)&qnl, g_qnl);
    cudaGetSymbolAddress((void**)&knh, g_knh);     cudaGetSymbolAddress((void**)&knl, g_knl);
    cudaGetSymbolAddress((void**)&vTh, g_vTh);     cudaGetSymbolAddress((void**)&vTl, g_vTl);
    cudaGetSymbolAddress((void**)&aohi, g_aohi);   cudaGetSymbolAddress((void**)&aolo, g_aolo);
    cudaGetSymbolAddress((void**)&o, g_o);
    cudaGetSymbolAddress((void**)&h2h16, g_h2h16);
    cudaGetSymbolAddress((void**)&gate, g_gate);
    cudaGetSymbolAddress((void**)&hid, g_hid);
    cudaGetSymbolAddress((void**)&expout, g_expout);
    cudaGetSymbolAddress((void**)&wqkvThi, g_wqkvThi); cudaGetSymbolAddress((void**)&wqkvTlo, g_wqkvTlo);
    cudaGetSymbolAddress((void**)&woT, g_woT);
    cudaGetSymbolAddress((void**)&w1Th, g_w1Th);
    cudaGetSymbolAddress((void**)&w2Th, g_w2Th);

    cudaFuncSetAttribute(bgemm_kernel<0,0>, cudaFuncAttributeMaxDynamicSharedMemorySize, SMEM_M0);
    cudaFuncSetAttribute(bgemm_kernel<0,3>, cudaFuncAttributeMaxDynamicSharedMemorySize, SMEM_M3);
    cudaFuncSetAttribute(bgemm_kernel<1,2>, cudaFuncAttributeMaxDynamicSharedMemorySize, SMEM_M2);
    cudaFuncSetAttribute(bgemm_kernel<2,2>, cudaFuncAttributeMaxDynamicSharedMemorySize, SMEM_M2);
    cudaFuncSetAttribute(flash_kernel,      cudaFuncAttributeMaxDynamicSharedMemorySize, SMEM_FL);

    // ---- side stream: ALL weight prep overlaps with LN/QKV/attention -------
    cudaStream_t s2;
    cudaStreamCreateWithFlags(&s2, cudaStreamNonBlocking);
    cudaEvent_t evFork, evQKV, evJoin;
    cudaEventCreateWithFlags(&evFork, cudaEventDisableTiming);
    cudaEventCreateWithFlags(&evQKV, cudaEventDisableTiming);
    cudaEventCreateWithFlags(&evJoin, cudaEventDisableTiming);

    cudaEventRecord(evFork, 0);
    cudaStreamWaitEvent(s2, evFork, 0);
    // QKV weight prep on side stream (overlaps with main-stream LN)
    wprep_kernel<<<dim3(Dm/32, Dm/32, 1), dim3(32,8), 0, s2>>>(Wq, wqkvThi,           wqkvTlo,           Dm, Dm);
    wprep_kernel<<<dim3(Dm/32, Dm/32, 1), dim3(32,8), 0, s2>>>(Wk, wqkvThi + Dm*Dm,   wqkvTlo + Dm*Dm,   Dm, Dm);
    wprep_kernel<<<dim3(Dm/32, Dm/32, 1), dim3(32,8), 0, s2>>>(Wv, wqkvThi + 2*Dm*Dm, wqkvTlo + 2*Dm*Dm, Dm, Dm);
    cudaEventRecord(evQKV, s2);
    // Wo (fp16) + MoE weight prep continues on side stream
    wprep16_kernel<<<dim3(Dm/32, Dm/64, 1), 256, 0, s2>>>(Wo, woT, Dm, Dm);
    wprep16_kernel<<<dim3(FFd/32, Dm/64, Ex), 256, 0, s2>>>(w1, w1Th, Dm, FFd);
    wprep16_kernel<<<dim3(Dm/32, FFd/64, Ex), 256, 0, s2>>>(w2, w2Th, FFd, Dm);
    cudaEventRecord(evJoin, s2);

    // 1. pre-attention LN -> bf16 hi/lo (overlaps QKV wprep)
    ln_kernel<<<ROWS, 256>>>(x, ln_g, ln_b, nullptr, h1hi, h1lo, nullptr,
                             nullptr, nullptr, nullptr);

    // QKV weights must be ready before step 2
    cudaStreamWaitEvent(0, evQKV, 0);

    // 2. fused QKV projection (bf16 3-term)
    bgemm_kernel<0,0><<<dim3(3*Dm/BN, ROWS/BM, 1), 256, SMEM_M0>>>(
        h1hi, h1lo, wqkvThi, wqkvTlo, 3*Dm, Dm, 0, 0, 0,
        qkvf, nullptr, nullptr, 0, nullptr);

    // 3. l2norm q+k + v transpose, one launch
    qkvprep_kernel<<<dim3((BH*Sq)/8, 3), 256>>>(qkvf, q_scale, k_scale,
                                                qnh, qnl, knh, knl, vTh, vTl);

    // 4. fused flash attention (heavy tiles first) -> fp16 hi/lo
    flash_kernel<<<dim3(Sq/128, BH), 256, SMEM_FL>>>(qnh, qnl, knh, knl, vTh, vTl, aohi, aolo);

    // join: Wo/w1/w2 prep must be done before step 5
    cudaStreamWaitEvent(0, evJoin, 0);

    // 5. output projection (fp16 2-term) + mid LN (with fused gate softmax)
    bgemm_kernel<0,3><<<dim3(Dm/BN, ROWS/BM, 1), 256, SMEM_M3>>>(
        aohi, aolo, woT, nullptr, Dm, Dm, 0, 0, 0,
        o, nullptr, nullptr, 0, nullptr);
    ln_kernel<<<ROWS, 256>>>(o, ln_g, ln_b, nullptr, nullptr, nullptr, h2h16,
                             gate_w, gate_b, gate);

    // 7. MoE GEMM1 (fp16 1-term, 3-stage)
    bgemm_kernel<1,2><<<dim3(FFd/BN, ROWS/BM, Ex), 256, SMEM_M2>>>(
        h2h16, nullptr, w1Th, nullptr, FFd, Dm,
        0, (long long)FFd*Dm, (long long)ROWS*FFd,
        nullptr, hid, b1, FFd, nullptr);

    // 8. MoE GEMM2 (fp16 1-term, 3-stage) -> fp16 gated expert outputs
    bgemm_kernel<2,2><<<dim3(Dm/BN, ROWS/BM, Ex), 256, SMEM_M2>>>(
        hid, nullptr, w2Th, nullptr, Dm, FFd,
        (long long)ROWS*FFd, (long long)Dm*FFd, (long long)ROWS*Dm,
        nullptr, expout, b2, Dm, gate);

    // 9. sum experts (fp16, vectorized) + final LN -> out
    redln_kernel<<<ROWS, 256>>>(expout, ln_g, ln_b, out);

    cudaEventDestroy(evFork);
    cudaEventDestroy(evQKV);
    cudaEventDestroy(evJoin);
    cudaStreamDestroy(s2);
}